// round 1
// baseline (speedup 1.0000x reference)
#include <cuda_runtime.h>
#include <math.h>

#define S_LEN 4096
#define D_IN  2048
#define NH    16
#define DH    128
#define HD    (NH*DH)   // 2048

// ---------------- scratch (device globals: no allocation allowed) ----------
__device__ float g_q [(size_t)S_LEN * HD];
__device__ float g_k [(size_t)S_LEN * HD];
__device__ float g_v [(size_t)S_LEN * HD];
__device__ float g_ao[(size_t)S_LEN * HD];
__device__ float g_cos[(size_t)S_LEN * (DH/2)];
__device__ float g_sin[(size_t)S_LEN * (DH/2)];

// ---------------- RoPE tables ----------------------------------------------
__global__ void rope_table_kernel() {
    int idx = blockIdx.x * blockDim.x + threadIdx.x;
    if (idx >= S_LEN * (DH/2)) return;
    int row = idx / (DH/2);
    int kp  = idx % (DH/2);
    // inv_freq = 10000^(-(2k)/128), computed in double then rounded to f32,
    // then f32 multiply by t — matches jnp's f32 einsum path.
    float inv = (float)pow(10000.0, -(double)(2*kp) / (double)DH);
    float fr  = (float)row * inv;
    g_cos[idx] = cosf(fr);
    g_sin[idx] = sinf(fr);
}

__global__ void rope_apply_kernel(float* __restrict__ q, float* __restrict__ k) {
    size_t idx = (size_t)blockIdx.x * blockDim.x + threadIdx.x;  // pair index
    if (idx >= (size_t)S_LEN * HD / 2) return;
    size_t row = idx / (HD/2);
    int colpair = (int)(idx % (HD/2));
    int d  = (colpair * 2) & (DH - 1);   // even index within head
    int kp = d >> 1;
    float c = g_cos[row * (DH/2) + kp];
    float s = g_sin[row * (DH/2) + kp];
    size_t base = row * HD + colpair * 2;
    float q0 = q[base], q1 = q[base+1];
    q[base]   = q0 * c - q1 * s;
    q[base+1] = q1 * c + q0 * s;
    float k0 = k[base], k1 = k[base+1];
    k[base]   = k0 * c - k1 * s;
    k[base+1] = k1 * c + k0 * s;
}

// ---------------- fp32 NT GEMM:  C[M,N] = A[M,K] * B[N,K]^T ----------------
// 64x64 tile, Kstep=16, 256 threads, 4x4 microtile, float4 smem reads.
__global__ void __launch_bounds__(256) gemm_nt_kernel(
    const float* __restrict__ A, const float* __restrict__ B,
    float* __restrict__ C, int M, int N, int K)
{
    __shared__ float As[16][68];   // [k][m], stride 68 => 272B rows (16B aligned)
    __shared__ float Bs[16][68];   // [k][n]
    const int tid = threadIdx.x;
    const int tx  = tid & 15;
    const int ty  = tid >> 4;
    const int m0  = blockIdx.y * 64;
    const int n0  = blockIdx.x * 64;
    const int lr  = tid >> 2;         // 0..63
    const int lc  = (tid & 3) << 2;   // 0,4,8,12

    float acc[4][4] = {};
    const float* Aptr = A + (size_t)(m0 + lr) * K + lc;
    const float* Bptr = B + (size_t)(n0 + lr) * K + lc;

    for (int k0 = 0; k0 < K; k0 += 16) {
        float4 a = *(const float4*)(Aptr + k0);
        float4 b = *(const float4*)(Bptr + k0);
        __syncthreads();
        As[lc+0][lr] = a.x; As[lc+1][lr] = a.y; As[lc+2][lr] = a.z; As[lc+3][lr] = a.w;
        Bs[lc+0][lr] = b.x; Bs[lc+1][lr] = b.y; Bs[lc+2][lr] = b.z; Bs[lc+3][lr] = b.w;
        __syncthreads();
#pragma unroll
        for (int kk = 0; kk < 16; kk++) {
            float4 ra = *(const float4*)&As[kk][ty*4];
            float4 rb = *(const float4*)&Bs[kk][tx*4];
            acc[0][0] += ra.x*rb.x; acc[0][1] += ra.x*rb.y; acc[0][2] += ra.x*rb.z; acc[0][3] += ra.x*rb.w;
            acc[1][0] += ra.y*rb.x; acc[1][1] += ra.y*rb.y; acc[1][2] += ra.y*rb.z; acc[1][3] += ra.y*rb.w;
            acc[2][0] += ra.z*rb.x; acc[2][1] += ra.z*rb.y; acc[2][2] += ra.z*rb.z; acc[2][3] += ra.z*rb.w;
            acc[3][0] += ra.w*rb.x; acc[3][1] += ra.w*rb.y; acc[3][2] += ra.w*rb.z; acc[3][3] += ra.w*rb.w;
        }
    }
#pragma unroll
    for (int i = 0; i < 4; i++) {
        float4 o = make_float4(acc[i][0], acc[i][1], acc[i][2], acc[i][3]);
        *(float4*)&C[(size_t)(m0 + ty*4 + i) * N + n0 + tx*4] = o;
    }
}

// ---------------- flash attention (fp32, causal) ---------------------------
// grid (S/64, H), 256 threads. BQ=BK=64. Online softmax; O in registers.
#define BQ 64
#define BK 64
#define ATTN_SMEM_FLOATS (2*128*68 + 64*128 + 64*68 + 128)
#define ATTN_SMEM_BYTES  (ATTN_SMEM_FLOATS * 4)

__global__ void __launch_bounds__(256) attn_kernel(
    const float* __restrict__ Q, const float* __restrict__ K,
    const float* __restrict__ V, float* __restrict__ O)
{
    extern __shared__ float sm[];
    float* QT   = sm;                 // [128][68]  (transposed: [d][m])
    float* KT   = QT + 128*68;        // [128][68]
    float* VS   = KT + 128*68;        // [64][128]
    float* SS   = VS + 64*128;        // [64][68]
    float* CORR = SS + 64*68;         // [64]
    float* LINV = CORR + 64;          // [64]

    const int tid = threadIdx.x;
    const int tx  = tid & 15;
    const int ty  = tid >> 4;
    const int qb  = blockIdx.x;
    const int h   = blockIdx.y;
    const float scale = 0.08838834764831845f;   // 1/sqrt(128)

    // load Q tile transposed (coalesced gmem, padded smem)
    const float* qbase = Q + (size_t)(qb * BQ) * HD + h * DH;
    for (int t = tid; t < BQ * DH; t += 256) {
        int m = t >> 7, d = t & 127;
        QT[d * 68 + m] = qbase[(size_t)m * HD + d];
    }

    const int sr = tid >> 2;   // softmax row  0..63
    const int sq = tid & 3;    // quarter of row
    float m_r = -INFINITY, l_r = 0.f;

    float o[4][8];
#pragma unroll
    for (int i = 0; i < 4; i++)
#pragma unroll
        for (int j = 0; j < 8; j++) o[i][j] = 0.f;

    __syncthreads();

    for (int jb = 0; jb <= qb; jb++) {
        // ---- load K (transposed) and V tiles ----
        const float* kbase = K + (size_t)(jb * BK) * HD + h * DH;
        const float* vbase = V + (size_t)(jb * BK) * HD + h * DH;
        for (int t = tid; t < BK * DH; t += 256) {
            int m = t >> 7, d = t & 127;
            KT[d * 68 + m]  = kbase[(size_t)m * HD + d];
            VS[m * 128 + d] = vbase[(size_t)m * HD + d];
        }
        __syncthreads();

        // ---- scores S = Q K^T (64x64 over 128) ----
        float sa[4][4] = {};
#pragma unroll 8
        for (int kk = 0; kk < 128; kk++) {
            float4 ra = *(const float4*)(QT + kk*68 + ty*4);
            float4 rb = *(const float4*)(KT + kk*68 + tx*4);
            sa[0][0] += ra.x*rb.x; sa[0][1] += ra.x*rb.y; sa[0][2] += ra.x*rb.z; sa[0][3] += ra.x*rb.w;
            sa[1][0] += ra.y*rb.x; sa[1][1] += ra.y*rb.y; sa[1][2] += ra.y*rb.z; sa[1][3] += ra.y*rb.w;
            sa[2][0] += ra.z*rb.x; sa[2][1] += ra.z*rb.y; sa[2][2] += ra.z*rb.z; sa[2][3] += ra.z*rb.w;
            sa[3][0] += ra.w*rb.x; sa[3][1] += ra.w*rb.y; sa[3][2] += ra.w*rb.z; sa[3][3] += ra.w*rb.w;
        }
        const bool diag = (jb == qb);
#pragma unroll
        for (int i = 0; i < 4; i++) {
            int m = ty*4 + i;
#pragma unroll
            for (int j = 0; j < 4; j++) {
                int n = tx*4 + j;
                float sv = sa[i][j] * scale;
                if (diag && n > m) sv = -INFINITY;
                SS[m * 68 + n] = sv;
            }
        }
        __syncthreads();

        // ---- online softmax (4 threads per row) ----
        {
            float lmax = -INFINITY;
#pragma unroll
            for (int cc = 0; cc < 16; cc++)
                lmax = fmaxf(lmax, SS[sr*68 + sq*16 + cc]);
            lmax = fmaxf(lmax, __shfl_xor_sync(0xffffffffu, lmax, 1));
            lmax = fmaxf(lmax, __shfl_xor_sync(0xffffffffu, lmax, 2));
            float m_new = fmaxf(m_r, lmax);
            float corr  = __expf(m_r - m_new);
            float lsum  = 0.f;
#pragma unroll
            for (int cc = 0; cc < 16; cc++) {
                float p = __expf(SS[sr*68 + sq*16 + cc] - m_new);
                SS[sr*68 + sq*16 + cc] = p;
                lsum += p;
            }
            lsum += __shfl_xor_sync(0xffffffffu, lsum, 1);
            lsum += __shfl_xor_sync(0xffffffffu, lsum, 2);
            l_r = l_r * corr + lsum;
            m_r = m_new;
            if (sq == 0) CORR[sr] = corr;
        }
        __syncthreads();

        // ---- rescale O, then O += P @ V  (64x128 over 64) ----
        float cr[4];
#pragma unroll
        for (int i = 0; i < 4; i++) cr[i] = CORR[ty*4 + i];
#pragma unroll
        for (int i = 0; i < 4; i++)
#pragma unroll
            for (int j = 0; j < 8; j++) o[i][j] *= cr[i];

#pragma unroll 4
        for (int kk = 0; kk < BK; kk++) {
            float4 vb0 = *(const float4*)(VS + kk*128 + tx*8);
            float4 vb1 = *(const float4*)(VS + kk*128 + tx*8 + 4);
#pragma unroll
            for (int i = 0; i < 4; i++) {
                float p = SS[(ty*4 + i) * 68 + kk];
                o[i][0] += p*vb0.x; o[i][1] += p*vb0.y; o[i][2] += p*vb0.z; o[i][3] += p*vb0.w;
                o[i][4] += p*vb1.x; o[i][5] += p*vb1.y; o[i][6] += p*vb1.z; o[i][7] += p*vb1.w;
            }
        }
        __syncthreads();   // protect SS/VS/KT before next iteration
    }

    if (sq == 0) LINV[sr] = 1.f / l_r;
    __syncthreads();

    float* obase = O + (size_t)(qb * BQ) * HD + h * DH;
#pragma unroll
    for (int i = 0; i < 4; i++) {
        int m = ty*4 + i;
        float li = LINV[m];
        float4 w0 = make_float4(o[i][0]*li, o[i][1]*li, o[i][2]*li, o[i][3]*li);
        float4 w1 = make_float4(o[i][4]*li, o[i][5]*li, o[i][6]*li, o[i][7]*li);
        *(float4*)(obase + (size_t)m * HD + tx*8)     = w0;
        *(float4*)(obase + (size_t)m * HD + tx*8 + 4) = w1;
    }
}

// ---------------- launch ----------------------------------------------------
extern "C" void kernel_launch(void* const* d_in, const int* in_sizes, int n_in,
                              void* d_out, int out_size)
{
    const float* x  = (const float*)d_in[0];
    // d_in[1] = mask (causal tril) — statically known, unused
    const float* wq = (const float*)d_in[2];
    const float* wk = (const float*)d_in[3];
    const float* wv = (const float*)d_in[4];
    const float* wo = (const float*)d_in[5];
    float* out = (float*)d_out;

    float *qp, *kp, *vp, *aop;
    cudaGetSymbolAddress((void**)&qp,  g_q);
    cudaGetSymbolAddress((void**)&kp,  g_k);
    cudaGetSymbolAddress((void**)&vp,  g_v);
    cudaGetSymbolAddress((void**)&aop, g_ao);

    dim3 gb(HD/64, S_LEN/64);   // (32, 64)
    gemm_nt_kernel<<<gb, 256>>>(x, wq, qp, S_LEN, HD, D_IN);
    gemm_nt_kernel<<<gb, 256>>>(x, wk, kp, S_LEN, HD, D_IN);
    gemm_nt_kernel<<<gb, 256>>>(x, wv, vp, S_LEN, HD, D_IN);

    rope_table_kernel<<<(S_LEN*(DH/2) + 255)/256, 256>>>();
    rope_apply_kernel<<<((S_LEN*HD/2) + 255)/256, 256>>>(qp, kp);

    cudaFuncSetAttribute(attn_kernel,
                         cudaFuncAttributeMaxDynamicSharedMemorySize,
                         ATTN_SMEM_BYTES);
    attn_kernel<<<dim3(S_LEN/BQ, NH), 256, ATTN_SMEM_BYTES>>>(qp, kp, vp, aop);

    gemm_nt_kernel<<<gb, 256>>>(aop, wo, out, S_LEN, D_IN, HD);
}

// round 3
// speedup vs baseline: 1.5260x; 1.5260x over previous
#include <cuda_runtime.h>
#include <cuda_bf16.h>
#include <math.h>
#include <stdint.h>

#define S_LEN 4096
#define D_IN  2048
#define NH    16
#define DH    128
#define HD    2048
#define GM 4096
#define GN 2048
#define GK 2048

// ---------------- scratch (device globals: no allocation allowed) ----------
__device__ float g_q [(size_t)S_LEN * HD];
__device__ float g_k [(size_t)S_LEN * HD];
__device__ float g_v [(size_t)S_LEN * HD];
__device__ float g_ao[(size_t)S_LEN * HD];
__device__ float g_cos[(size_t)S_LEN * (DH/2)];
__device__ float g_sin[(size_t)S_LEN * (DH/2)];
// split-bf16 operands
__device__ __nv_bfloat16 g_xhi [(size_t)S_LEN * D_IN];
__device__ __nv_bfloat16 g_xlo [(size_t)S_LEN * D_IN];
__device__ __nv_bfloat16 g_wqhi[(size_t)HD * D_IN];
__device__ __nv_bfloat16 g_wqlo[(size_t)HD * D_IN];
__device__ __nv_bfloat16 g_wkhi[(size_t)HD * D_IN];
__device__ __nv_bfloat16 g_wklo[(size_t)HD * D_IN];
__device__ __nv_bfloat16 g_wvhi[(size_t)HD * D_IN];
__device__ __nv_bfloat16 g_wvlo[(size_t)HD * D_IN];
__device__ __nv_bfloat16 g_wohi[(size_t)D_IN * HD];
__device__ __nv_bfloat16 g_wolo[(size_t)D_IN * HD];
__device__ __nv_bfloat16 g_aohi[(size_t)S_LEN * HD];
__device__ __nv_bfloat16 g_aolo[(size_t)S_LEN * HD];

// ---------------- PTX helpers ------------------------------------------------
__device__ __forceinline__ uint32_t smem_u32(const void* p) {
    uint32_t a;
    asm("{ .reg .u64 t; cvta.to.shared.u64 t, %1; cvt.u32.u64 %0, t; }"
        : "=r"(a) : "l"(p));
    return a;
}
__device__ __forceinline__ void cpa16(uint32_t dst, const void* src) {
    asm volatile("cp.async.cg.shared.global [%0], [%1], 16;" :: "r"(dst), "l"(src));
}
__device__ __forceinline__ void cpa_commit() { asm volatile("cp.async.commit_group;"); }
__device__ __forceinline__ void cpa_wait0()  { asm volatile("cp.async.wait_group 0;"); }

__device__ __forceinline__ void ldsm4(uint32_t r[4], uint32_t addr) {
    asm volatile("ldmatrix.sync.aligned.m8n8.x4.shared.b16 {%0,%1,%2,%3}, [%4];"
        : "=r"(r[0]), "=r"(r[1]), "=r"(r[2]), "=r"(r[3]) : "r"(addr));
}
__device__ __forceinline__ void mma16816(float c[4], const uint32_t a[4],
                                         uint32_t b0, uint32_t b1) {
    asm volatile(
        "mma.sync.aligned.m16n8k16.row.col.f32.bf16.bf16.f32 "
        "{%0,%1,%2,%3}, {%4,%5,%6,%7}, {%8,%9}, {%0,%1,%2,%3};"
        : "+f"(c[0]), "+f"(c[1]), "+f"(c[2]), "+f"(c[3])
        : "r"(a[0]), "r"(a[1]), "r"(a[2]), "r"(a[3]), "r"(b0), "r"(b1));
}

// ---------------- fp32 -> (hi, lo) bf16 split ---------------------------------
__global__ void cvt_split_kernel(const float* __restrict__ in,
                                 __nv_bfloat16* __restrict__ hi,
                                 __nv_bfloat16* __restrict__ lo, int n4) {
    int i = blockIdx.x * blockDim.x + threadIdx.x;
    if (i >= n4) return;
    float4 v = ((const float4*)in)[i];
    __nv_bfloat16 h0 = __float2bfloat16(v.x);
    __nv_bfloat16 h1 = __float2bfloat16(v.y);
    __nv_bfloat16 h2 = __float2bfloat16(v.z);
    __nv_bfloat16 h3 = __float2bfloat16(v.w);
    __nv_bfloat16 l0 = __float2bfloat16(v.x - __bfloat162float(h0));
    __nv_bfloat16 l1 = __float2bfloat16(v.y - __bfloat162float(h1));
    __nv_bfloat16 l2 = __float2bfloat16(v.z - __bfloat162float(h2));
    __nv_bfloat16 l3 = __float2bfloat16(v.w - __bfloat162float(h3));
    __nv_bfloat162 hh0; hh0.x = h0; hh0.y = h1;
    __nv_bfloat162 hh1; hh1.x = h2; hh1.y = h3;
    __nv_bfloat162 ll0; ll0.x = l0; ll0.y = l1;
    __nv_bfloat162 ll1; ll1.x = l2; ll1.y = l3;
    ((__nv_bfloat162*)hi)[2*i]   = hh0;
    ((__nv_bfloat162*)hi)[2*i+1] = hh1;
    ((__nv_bfloat162*)lo)[2*i]   = ll0;
    ((__nv_bfloat162*)lo)[2*i+1] = ll1;
}

// ---------------- mma.sync split-bf16 GEMM ------------------------------------
// C[M,N] = A[M,K] * B[N,K]^T with A=Ah+Al, B=Bh+Bl (drop Al*Bl).
// 128x128 CTA tile, 8 warps (4M x 2N), warp tile 32x64, K slab 32, 2-stage cp.async.
#define KS   32
#define ROWB 80                  // smem row stride bytes (64B data + 16B pad)
#define OPB  (128*ROWB)          // 10240 per operand tile
#define STB  (4*OPB)             // 40960 per stage
#define GSM  (2*STB)             // 81920 dynamic smem

__global__ void __launch_bounds__(256, 1) gemm_mma_kernel(
    const __nv_bfloat16* __restrict__ Ah, const __nv_bfloat16* __restrict__ Al,
    const __nv_bfloat16* __restrict__ Bh, const __nv_bfloat16* __restrict__ Bl,
    float* __restrict__ C)
{
    extern __shared__ char smraw[];
    const uint32_t sb = smem_u32(smraw);
    const int tid = threadIdx.x;
    const int w   = tid >> 5;
    const int l   = tid & 31;
    const int wm  = w & 3;          // 0..3 -> 32-row slice
    const int wn  = w >> 2;         // 0..1 -> 64-col slice
    const int m0  = blockIdx.y * 128;
    const int n0  = blockIdx.x * 128;

    const __nv_bfloat16* ops[4] = {
        Ah + (size_t)m0 * GK, Al + (size_t)m0 * GK,
        Bh + (size_t)n0 * GK, Bl + (size_t)n0 * GK };

    // per-thread load coords (2 chunks of 16B per operand per slab)
    const int r0 = tid >> 2, c0 = tid & 3;            // chunk 0
    const int r1 = (tid + 256) >> 2, c1 = tid & 3;    // chunk 1 (i&3 same)

    float acc[2][8][4];
#pragma unroll
    for (int a = 0; a < 2; a++)
#pragma unroll
        for (int b = 0; b < 8; b++)
#pragma unroll
            for (int c = 0; c < 4; c++) acc[a][b][c] = 0.f;

    // ---- prologue: stage 0 ----
#pragma unroll
    for (int op = 0; op < 4; op++) {
        cpa16(sb + op*OPB + r0*ROWB + c0*16, ops[op] + (size_t)r0 * GK + c0*8);
        cpa16(sb + op*OPB + r1*ROWB + c1*16, ops[op] + (size_t)r1 * GK + c1*8);
    }
    cpa_commit();

    // ldmatrix lane addressing (constant per thread)
    const int a_row = wm*32 + (l & 15);         // + mt*16
    const int a_kc  = (l >> 4) * 8;             // + ks*16
    const int b_row = wn*64 + (l & 7) + ((l >> 4) << 3);   // + np*16
    const int b_kc  = ((l >> 3) & 1) * 8;       // + ks*16

    const int NSLAB = GK / KS;   // 64
    for (int s = 0; s < NSLAB; s++) {
        const int buf = s & 1;
        cpa_wait0();
        __syncthreads();
        if (s + 1 < NSLAB) {
            const int k0 = (s + 1) * KS;
            const uint32_t dst = sb + (buf ^ 1) * STB;
#pragma unroll
            for (int op = 0; op < 4; op++) {
                cpa16(dst + op*OPB + r0*ROWB + c0*16, ops[op] + (size_t)r0*GK + k0 + c0*8);
                cpa16(dst + op*OPB + r1*ROWB + c1*16, ops[op] + (size_t)r1*GK + k0 + c1*8);
            }
            cpa_commit();
        }
        const uint32_t base = sb + buf * STB;
#pragma unroll
        for (int ks = 0; ks < 2; ks++) {
            uint32_t ah[2][4], al[2][4];
#pragma unroll
            for (int mt = 0; mt < 2; mt++) {
                uint32_t aaddr = base + (a_row + mt*16) * ROWB + (ks*16 + a_kc) * 2;
                ldsm4(ah[mt], aaddr);            // operand 0 (Ah)
                ldsm4(al[mt], aaddr + OPB);      // operand 1 (Al)
            }
#pragma unroll
            for (int np = 0; np < 4; np++) {
                uint32_t bh[4], bl[4];
                uint32_t baddr = base + 2*OPB + (b_row + np*16) * ROWB + (ks*16 + b_kc) * 2;
                ldsm4(bh, baddr);
                ldsm4(bl, baddr + OPB);
#pragma unroll
                for (int mt = 0; mt < 2; mt++) {
                    mma16816(acc[mt][np*2+0], ah[mt], bh[0], bh[1]);
                    mma16816(acc[mt][np*2+0], ah[mt], bl[0], bl[1]);
                    mma16816(acc[mt][np*2+0], al[mt], bh[0], bh[1]);
                    mma16816(acc[mt][np*2+1], ah[mt], bh[2], bh[3]);
                    mma16816(acc[mt][np*2+1], ah[mt], bl[2], bl[3]);
                    mma16816(acc[mt][np*2+1], al[mt], bh[2], bh[3]);
                }
            }
        }
        __syncthreads();
    }

    // ---- epilogue ----
#pragma unroll
    for (int mt = 0; mt < 2; mt++) {
        const int row = m0 + wm*32 + mt*16 + (l >> 2);
#pragma unroll
        for (int nt = 0; nt < 8; nt++) {
            const int col = n0 + wn*64 + nt*8 + (l & 3) * 2;
            float2 v0 = make_float2(acc[mt][nt][0], acc[mt][nt][1]);
            float2 v1 = make_float2(acc[mt][nt][2], acc[mt][nt][3]);
            *(float2*)&C[(size_t)row * GN + col]       = v0;
            *(float2*)&C[(size_t)(row + 8) * GN + col] = v1;
        }
    }
}

// ---------------- RoPE ---------------------------------------------------------
__global__ void rope_table_kernel() {
    int idx = blockIdx.x * blockDim.x + threadIdx.x;
    if (idx >= S_LEN * (DH/2)) return;
    int row = idx / (DH/2);
    int kp  = idx % (DH/2);
    float inv = (float)pow(10000.0, -(double)(2*kp) / (double)DH);
    float fr  = (float)row * inv;
    g_cos[idx] = cosf(fr);
    g_sin[idx] = sinf(fr);
}

__global__ void rope_apply_kernel(float* __restrict__ q, float* __restrict__ k) {
    size_t idx = (size_t)blockIdx.x * blockDim.x + threadIdx.x;
    if (idx >= (size_t)S_LEN * HD / 2) return;
    size_t row = idx / (HD/2);
    int colpair = (int)(idx % (HD/2));
    int d  = (colpair * 2) & (DH - 1);
    int kp = d >> 1;
    float c = g_cos[row * (DH/2) + kp];
    float s = g_sin[row * (DH/2) + kp];
    size_t base = row * HD + colpair * 2;
    float q0 = q[base], q1 = q[base+1];
    q[base]   = q0 * c - q1 * s;
    q[base+1] = q1 * c + q0 * s;
    float k0 = k[base], k1 = k[base+1];
    k[base]   = k0 * c - k1 * s;
    k[base+1] = k1 * c + k0 * s;
}

// ---------------- flash attention (fp32, causal) -------------------------------
#define BQ 64
#define BK 64
#define ATTN_SMEM_FLOATS (2*128*68 + 64*128 + 64*68 + 128)
#define ATTN_SMEM_BYTES  (ATTN_SMEM_FLOATS * 4)

__global__ void __launch_bounds__(256) attn_kernel(
    const float* __restrict__ Q, const float* __restrict__ K,
    const float* __restrict__ V, float* __restrict__ O)
{
    extern __shared__ float sm[];
    float* QT   = sm;
    float* KT   = QT + 128*68;
    float* VS   = KT + 128*68;
    float* SS   = VS + 64*128;
    float* CORR = SS + 64*68;
    float* LINV = CORR + 64;

    const int tid = threadIdx.x;
    const int tx  = tid & 15;
    const int ty  = tid >> 4;
    const int qb  = blockIdx.x;
    const int h   = blockIdx.y;
    const float scale = 0.08838834764831845f;

    const float* qbase = Q + (size_t)(qb * BQ) * HD + h * DH;
    for (int t = tid; t < BQ * DH; t += 256) {
        int m = t >> 7, d = t & 127;
        QT[d * 68 + m] = qbase[(size_t)m * HD + d];
    }

    const int sr = tid >> 2;
    const int sq = tid & 3;
    float m_r = -INFINITY, l_r = 0.f;

    float o[4][8];
#pragma unroll
    for (int i = 0; i < 4; i++)
#pragma unroll
        for (int j = 0; j < 8; j++) o[i][j] = 0.f;

    __syncthreads();

    for (int jb = 0; jb <= qb; jb++) {
        const float* kbase = K + (size_t)(jb * BK) * HD + h * DH;
        const float* vbase = V + (size_t)(jb * BK) * HD + h * DH;
        for (int t = tid; t < BK * DH; t += 256) {
            int m = t >> 7, d = t & 127;
            KT[d * 68 + m]  = kbase[(size_t)m * HD + d];
            VS[m * 128 + d] = vbase[(size_t)m * HD + d];
        }
        __syncthreads();

        float sa[4][4] = {};
#pragma unroll 8
        for (int kk = 0; kk < 128; kk++) {
            float4 ra = *(const float4*)(QT + kk*68 + ty*4);
            float4 rb = *(const float4*)(KT + kk*68 + tx*4);
            sa[0][0] += ra.x*rb.x; sa[0][1] += ra.x*rb.y; sa[0][2] += ra.x*rb.z; sa[0][3] += ra.x*rb.w;
            sa[1][0] += ra.y*rb.x; sa[1][1] += ra.y*rb.y; sa[1][2] += ra.y*rb.z; sa[1][3] += ra.y*rb.w;
            sa[2][0] += ra.z*rb.x; sa[2][1] += ra.z*rb.y; sa[2][2] += ra.z*rb.z; sa[2][3] += ra.z*rb.w;
            sa[3][0] += ra.w*rb.x; sa[3][1] += ra.w*rb.y; sa[3][2] += ra.w*rb.z; sa[3][3] += ra.w*rb.w;
        }
        const bool diag = (jb == qb);
#pragma unroll
        for (int i = 0; i < 4; i++) {
            int m = ty*4 + i;
#pragma unroll
            for (int j = 0; j < 4; j++) {
                int n = tx*4 + j;
                float sv = sa[i][j] * scale;
                if (diag && n > m) sv = -INFINITY;
                SS[m * 68 + n] = sv;
            }
        }
        __syncthreads();

        {
            float lmax = -INFINITY;
#pragma unroll
            for (int cc = 0; cc < 16; cc++)
                lmax = fmaxf(lmax, SS[sr*68 + sq*16 + cc]);
            lmax = fmaxf(lmax, __shfl_xor_sync(0xffffffffu, lmax, 1));
            lmax = fmaxf(lmax, __shfl_xor_sync(0xffffffffu, lmax, 2));
            float m_new = fmaxf(m_r, lmax);
            float corr  = __expf(m_r - m_new);
            float lsum  = 0.f;
#pragma unroll
            for (int cc = 0; cc < 16; cc++) {
                float p = __expf(SS[sr*68 + sq*16 + cc] - m_new);
                SS[sr*68 + sq*16 + cc] = p;
                lsum += p;
            }
            lsum += __shfl_xor_sync(0xffffffffu, lsum, 1);
            lsum += __shfl_xor_sync(0xffffffffu, lsum, 2);
            l_r = l_r * corr + lsum;
            m_r = m_new;
            if (sq == 0) CORR[sr] = corr;
        }
        __syncthreads();

        float cr[4];
#pragma unroll
        for (int i = 0; i < 4; i++) cr[i] = CORR[ty*4 + i];
#pragma unroll
        for (int i = 0; i < 4; i++)
#pragma unroll
            for (int j = 0; j < 8; j++) o[i][j] *= cr[i];

#pragma unroll 4
        for (int kk = 0; kk < BK; kk++) {
            float4 vb0 = *(const float4*)(VS + kk*128 + tx*8);
            float4 vb1 = *(const float4*)(VS + kk*128 + tx*8 + 4);
#pragma unroll
            for (int i = 0; i < 4; i++) {
                float p = SS[(ty*4 + i) * 68 + kk];
                o[i][0] += p*vb0.x; o[i][1] += p*vb0.y; o[i][2] += p*vb0.z; o[i][3] += p*vb0.w;
                o[i][4] += p*vb1.x; o[i][5] += p*vb1.y; o[i][6] += p*vb1.z; o[i][7] += p*vb1.w;
            }
        }
        __syncthreads();
    }

    if (sq == 0) LINV[sr] = 1.f / l_r;
    __syncthreads();

    float* obase = O + (size_t)(qb * BQ) * HD + h * DH;
#pragma unroll
    for (int i = 0; i < 4; i++) {
        int m = ty*4 + i;
        float li = LINV[m];
        float4 w0 = make_float4(o[i][0]*li, o[i][1]*li, o[i][2]*li, o[i][3]*li);
        float4 w1 = make_float4(o[i][4]*li, o[i][5]*li, o[i][6]*li, o[i][7]*li);
        *(float4*)(obase + (size_t)m * HD + tx*8)     = w0;
        *(float4*)(obase + (size_t)m * HD + tx*8 + 4) = w1;
    }
}

// ---------------- launch ---------------------------------------------------------
extern "C" void kernel_launch(void* const* d_in, const int* in_sizes, int n_in,
                              void* d_out, int out_size)
{
    const float* x  = (const float*)d_in[0];
    const float* wq = (const float*)d_in[2];
    const float* wk = (const float*)d_in[3];
    const float* wv = (const float*)d_in[4];
    const float* wo = (const float*)d_in[5];
    float* out = (float*)d_out;

    float *qp, *kp, *vp, *aop;
    cudaGetSymbolAddress((void**)&qp,  g_q);
    cudaGetSymbolAddress((void**)&kp,  g_k);
    cudaGetSymbolAddress((void**)&vp,  g_v);
    cudaGetSymbolAddress((void**)&aop, g_ao);

    __nv_bfloat16 *xhi, *xlo, *wqhi, *wqlo, *wkhi, *wklo, *wvhi, *wvlo, *wohi, *wolo, *aohi, *aolo;
    cudaGetSymbolAddress((void**)&xhi,  g_xhi);  cudaGetSymbolAddress((void**)&xlo,  g_xlo);
    cudaGetSymbolAddress((void**)&wqhi, g_wqhi); cudaGetSymbolAddress((void**)&wqlo, g_wqlo);
    cudaGetSymbolAddress((void**)&wkhi, g_wkhi); cudaGetSymbolAddress((void**)&wklo, g_wklo);
    cudaGetSymbolAddress((void**)&wvhi, g_wvhi); cudaGetSymbolAddress((void**)&wvlo, g_wvlo);
    cudaGetSymbolAddress((void**)&wohi, g_wohi); cudaGetSymbolAddress((void**)&wolo, g_wolo);
    cudaGetSymbolAddress((void**)&aohi, g_aohi); cudaGetSymbolAddress((void**)&aolo, g_aolo);

    cudaFuncSetAttribute(gemm_mma_kernel,
                         cudaFuncAttributeMaxDynamicSharedMemorySize, GSM);
    cudaFuncSetAttribute(attn_kernel,
                         cudaFuncAttributeMaxDynamicSharedMemorySize, ATTN_SMEM_BYTES);

    const int n4x = S_LEN * D_IN / 4;
    const int n4w = HD * D_IN / 4;
    cvt_split_kernel<<<(n4x + 255)/256, 256>>>(x,  xhi,  xlo,  n4x);
    cvt_split_kernel<<<(n4w + 255)/256, 256>>>(wq, wqhi, wqlo, n4w);
    cvt_split_kernel<<<(n4w + 255)/256, 256>>>(wk, wkhi, wklo, n4w);
    cvt_split_kernel<<<(n4w + 255)/256, 256>>>(wv, wvhi, wvlo, n4w);
    cvt_split_kernel<<<(n4w + 255)/256, 256>>>(wo, wohi, wolo, n4w);

    dim3 gg(GN/128, GM/128);   // (16, 32)
    gemm_mma_kernel<<<gg, 256, GSM>>>(xhi, xlo, wqhi, wqlo, qp);
    gemm_mma_kernel<<<gg, 256, GSM>>>(xhi, xlo, wkhi, wklo, kp);
    gemm_mma_kernel<<<gg, 256, GSM>>>(xhi, xlo, wvhi, wvlo, vp);

    rope_table_kernel<<<(S_LEN*(DH/2) + 255)/256, 256>>>();
    rope_apply_kernel<<<((S_LEN*HD/2) + 255)/256, 256>>>(qp, kp);

    attn_kernel<<<dim3(S_LEN/BQ, NH), 256, ATTN_SMEM_BYTES>>>(qp, kp, vp, aop);

    cvt_split_kernel<<<(n4x + 255)/256, 256>>>(aop, aohi, aolo, n4x);
    gemm_mma_kernel<<<gg, 256, GSM>>>(aohi, aolo, wohi, wolo, out);
}

// round 4
// speedup vs baseline: 3.1280x; 2.0498x over previous
#include <cuda_runtime.h>
#include <cuda_bf16.h>
#include <math.h>
#include <stdint.h>

#define S_LEN 4096
#define D_IN  2048
#define NH    16
#define DH    128
#define HD    2048
#define GM 4096
#define GN 2048
#define GK 2048

// ---------------- scratch (device globals: no allocation allowed) ----------
__device__ float g_q [(size_t)S_LEN * HD];
__device__ float g_k [(size_t)S_LEN * HD];
__device__ float g_v [(size_t)S_LEN * HD];
__device__ float g_cos[(size_t)S_LEN * (DH/2)];
__device__ float g_sin[(size_t)S_LEN * (DH/2)];
// split-bf16 operands
__device__ __nv_bfloat16 g_xhi [(size_t)S_LEN * D_IN];
__device__ __nv_bfloat16 g_xlo [(size_t)S_LEN * D_IN];
__device__ __nv_bfloat16 g_wqhi[(size_t)HD * D_IN];
__device__ __nv_bfloat16 g_wqlo[(size_t)HD * D_IN];
__device__ __nv_bfloat16 g_wkhi[(size_t)HD * D_IN];
__device__ __nv_bfloat16 g_wklo[(size_t)HD * D_IN];
__device__ __nv_bfloat16 g_wvhi[(size_t)HD * D_IN];
__device__ __nv_bfloat16 g_wvlo[(size_t)HD * D_IN];
__device__ __nv_bfloat16 g_wohi[(size_t)D_IN * HD];
__device__ __nv_bfloat16 g_wolo[(size_t)D_IN * HD];
// bf16 split attention operands / outputs
__device__ __nv_bfloat16 g_qhi[(size_t)S_LEN * HD];
__device__ __nv_bfloat16 g_qlo[(size_t)S_LEN * HD];
__device__ __nv_bfloat16 g_khi[(size_t)S_LEN * HD];
__device__ __nv_bfloat16 g_klo[(size_t)S_LEN * HD];
__device__ __nv_bfloat16 g_vhi[(size_t)S_LEN * HD];
__device__ __nv_bfloat16 g_vlo[(size_t)S_LEN * HD];
__device__ __nv_bfloat16 g_aohi[(size_t)S_LEN * HD];
__device__ __nv_bfloat16 g_aolo[(size_t)S_LEN * HD];

// ---------------- PTX helpers ------------------------------------------------
__device__ __forceinline__ uint32_t smem_u32(const void* p) {
    uint32_t a;
    asm("{ .reg .u64 t; cvta.to.shared.u64 t, %1; cvt.u32.u64 %0, t; }"
        : "=r"(a) : "l"(p));
    return a;
}
__device__ __forceinline__ void cpa16(uint32_t dst, const void* src) {
    asm volatile("cp.async.cg.shared.global [%0], [%1], 16;" :: "r"(dst), "l"(src));
}
__device__ __forceinline__ void cpa_commit() { asm volatile("cp.async.commit_group;"); }
__device__ __forceinline__ void cpa_wait0()  { asm volatile("cp.async.wait_group 0;"); }

__device__ __forceinline__ void ldsm4(uint32_t r[4], uint32_t addr) {
    asm volatile("ldmatrix.sync.aligned.m8n8.x4.shared.b16 {%0,%1,%2,%3}, [%4];"
        : "=r"(r[0]), "=r"(r[1]), "=r"(r[2]), "=r"(r[3]) : "r"(addr));
}
__device__ __forceinline__ void ldsm4t(uint32_t r[4], uint32_t addr) {
    asm volatile("ldmatrix.sync.aligned.m8n8.x4.trans.shared.b16 {%0,%1,%2,%3}, [%4];"
        : "=r"(r[0]), "=r"(r[1]), "=r"(r[2]), "=r"(r[3]) : "r"(addr));
}
__device__ __forceinline__ void mma16816(float c[4], const uint32_t a[4],
                                         uint32_t b0, uint32_t b1) {
    asm volatile(
        "mma.sync.aligned.m16n8k16.row.col.f32.bf16.bf16.f32 "
        "{%0,%1,%2,%3}, {%4,%5,%6,%7}, {%8,%9}, {%0,%1,%2,%3};"
        : "+f"(c[0]), "+f"(c[1]), "+f"(c[2]), "+f"(c[3])
        : "r"(a[0]), "r"(a[1]), "r"(a[2]), "r"(a[3]), "r"(b0), "r"(b1));
}
__device__ __forceinline__ uint32_t packbf(float a, float b) {
    __nv_bfloat162 t = __floats2bfloat162_rn(a, b);
    return *(uint32_t*)&t;
}

// ---------------- fp32 -> (hi, lo) bf16 split ---------------------------------
__global__ void cvt_split_kernel(const float* __restrict__ in,
                                 __nv_bfloat16* __restrict__ hi,
                                 __nv_bfloat16* __restrict__ lo, int n4) {
    int i = blockIdx.x * blockDim.x + threadIdx.x;
    if (i >= n4) return;
    float4 v = ((const float4*)in)[i];
    __nv_bfloat16 h0 = __float2bfloat16(v.x);
    __nv_bfloat16 h1 = __float2bfloat16(v.y);
    __nv_bfloat16 h2 = __float2bfloat16(v.z);
    __nv_bfloat16 h3 = __float2bfloat16(v.w);
    ((uint32_t*)hi)[2*i]   = packbf(v.x, v.y);
    ((uint32_t*)hi)[2*i+1] = packbf(v.z, v.w);
    ((uint32_t*)lo)[2*i]   = packbf(v.x - __bfloat162float(h0), v.y - __bfloat162float(h1));
    ((uint32_t*)lo)[2*i+1] = packbf(v.z - __bfloat162float(h2), v.w - __bfloat162float(h3));
}

// ---------------- mma.sync split-bf16 GEMM ------------------------------------
#define KS   32
#define ROWB 80
#define OPB  (128*ROWB)
#define STB  (4*OPB)
#define GSM  (2*STB)

__global__ void __launch_bounds__(256, 1) gemm_mma_kernel(
    const __nv_bfloat16* __restrict__ Ah, const __nv_bfloat16* __restrict__ Al,
    const __nv_bfloat16* __restrict__ Bh, const __nv_bfloat16* __restrict__ Bl,
    float* __restrict__ C)
{
    extern __shared__ char smraw[];
    const uint32_t sb = smem_u32(smraw);
    const int tid = threadIdx.x;
    const int w   = tid >> 5;
    const int l   = tid & 31;
    const int wm  = w & 3;
    const int wn  = w >> 2;
    const int m0  = blockIdx.y * 128;
    const int n0  = blockIdx.x * 128;

    const __nv_bfloat16* ops[4] = {
        Ah + (size_t)m0 * GK, Al + (size_t)m0 * GK,
        Bh + (size_t)n0 * GK, Bl + (size_t)n0 * GK };

    const int r0 = tid >> 2, c0 = tid & 3;
    const int r1 = (tid + 256) >> 2, c1 = tid & 3;

    float acc[2][8][4];
#pragma unroll
    for (int a = 0; a < 2; a++)
#pragma unroll
        for (int b = 0; b < 8; b++)
#pragma unroll
            for (int c = 0; c < 4; c++) acc[a][b][c] = 0.f;

#pragma unroll
    for (int op = 0; op < 4; op++) {
        cpa16(sb + op*OPB + r0*ROWB + c0*16, ops[op] + (size_t)r0 * GK + c0*8);
        cpa16(sb + op*OPB + r1*ROWB + c1*16, ops[op] + (size_t)r1 * GK + c1*8);
    }
    cpa_commit();

    const int a_row = wm*32 + (l & 15);
    const int a_kc  = (l >> 4) * 8;
    const int b_row = wn*64 + (l & 7) + ((l >> 4) << 3);
    const int b_kc  = ((l >> 3) & 1) * 8;

    const int NSLAB = GK / KS;
    for (int s = 0; s < NSLAB; s++) {
        const int buf = s & 1;
        cpa_wait0();
        __syncthreads();
        if (s + 1 < NSLAB) {
            const int k0 = (s + 1) * KS;
            const uint32_t dst = sb + (buf ^ 1) * STB;
#pragma unroll
            for (int op = 0; op < 4; op++) {
                cpa16(dst + op*OPB + r0*ROWB + c0*16, ops[op] + (size_t)r0*GK + k0 + c0*8);
                cpa16(dst + op*OPB + r1*ROWB + c1*16, ops[op] + (size_t)r1*GK + k0 + c1*8);
            }
            cpa_commit();
        }
        const uint32_t base = sb + buf * STB;
#pragma unroll
        for (int ks = 0; ks < 2; ks++) {
            uint32_t ah[2][4], al[2][4];
#pragma unroll
            for (int mt = 0; mt < 2; mt++) {
                uint32_t aaddr = base + (a_row + mt*16) * ROWB + (ks*16 + a_kc) * 2;
                ldsm4(ah[mt], aaddr);
                ldsm4(al[mt], aaddr + OPB);
            }
#pragma unroll
            for (int np = 0; np < 4; np++) {
                uint32_t bh[4], bl[4];
                uint32_t baddr = base + 2*OPB + (b_row + np*16) * ROWB + (ks*16 + b_kc) * 2;
                ldsm4(bh, baddr);
                ldsm4(bl, baddr + OPB);
#pragma unroll
                for (int mt = 0; mt < 2; mt++) {
                    mma16816(acc[mt][np*2+0], ah[mt], bh[0], bh[1]);
                    mma16816(acc[mt][np*2+0], ah[mt], bl[0], bl[1]);
                    mma16816(acc[mt][np*2+0], al[mt], bh[0], bh[1]);
                    mma16816(acc[mt][np*2+1], ah[mt], bh[2], bh[3]);
                    mma16816(acc[mt][np*2+1], ah[mt], bl[2], bl[3]);
                    mma16816(acc[mt][np*2+1], al[mt], bh[2], bh[3]);
                }
            }
        }
        __syncthreads();
    }

#pragma unroll
    for (int mt = 0; mt < 2; mt++) {
        const int row = m0 + wm*32 + mt*16 + (l >> 2);
#pragma unroll
        for (int nt = 0; nt < 8; nt++) {
            const int col = n0 + wn*64 + nt*8 + (l & 3) * 2;
            float2 v0 = make_float2(acc[mt][nt][0], acc[mt][nt][1]);
            float2 v1 = make_float2(acc[mt][nt][2], acc[mt][nt][3]);
            *(float2*)&C[(size_t)row * GN + col]       = v0;
            *(float2*)&C[(size_t)(row + 8) * GN + col] = v1;
        }
    }
}

// ---------------- RoPE ---------------------------------------------------------
__global__ void rope_table_kernel() {
    int idx = blockIdx.x * blockDim.x + threadIdx.x;
    if (idx >= S_LEN * (DH/2)) return;
    int row = idx / (DH/2);
    int kp  = idx % (DH/2);
    float inv = (float)pow(10000.0, -(double)(2*kp) / (double)DH);
    float fr  = (float)row * inv;
    g_cos[idx] = cosf(fr);
    g_sin[idx] = sinf(fr);
}

// RoPE + bf16 hi/lo split for q and k (reads fp32 post-GEMM, writes bf16 splits)
__global__ void rope_cvt_kernel(const float* __restrict__ q, const float* __restrict__ k,
                                __nv_bfloat16* __restrict__ qhi, __nv_bfloat16* __restrict__ qlo,
                                __nv_bfloat16* __restrict__ khi, __nv_bfloat16* __restrict__ klo)
{
    size_t idx = (size_t)blockIdx.x * blockDim.x + threadIdx.x;
    if (idx >= (size_t)S_LEN * HD / 2) return;
    size_t row = idx / (HD/2);
    int colpair = (int)(idx % (HD/2));
    int d  = (colpair * 2) & (DH - 1);
    int kp = d >> 1;
    float c = g_cos[row * (DH/2) + kp];
    float s = g_sin[row * (DH/2) + kp];
    size_t base = row * HD + colpair * 2;

    float q0 = q[base], q1 = q[base+1];
    float rq0 = q0 * c - q1 * s;
    float rq1 = q1 * c + q0 * s;
    __nv_bfloat16 h0 = __float2bfloat16(rq0), h1 = __float2bfloat16(rq1);
    *(uint32_t*)&qhi[base] = packbf(rq0, rq1);
    *(uint32_t*)&qlo[base] = packbf(rq0 - __bfloat162float(h0), rq1 - __bfloat162float(h1));

    float k0 = k[base], k1 = k[base+1];
    float rk0 = k0 * c - k1 * s;
    float rk1 = k1 * c + k0 * s;
    __nv_bfloat16 g0 = __float2bfloat16(rk0), g1 = __float2bfloat16(rk1);
    *(uint32_t*)&khi[base] = packbf(rk0, rk1);
    *(uint32_t*)&klo[base] = packbf(rk0 - __bfloat162float(g0), rk1 - __bfloat162float(g1));
}

// ---------------- tensor-core flash attention (split-bf16, causal) -------------
// BQ=128 (8 warps, 16 rows/warp), BK=64, K/V hi/lo double-buffered in smem.
#define KROWB 272                 // 256B data + 16B pad (conflict-free, 16B aligned)
#define KOPB  (64*KROWB)          // 17408 per operand
#define KSTB  (4*KOPB)            // 69632 per stage (Kh,Kl,Vh,Vl)
#define ASMEM (2*KSTB)            // 139264

__device__ __forceinline__ void attn_load_kv(
    uint32_t dstbase,
    const __nv_bfloat16* __restrict__ kh, const __nv_bfloat16* __restrict__ kl,
    const __nv_bfloat16* __restrict__ vh, const __nv_bfloat16* __restrict__ vl,
    int kvbase, int tid)
{
#pragma unroll
    for (int i = 0; i < 16; i++) {
        const int op  = i >> 2;                 // compile-time per i
        const int rem = (i & 3) * 256 + tid;    // 0..1023
        const int row = rem >> 4;
        const int col = rem & 15;
        const __nv_bfloat16* src = (op == 0) ? kh : (op == 1) ? kl : (op == 2) ? vh : vl;
        cpa16(dstbase + op*KOPB + row*KROWB + col*16,
              src + (size_t)(kvbase + row) * HD + col*8);
    }
    cpa_commit();
}

__global__ void __launch_bounds__(256, 1) attn_mma_kernel(
    const __nv_bfloat16* __restrict__ Qh, const __nv_bfloat16* __restrict__ Ql,
    const __nv_bfloat16* __restrict__ Kh, const __nv_bfloat16* __restrict__ Kl,
    const __nv_bfloat16* __restrict__ Vh, const __nv_bfloat16* __restrict__ Vl,
    __nv_bfloat16* __restrict__ Ohi, __nv_bfloat16* __restrict__ Olo)
{
    extern __shared__ char smraw[];
    const uint32_t sb = smem_u32(smraw);
    const int tid = threadIdx.x;
    const int w = tid >> 5, l = tid & 31;
    const int qb = blockIdx.x, h = blockIdx.y;
    const int lq = l >> 2;          // row within 8-group
    const int lc = (l & 3) * 2;     // col pair base
    const float scale = 0.08838834764831845f;

    const int R = qb * 128 + w * 16;
    const size_t hoff = (size_t)h * DH;
    const __nv_bfloat16* kh = Kh + hoff;
    const __nv_bfloat16* kl = Kl + hoff;
    const __nv_bfloat16* vh = Vh + hoff;
    const __nv_bfloat16* vl = Vl + hoff;

    // Q fragments in registers (A-operand layout), hi and lo
    uint32_t qfh[8][4], qfl[8][4];
    {
        const __nv_bfloat16* qhp = Qh + hoff;
        const __nv_bfloat16* qlp = Ql + hoff;
        const size_t ra = (size_t)(R + lq) * HD;
        const size_t rb = (size_t)(R + lq + 8) * HD;
#pragma unroll
        for (int kc = 0; kc < 8; kc++) {
            const int c = kc * 16 + lc;
            qfh[kc][0] = *(const uint32_t*)&qhp[ra + c];
            qfh[kc][1] = *(const uint32_t*)&qhp[rb + c];
            qfh[kc][2] = *(const uint32_t*)&qhp[ra + c + 8];
            qfh[kc][3] = *(const uint32_t*)&qhp[rb + c + 8];
            qfl[kc][0] = *(const uint32_t*)&qlp[ra + c];
            qfl[kc][1] = *(const uint32_t*)&qlp[rb + c];
            qfl[kc][2] = *(const uint32_t*)&qlp[ra + c + 8];
            qfl[kc][3] = *(const uint32_t*)&qlp[rb + c + 8];
        }
    }

    float O_[16][4];
#pragma unroll
    for (int nb = 0; nb < 16; nb++)
#pragma unroll
        for (int e = 0; e < 4; e++) O_[nb][e] = 0.f;
    float mrow0 = -INFINITY, mrow1 = -INFINITY;
    float lrow0 = 0.f, lrow1 = 0.f;

    const int nkv = 2 * qb + 2;
    attn_load_kv(sb, kh, kl, vh, vl, 0, tid);

    for (int jb = 0; jb < nkv; jb++) {
        const uint32_t base = sb + (jb & 1) * KSTB;
        cpa_wait0();
        __syncthreads();
        if (jb + 1 < nkv)
            attn_load_kv(sb + ((jb + 1) & 1) * KSTB, kh, kl, vh, vl, (jb + 1) * 64, tid);

        // ---- S = Q K^T (16 x 64), 3-pass split ----
        float S_[8][4];
#pragma unroll
        for (int nb = 0; nb < 8; nb++)
#pragma unroll
            for (int e = 0; e < 4; e++) S_[nb][e] = 0.f;

        const uint32_t krow = (l & 7) + ((l >> 4) << 3);
        const uint32_t kcol = ((l >> 3) & 1) * 8;
#pragma unroll
        for (int kc = 0; kc < 8; kc++) {
#pragma unroll
            for (int p = 0; p < 4; p++) {
                uint32_t bh[4], bl[4];
                uint32_t addr = base + (p*16 + krow) * KROWB + (kc*16 + kcol) * 2;
                ldsm4(bh, addr);
                ldsm4(bl, addr + KOPB);
                mma16816(S_[p*2+0], qfh[kc], bh[0], bh[1]);
                mma16816(S_[p*2+0], qfh[kc], bl[0], bl[1]);
                mma16816(S_[p*2+0], qfl[kc], bh[0], bh[1]);
                mma16816(S_[p*2+1], qfh[kc], bh[2], bh[3]);
                mma16816(S_[p*2+1], qfh[kc], bl[2], bl[3]);
                mma16816(S_[p*2+1], qfl[kc], bh[2], bh[3]);
            }
        }

        // ---- online softmax ----
        const int kvb = jb * 64;
        const bool domask = (kvb + 63 > R);
        float mx0 = -INFINITY, mx1 = -INFINITY;
#pragma unroll
        for (int nb = 0; nb < 8; nb++) {
            const int colb = kvb + nb*8 + lc;
#pragma unroll
            for (int e = 0; e < 4; e++) {
                float v = S_[nb][e] * scale;
                if (domask) {
                    int row = R + lq + (e >> 1) * 8;
                    int col = colb + (e & 1);
                    if (col > row) v = -INFINITY;
                }
                S_[nb][e] = v;
                if (e < 2) mx0 = fmaxf(mx0, v); else mx1 = fmaxf(mx1, v);
            }
        }
        mx0 = fmaxf(mx0, __shfl_xor_sync(0xffffffffu, mx0, 1));
        mx0 = fmaxf(mx0, __shfl_xor_sync(0xffffffffu, mx0, 2));
        mx1 = fmaxf(mx1, __shfl_xor_sync(0xffffffffu, mx1, 1));
        mx1 = fmaxf(mx1, __shfl_xor_sync(0xffffffffu, mx1, 2));
        const float mn0 = fmaxf(mrow0, mx0);
        const float mn1 = fmaxf(mrow1, mx1);
        const float cr0 = __expf(mrow0 - mn0);
        const float cr1 = __expf(mrow1 - mn1);
        mrow0 = mn0; mrow1 = mn1;
        float ls0 = 0.f, ls1 = 0.f;
#pragma unroll
        for (int nb = 0; nb < 8; nb++) {
            float p0 = __expf(S_[nb][0] - mn0);
            float p1 = __expf(S_[nb][1] - mn0);
            float p2 = __expf(S_[nb][2] - mn1);
            float p3 = __expf(S_[nb][3] - mn1);
            S_[nb][0] = p0; S_[nb][1] = p1; S_[nb][2] = p2; S_[nb][3] = p3;
            ls0 += p0 + p1; ls1 += p2 + p3;
        }
        ls0 += __shfl_xor_sync(0xffffffffu, ls0, 1);
        ls0 += __shfl_xor_sync(0xffffffffu, ls0, 2);
        ls1 += __shfl_xor_sync(0xffffffffu, ls1, 1);
        ls1 += __shfl_xor_sync(0xffffffffu, ls1, 2);
        lrow0 = lrow0 * cr0 + ls0;
        lrow1 = lrow1 * cr1 + ls1;

        // ---- pack P (hi/lo) into A-fragments ----
        uint32_t aPh[4][4], aPl[4][4];
#pragma unroll
        for (int kj = 0; kj < 4; kj++) {
#pragma unroll
            for (int half = 0; half < 2; half++) {       // half 0: nb=2kj (k0-7), 1: nb=2kj+1 (k8-15)
                const int nb = kj*2 + half;
                float p0 = S_[nb][0], p1 = S_[nb][1], p2 = S_[nb][2], p3 = S_[nb][3];
                __nv_bfloat16 h0 = __float2bfloat16(p0), h1 = __float2bfloat16(p1);
                __nv_bfloat16 h2 = __float2bfloat16(p2), h3 = __float2bfloat16(p3);
                aPh[kj][half*2+0] = packbf(p0, p1);       // a0/a2: row lq
                aPh[kj][half*2+1] = packbf(p2, p3);       // a1/a3: row lq+8
                aPl[kj][half*2+0] = packbf(p0 - __bfloat162float(h0), p1 - __bfloat162float(h1));
                aPl[kj][half*2+1] = packbf(p2 - __bfloat162float(h2), p3 - __bfloat162float(h3));
            }
        }
        // fix ordering: a-frag order is {a0(row,klo), a1(row+8,klo), a2(row,khi), a3(row+8,khi)}
        // half=0 wrote [0],[1]; half=1 wrote [2],[3] — matches (a0,a1)=(k0-7), (a2,a3)=(k8-15). OK.

        // ---- rescale O ----
#pragma unroll
        for (int nb = 0; nb < 16; nb++) {
            O_[nb][0] *= cr0; O_[nb][1] *= cr0;
            O_[nb][2] *= cr1; O_[nb][3] *= cr1;
        }

        // ---- O += P V (3-pass split), V via ldmatrix.trans ----
        const uint32_t vrow = (l & 15);
        const uint32_t vcol = ((l >> 4) << 3);
#pragma unroll
        for (int kj = 0; kj < 4; kj++) {
#pragma unroll
            for (int p = 0; p < 8; p++) {
                uint32_t vhf[4], vlf[4];
                uint32_t addr = base + 2*KOPB + (kj*16 + vrow) * KROWB + (p*16 + vcol) * 2;
                ldsm4t(vhf, addr);
                ldsm4t(vlf, addr + KOPB);
                mma16816(O_[p*2+0], aPh[kj], vhf[0], vhf[1]);
                mma16816(O_[p*2+0], aPh[kj], vlf[0], vlf[1]);
                mma16816(O_[p*2+0], aPl[kj], vhf[0], vhf[1]);
                mma16816(O_[p*2+1], aPh[kj], vhf[2], vhf[3]);
                mma16816(O_[p*2+1], aPh[kj], vlf[2], vlf[3]);
                mma16816(O_[p*2+1], aPl[kj], vhf[2], vhf[3]);
            }
        }
    }

    // ---- epilogue: normalize, split to bf16 hi/lo, store ----
    const float li0 = 1.f / lrow0;
    const float li1 = 1.f / lrow1;
    const size_t ra = (size_t)(R + lq) * HD + hoff;
    const size_t rb = (size_t)(R + lq + 8) * HD + hoff;
#pragma unroll
    for (int nb = 0; nb < 16; nb++) {
        const int c = nb*8 + lc;
        float a0 = O_[nb][0] * li0, a1 = O_[nb][1] * li0;
        float b0 = O_[nb][2] * li1, b1 = O_[nb][3] * li1;
        __nv_bfloat16 ha0 = __float2bfloat16(a0), ha1 = __float2bfloat16(a1);
        __nv_bfloat16 hb0 = __float2bfloat16(b0), hb1 = __float2bfloat16(b1);
        *(uint32_t*)&Ohi[ra + c] = packbf(a0, a1);
        *(uint32_t*)&Ohi[rb + c] = packbf(b0, b1);
        *(uint32_t*)&Olo[ra + c] = packbf(a0 - __bfloat162float(ha0), a1 - __bfloat162float(ha1));
        *(uint32_t*)&Olo[rb + c] = packbf(b0 - __bfloat162float(hb0), b1 - __bfloat162float(hb1));
    }
}

// ---------------- launch ---------------------------------------------------------
extern "C" void kernel_launch(void* const* d_in, const int* in_sizes, int n_in,
                              void* d_out, int out_size)
{
    const float* x  = (const float*)d_in[0];
    const float* wq = (const float*)d_in[2];
    const float* wk = (const float*)d_in[3];
    const float* wv = (const float*)d_in[4];
    const float* wo = (const float*)d_in[5];
    float* out = (float*)d_out;

    float *qp, *kp, *vp;
    cudaGetSymbolAddress((void**)&qp, g_q);
    cudaGetSymbolAddress((void**)&kp, g_k);
    cudaGetSymbolAddress((void**)&vp, g_v);

    __nv_bfloat16 *xhi, *xlo, *wqhi, *wqlo, *wkhi, *wklo, *wvhi, *wvlo, *wohi, *wolo;
    __nv_bfloat16 *qhi, *qlo, *khi, *klo, *vhi, *vlo, *aohi, *aolo;
    cudaGetSymbolAddress((void**)&xhi,  g_xhi);  cudaGetSymbolAddress((void**)&xlo,  g_xlo);
    cudaGetSymbolAddress((void**)&wqhi, g_wqhi); cudaGetSymbolAddress((void**)&wqlo, g_wqlo);
    cudaGetSymbolAddress((void**)&wkhi, g_wkhi); cudaGetSymbolAddress((void**)&wklo, g_wklo);
    cudaGetSymbolAddress((void**)&wvhi, g_wvhi); cudaGetSymbolAddress((void**)&wvlo, g_wvlo);
    cudaGetSymbolAddress((void**)&wohi, g_wohi); cudaGetSymbolAddress((void**)&wolo, g_wolo);
    cudaGetSymbolAddress((void**)&qhi,  g_qhi);  cudaGetSymbolAddress((void**)&qlo,  g_qlo);
    cudaGetSymbolAddress((void**)&khi,  g_khi);  cudaGetSymbolAddress((void**)&klo,  g_klo);
    cudaGetSymbolAddress((void**)&vhi,  g_vhi);  cudaGetSymbolAddress((void**)&vlo,  g_vlo);
    cudaGetSymbolAddress((void**)&aohi, g_aohi); cudaGetSymbolAddress((void**)&aolo, g_aolo);

    cudaFuncSetAttribute(gemm_mma_kernel,
                         cudaFuncAttributeMaxDynamicSharedMemorySize, GSM);
    cudaFuncSetAttribute(attn_mma_kernel,
                         cudaFuncAttributeMaxDynamicSharedMemorySize, ASMEM);

    const int n4x = S_LEN * D_IN / 4;
    const int n4w = HD * D_IN / 4;
    cvt_split_kernel<<<(n4x + 255)/256, 256>>>(x,  xhi,  xlo,  n4x);
    cvt_split_kernel<<<(n4w + 255)/256, 256>>>(wq, wqhi, wqlo, n4w);
    cvt_split_kernel<<<(n4w + 255)/256, 256>>>(wk, wkhi, wklo, n4w);
    cvt_split_kernel<<<(n4w + 255)/256, 256>>>(wv, wvhi, wvlo, n4w);
    cvt_split_kernel<<<(n4w + 255)/256, 256>>>(wo, wohi, wolo, n4w);

    dim3 gg(GN/128, GM/128);
    gemm_mma_kernel<<<gg, 256, GSM>>>(xhi, xlo, wqhi, wqlo, qp);
    gemm_mma_kernel<<<gg, 256, GSM>>>(xhi, xlo, wkhi, wklo, kp);
    gemm_mma_kernel<<<gg, 256, GSM>>>(xhi, xlo, wvhi, wvlo, vp);

    rope_table_kernel<<<(S_LEN*(DH/2) + 255)/256, 256>>>();
    rope_cvt_kernel<<<((S_LEN*HD/2) + 255)/256, 256>>>(qp, kp, qhi, qlo, khi, klo);
    cvt_split_kernel<<<(n4x + 255)/256, 256>>>(vp, vhi, vlo, n4x);

    attn_mma_kernel<<<dim3(S_LEN/128, NH), 256, ASMEM>>>(
        qhi, qlo, khi, klo, vhi, vlo, aohi, aolo);

    gemm_mma_kernel<<<gg, 256, GSM>>>(aohi, aolo, wohi, wolo, out);
}

// round 5
// speedup vs baseline: 4.4167x; 1.4120x over previous
#include <cuda_runtime.h>
#include <cuda_fp16.h>
#include <math.h>
#include <stdint.h>

#define S_LEN 4096
#define D_IN  2048
#define NH    16
#define DH    128
#define HD    2048
#define GM 4096
#define GN 2048
#define GK 2048

// ---------------- scratch (device globals: no allocation allowed) ----------
__device__ float g_q [(size_t)S_LEN * HD];
__device__ float g_k [(size_t)S_LEN * HD];
__device__ float g_v [(size_t)S_LEN * HD];
__device__ float g_cos[(size_t)S_LEN * (DH/2)];
__device__ float g_sin[(size_t)S_LEN * (DH/2)];
// fp16 operands: A-side split hi/lo, B-side single
__device__ __half g_xhi [(size_t)S_LEN * D_IN];
__device__ __half g_xlo [(size_t)S_LEN * D_IN];
__device__ __half g_wqh [(size_t)HD * D_IN];
__device__ __half g_wkh [(size_t)HD * D_IN];
__device__ __half g_wvh [(size_t)HD * D_IN];
__device__ __half g_woh [(size_t)D_IN * HD];
__device__ __half g_qhi [(size_t)S_LEN * HD];
__device__ __half g_qlo [(size_t)S_LEN * HD];
__device__ __half g_khi [(size_t)S_LEN * HD];
__device__ __half g_vhi [(size_t)S_LEN * HD];
__device__ __half g_aohi[(size_t)S_LEN * HD];
__device__ __half g_aolo[(size_t)S_LEN * HD];

// ---------------- PTX helpers ------------------------------------------------
__device__ __forceinline__ uint32_t smem_u32(const void* p) {
    uint32_t a;
    asm("{ .reg .u64 t; cvta.to.shared.u64 t, %1; cvt.u32.u64 %0, t; }"
        : "=r"(a) : "l"(p));
    return a;
}
__device__ __forceinline__ void cpa16(uint32_t dst, const void* src) {
    asm volatile("cp.async.cg.shared.global [%0], [%1], 16;" :: "r"(dst), "l"(src));
}
__device__ __forceinline__ void cpa_commit() { asm volatile("cp.async.commit_group;"); }
__device__ __forceinline__ void cpa_wait0()  { asm volatile("cp.async.wait_group 0;"); }

__device__ __forceinline__ void ldsm4(uint32_t r[4], uint32_t addr) {
    asm volatile("ldmatrix.sync.aligned.m8n8.x4.shared.b16 {%0,%1,%2,%3}, [%4];"
        : "=r"(r[0]), "=r"(r[1]), "=r"(r[2]), "=r"(r[3]) : "r"(addr));
}
__device__ __forceinline__ void ldsm4t(uint32_t r[4], uint32_t addr) {
    asm volatile("ldmatrix.sync.aligned.m8n8.x4.trans.shared.b16 {%0,%1,%2,%3}, [%4];"
        : "=r"(r[0]), "=r"(r[1]), "=r"(r[2]), "=r"(r[3]) : "r"(addr));
}
__device__ __forceinline__ void mma16816h(float c[4], const uint32_t a[4],
                                          uint32_t b0, uint32_t b1) {
    asm volatile(
        "mma.sync.aligned.m16n8k16.row.col.f32.f16.f16.f32 "
        "{%0,%1,%2,%3}, {%4,%5,%6,%7}, {%8,%9}, {%0,%1,%2,%3};"
        : "+f"(c[0]), "+f"(c[1]), "+f"(c[2]), "+f"(c[3])
        : "r"(a[0]), "r"(a[1]), "r"(a[2]), "r"(a[3]), "r"(b0), "r"(b1));
}
__device__ __forceinline__ uint32_t packh(float a, float b) {
    __half2 t = __floats2half2_rn(a, b);
    return *(uint32_t*)&t;
}

// ---------------- fp32 -> fp16 conversions -------------------------------------
__global__ void cvt_split_h_kernel(const float* __restrict__ in,
                                   __half* __restrict__ hi,
                                   __half* __restrict__ lo, int n4) {
    int i = blockIdx.x * blockDim.x + threadIdx.x;
    if (i >= n4) return;
    float4 v = ((const float4*)in)[i];
    __half h0 = __float2half_rn(v.x);
    __half h1 = __float2half_rn(v.y);
    __half h2 = __float2half_rn(v.z);
    __half h3 = __float2half_rn(v.w);
    ((uint32_t*)hi)[2*i]   = packh(v.x, v.y);
    ((uint32_t*)hi)[2*i+1] = packh(v.z, v.w);
    ((uint32_t*)lo)[2*i]   = packh(v.x - __half2float(h0), v.y - __half2float(h1));
    ((uint32_t*)lo)[2*i+1] = packh(v.z - __half2float(h2), v.w - __half2float(h3));
}

__global__ void cvt_h_kernel(const float* __restrict__ in,
                             __half* __restrict__ out, int n4) {
    int i = blockIdx.x * blockDim.x + threadIdx.x;
    if (i >= n4) return;
    float4 v = ((const float4*)in)[i];
    ((uint32_t*)out)[2*i]   = packh(v.x, v.y);
    ((uint32_t*)out)[2*i+1] = packh(v.z, v.w);
}

// ---------------- mma.sync fp16 2-pass GEMM ------------------------------------
// C[M,N] = (Ah+Al)[M,K] * Bh[N,K]^T. 128x128 tile, 8 warps, K slab 32.
#define KS   32
#define ROWB 80
#define OPB  (128*ROWB)
#define STB  (3*OPB)
#define GSM  (2*STB)

__global__ void __launch_bounds__(256, 1) gemm_mma_kernel(
    const __half* __restrict__ Ah, const __half* __restrict__ Al,
    const __half* __restrict__ Bh, float* __restrict__ C)
{
    extern __shared__ char smraw[];
    const uint32_t sb = smem_u32(smraw);
    const int tid = threadIdx.x;
    const int w   = tid >> 5;
    const int l   = tid & 31;
    const int wm  = w & 3;
    const int wn  = w >> 2;
    const int m0  = blockIdx.y * 128;
    const int n0  = blockIdx.x * 128;

    const __half* ops[3] = {
        Ah + (size_t)m0 * GK, Al + (size_t)m0 * GK, Bh + (size_t)n0 * GK };

    const int r0 = tid >> 2, c0 = tid & 3;
    const int r1 = (tid + 256) >> 2, c1 = tid & 3;

    float acc[2][8][4];
#pragma unroll
    for (int a = 0; a < 2; a++)
#pragma unroll
        for (int b = 0; b < 8; b++)
#pragma unroll
            for (int c = 0; c < 4; c++) acc[a][b][c] = 0.f;

#pragma unroll
    for (int op = 0; op < 3; op++) {
        cpa16(sb + op*OPB + r0*ROWB + c0*16, ops[op] + (size_t)r0 * GK + c0*8);
        cpa16(sb + op*OPB + r1*ROWB + c1*16, ops[op] + (size_t)r1 * GK + c1*8);
    }
    cpa_commit();

    const int a_row = wm*32 + (l & 15);
    const int a_kc  = (l >> 4) * 8;
    const int b_row = wn*64 + (l & 7) + ((l >> 4) << 3);
    const int b_kc  = ((l >> 3) & 1) * 8;

    const int NSLAB = GK / KS;
    for (int s = 0; s < NSLAB; s++) {
        const int buf = s & 1;
        cpa_wait0();
        __syncthreads();
        if (s + 1 < NSLAB) {
            const int k0 = (s + 1) * KS;
            const uint32_t dst = sb + (buf ^ 1) * STB;
#pragma unroll
            for (int op = 0; op < 3; op++) {
                cpa16(dst + op*OPB + r0*ROWB + c0*16, ops[op] + (size_t)r0*GK + k0 + c0*8);
                cpa16(dst + op*OPB + r1*ROWB + c1*16, ops[op] + (size_t)r1*GK + k0 + c1*8);
            }
            cpa_commit();
        }
        const uint32_t base = sb + buf * STB;
#pragma unroll
        for (int ks = 0; ks < 2; ks++) {
            uint32_t ah[2][4], al[2][4];
#pragma unroll
            for (int mt = 0; mt < 2; mt++) {
                uint32_t aaddr = base + (a_row + mt*16) * ROWB + (ks*16 + a_kc) * 2;
                ldsm4(ah[mt], aaddr);
                ldsm4(al[mt], aaddr + OPB);
            }
#pragma unroll
            for (int np = 0; np < 4; np++) {
                uint32_t bh[4];
                uint32_t baddr = base + 2*OPB + (b_row + np*16) * ROWB + (ks*16 + b_kc) * 2;
                ldsm4(bh, baddr);
#pragma unroll
                for (int mt = 0; mt < 2; mt++) {
                    mma16816h(acc[mt][np*2+0], ah[mt], bh[0], bh[1]);
                    mma16816h(acc[mt][np*2+0], al[mt], bh[0], bh[1]);
                    mma16816h(acc[mt][np*2+1], ah[mt], bh[2], bh[3]);
                    mma16816h(acc[mt][np*2+1], al[mt], bh[2], bh[3]);
                }
            }
        }
        __syncthreads();
    }

#pragma unroll
    for (int mt = 0; mt < 2; mt++) {
        const int row = m0 + wm*32 + mt*16 + (l >> 2);
#pragma unroll
        for (int nt = 0; nt < 8; nt++) {
            const int col = n0 + wn*64 + nt*8 + (l & 3) * 2;
            float2 v0 = make_float2(acc[mt][nt][0], acc[mt][nt][1]);
            float2 v1 = make_float2(acc[mt][nt][2], acc[mt][nt][3]);
            *(float2*)&C[(size_t)row * GN + col]       = v0;
            *(float2*)&C[(size_t)(row + 8) * GN + col] = v1;
        }
    }
}

// ---------------- RoPE ---------------------------------------------------------
__global__ void rope_table_kernel() {
    int idx = blockIdx.x * blockDim.x + threadIdx.x;
    if (idx >= S_LEN * (DH/2)) return;
    int row = idx / (DH/2);
    int kp  = idx % (DH/2);
    float inv = (float)pow(10000.0, -(double)(2*kp) / (double)DH);
    float fr  = (float)row * inv;
    g_cos[idx] = cosf(fr);
    g_sin[idx] = sinf(fr);
}

// RoPE; q -> fp16 hi/lo (A-side of S), k -> single fp16 (B-side of S)
__global__ void rope_cvt_kernel(const float* __restrict__ q, const float* __restrict__ k,
                                __half* __restrict__ qhi, __half* __restrict__ qlo,
                                __half* __restrict__ khi)
{
    size_t idx = (size_t)blockIdx.x * blockDim.x + threadIdx.x;
    if (idx >= (size_t)S_LEN * HD / 2) return;
    size_t row = idx / (HD/2);
    int colpair = (int)(idx % (HD/2));
    int d  = (colpair * 2) & (DH - 1);
    int kp = d >> 1;
    float c = g_cos[row * (DH/2) + kp];
    float s = g_sin[row * (DH/2) + kp];
    size_t base = row * HD + colpair * 2;

    float q0 = q[base], q1 = q[base+1];
    float rq0 = q0 * c - q1 * s;
    float rq1 = q1 * c + q0 * s;
    __half h0 = __float2half_rn(rq0), h1 = __float2half_rn(rq1);
    *(uint32_t*)&qhi[base] = packh(rq0, rq1);
    *(uint32_t*)&qlo[base] = packh(rq0 - __half2float(h0), rq1 - __half2float(h1));

    float k0 = k[base], k1 = k[base+1];
    float rk0 = k0 * c - k1 * s;
    float rk1 = k1 * c + k0 * s;
    *(uint32_t*)&khi[base] = packh(rk0, rk1);
}

// ---------------- tensor-core flash attention (fp16 2-pass, causal) ------------
#define KROWB 272
#define KOPB  (64*KROWB)          // 17408 per operand (K or V)
#define KSTB  (2*KOPB)            // per stage
#define ASMEM (2*KSTB)            // 69632

__device__ __forceinline__ void attn_load_kv(
    uint32_t dstbase,
    const __half* __restrict__ kh, const __half* __restrict__ vh,
    int kvbase, int tid)
{
#pragma unroll
    for (int i = 0; i < 8; i++) {
        const int op  = i >> 2;
        const int rem = (i & 3) * 256 + tid;
        const int row = rem >> 4;
        const int col = rem & 15;
        const __half* src = (op == 0) ? kh : vh;
        cpa16(dstbase + op*KOPB + row*KROWB + col*16,
              src + (size_t)(kvbase + row) * HD + col*8);
    }
    cpa_commit();
}

__global__ void __launch_bounds__(256, 1) attn_mma_kernel(
    const __half* __restrict__ Qh, const __half* __restrict__ Ql,
    const __half* __restrict__ Kh, const __half* __restrict__ Vh,
    __half* __restrict__ Ohi, __half* __restrict__ Olo)
{
    extern __shared__ char smraw[];
    const uint32_t sb = smem_u32(smraw);
    const int tid = threadIdx.x;
    const int w = tid >> 5, l = tid & 31;
    const int qb = gridDim.x - 1 - blockIdx.x;   // big tiles first
    const int h  = blockIdx.y;
    const int lq = l >> 2;
    const int lc = (l & 3) * 2;
    const float scale = 0.08838834764831845f;

    const int R = qb * 128 + w * 16;
    const size_t hoff = (size_t)h * DH;
    const __half* kh = Kh + hoff;
    const __half* vh = Vh + hoff;

    uint32_t qfh[8][4], qfl[8][4];
    {
        const __half* qhp = Qh + hoff;
        const __half* qlp = Ql + hoff;
        const size_t ra = (size_t)(R + lq) * HD;
        const size_t rb = (size_t)(R + lq + 8) * HD;
#pragma unroll
        for (int kc = 0; kc < 8; kc++) {
            const int c = kc * 16 + lc;
            qfh[kc][0] = *(const uint32_t*)&qhp[ra + c];
            qfh[kc][1] = *(const uint32_t*)&qhp[rb + c];
            qfh[kc][2] = *(const uint32_t*)&qhp[ra + c + 8];
            qfh[kc][3] = *(const uint32_t*)&qhp[rb + c + 8];
            qfl[kc][0] = *(const uint32_t*)&qlp[ra + c];
            qfl[kc][1] = *(const uint32_t*)&qlp[rb + c];
            qfl[kc][2] = *(const uint32_t*)&qlp[ra + c + 8];
            qfl[kc][3] = *(const uint32_t*)&qlp[rb + c + 8];
        }
    }

    float O_[16][4];
#pragma unroll
    for (int nb = 0; nb < 16; nb++)
#pragma unroll
        for (int e = 0; e < 4; e++) O_[nb][e] = 0.f;
    float mrow0 = -INFINITY, mrow1 = -INFINITY;
    float lrow0 = 0.f, lrow1 = 0.f;

    const int nkv = 2 * qb + 2;
    attn_load_kv(sb, kh, vh, 0, tid);

    for (int jb = 0; jb < nkv; jb++) {
        const uint32_t base = sb + (jb & 1) * KSTB;
        cpa_wait0();
        __syncthreads();
        if (jb + 1 < nkv)
            attn_load_kv(sb + ((jb + 1) & 1) * KSTB, kh, vh, (jb + 1) * 64, tid);

        // ---- S = Q K^T (16 x 64), 2-pass ----
        float S_[8][4];
#pragma unroll
        for (int nb = 0; nb < 8; nb++)
#pragma unroll
            for (int e = 0; e < 4; e++) S_[nb][e] = 0.f;

        const uint32_t krow = (l & 7) + ((l >> 4) << 3);
        const uint32_t kcol = ((l >> 3) & 1) * 8;
#pragma unroll
        for (int kc = 0; kc < 8; kc++) {
#pragma unroll
            for (int p = 0; p < 4; p++) {
                uint32_t bh[4];
                uint32_t addr = base + (p*16 + krow) * KROWB + (kc*16 + kcol) * 2;
                ldsm4(bh, addr);
                mma16816h(S_[p*2+0], qfh[kc], bh[0], bh[1]);
                mma16816h(S_[p*2+0], qfl[kc], bh[0], bh[1]);
                mma16816h(S_[p*2+1], qfh[kc], bh[2], bh[3]);
                mma16816h(S_[p*2+1], qfl[kc], bh[2], bh[3]);
            }
        }

        // ---- online softmax ----
        const int kvb = jb * 64;
        const bool domask = (kvb + 63 > R);
        float mx0 = -INFINITY, mx1 = -INFINITY;
#pragma unroll
        for (int nb = 0; nb < 8; nb++) {
            const int colb = kvb + nb*8 + lc;
#pragma unroll
            for (int e = 0; e < 4; e++) {
                float v = S_[nb][e] * scale;
                if (domask) {
                    int row = R + lq + (e >> 1) * 8;
                    int col = colb + (e & 1);
                    if (col > row) v = -INFINITY;
                }
                S_[nb][e] = v;
                if (e < 2) mx0 = fmaxf(mx0, v); else mx1 = fmaxf(mx1, v);
            }
        }
        mx0 = fmaxf(mx0, __shfl_xor_sync(0xffffffffu, mx0, 1));
        mx0 = fmaxf(mx0, __shfl_xor_sync(0xffffffffu, mx0, 2));
        mx1 = fmaxf(mx1, __shfl_xor_sync(0xffffffffu, mx1, 1));
        mx1 = fmaxf(mx1, __shfl_xor_sync(0xffffffffu, mx1, 2));
        const float mn0 = fmaxf(mrow0, mx0);
        const float mn1 = fmaxf(mrow1, mx1);
        const float cr0 = __expf(mrow0 - mn0);
        const float cr1 = __expf(mrow1 - mn1);
        mrow0 = mn0; mrow1 = mn1;
        float ls0 = 0.f, ls1 = 0.f;
#pragma unroll
        for (int nb = 0; nb < 8; nb++) {
            float p0 = __expf(S_[nb][0] - mn0);
            float p1 = __expf(S_[nb][1] - mn0);
            float p2 = __expf(S_[nb][2] - mn1);
            float p3 = __expf(S_[nb][3] - mn1);
            S_[nb][0] = p0; S_[nb][1] = p1; S_[nb][2] = p2; S_[nb][3] = p3;
            ls0 += p0 + p1; ls1 += p2 + p3;
        }
        ls0 += __shfl_xor_sync(0xffffffffu, ls0, 1);
        ls0 += __shfl_xor_sync(0xffffffffu, ls0, 2);
        ls1 += __shfl_xor_sync(0xffffffffu, ls1, 1);
        ls1 += __shfl_xor_sync(0xffffffffu, ls1, 2);
        lrow0 = lrow0 * cr0 + ls0;
        lrow1 = lrow1 * cr1 + ls1;

        // ---- pack P (hi/lo fp16) into A-fragments ----
        uint32_t aPh[4][4], aPl[4][4];
#pragma unroll
        for (int kj = 0; kj < 4; kj++) {
#pragma unroll
            for (int half = 0; half < 2; half++) {
                const int nb = kj*2 + half;
                float p0 = S_[nb][0], p1 = S_[nb][1], p2 = S_[nb][2], p3 = S_[nb][3];
                __half h0 = __float2half_rn(p0), h1 = __float2half_rn(p1);
                __half h2 = __float2half_rn(p2), h3 = __float2half_rn(p3);
                aPh[kj][half*2+0] = packh(p0, p1);
                aPh[kj][half*2+1] = packh(p2, p3);
                aPl[kj][half*2+0] = packh(p0 - __half2float(h0), p1 - __half2float(h1));
                aPl[kj][half*2+1] = packh(p2 - __half2float(h2), p3 - __half2float(h3));
            }
        }

        // ---- rescale O ----
#pragma unroll
        for (int nb = 0; nb < 16; nb++) {
            O_[nb][0] *= cr0; O_[nb][1] *= cr0;
            O_[nb][2] *= cr1; O_[nb][3] *= cr1;
        }

        // ---- O += P V (2-pass), V via ldmatrix.trans ----
        const uint32_t vrow = (l & 15);
        const uint32_t vcol = ((l >> 4) << 3);
#pragma unroll
        for (int kj = 0; kj < 4; kj++) {
#pragma unroll
            for (int p = 0; p < 8; p++) {
                uint32_t vf[4];
                uint32_t addr = base + KOPB + (kj*16 + vrow) * KROWB + (p*16 + vcol) * 2;
                ldsm4t(vf, addr);
                mma16816h(O_[p*2+0], aPh[kj], vf[0], vf[1]);
                mma16816h(O_[p*2+0], aPl[kj], vf[0], vf[1]);
                mma16816h(O_[p*2+1], aPh[kj], vf[2], vf[3]);
                mma16816h(O_[p*2+1], aPl[kj], vf[2], vf[3]);
            }
        }
    }

    // ---- epilogue: normalize, split to fp16 hi/lo, store ----
    const float li0 = 1.f / lrow0;
    const float li1 = 1.f / lrow1;
    const size_t ra = (size_t)(R + lq) * HD + hoff;
    const size_t rb = (size_t)(R + lq + 8) * HD + hoff;
#pragma unroll
    for (int nb = 0; nb < 16; nb++) {
        const int c = nb*8 + lc;
        float a0 = O_[nb][0] * li0, a1 = O_[nb][1] * li0;
        float b0 = O_[nb][2] * li1, b1 = O_[nb][3] * li1;
        __half ha0 = __float2half_rn(a0), ha1 = __float2half_rn(a1);
        __half hb0 = __float2half_rn(b0), hb1 = __float2half_rn(b1);
        *(uint32_t*)&Ohi[ra + c] = packh(a0, a1);
        *(uint32_t*)&Ohi[rb + c] = packh(b0, b1);
        *(uint32_t*)&Olo[ra + c] = packh(a0 - __half2float(ha0), a1 - __half2float(ha1));
        *(uint32_t*)&Olo[rb + c] = packh(b0 - __half2float(hb0), b1 - __half2float(hb1));
    }
}

// ---------------- launch ---------------------------------------------------------
extern "C" void kernel_launch(void* const* d_in, const int* in_sizes, int n_in,
                              void* d_out, int out_size)
{
    const float* x  = (const float*)d_in[0];
    const float* wq = (const float*)d_in[2];
    const float* wk = (const float*)d_in[3];
    const float* wv = (const float*)d_in[4];
    const float* wo = (const float*)d_in[5];
    float* out = (float*)d_out;

    float *qp, *kp, *vp;
    cudaGetSymbolAddress((void**)&qp, g_q);
    cudaGetSymbolAddress((void**)&kp, g_k);
    cudaGetSymbolAddress((void**)&vp, g_v);

    __half *xhi, *xlo, *wqh, *wkh, *wvh, *woh;
    __half *qhi, *qlo, *khi, *vhi, *aohi, *aolo;
    cudaGetSymbolAddress((void**)&xhi,  g_xhi);  cudaGetSymbolAddress((void**)&xlo,  g_xlo);
    cudaGetSymbolAddress((void**)&wqh,  g_wqh);  cudaGetSymbolAddress((void**)&wkh,  g_wkh);
    cudaGetSymbolAddress((void**)&wvh,  g_wvh);  cudaGetSymbolAddress((void**)&woh,  g_woh);
    cudaGetSymbolAddress((void**)&qhi,  g_qhi);  cudaGetSymbolAddress((void**)&qlo,  g_qlo);
    cudaGetSymbolAddress((void**)&khi,  g_khi);  cudaGetSymbolAddress((void**)&vhi,  g_vhi);
    cudaGetSymbolAddress((void**)&aohi, g_aohi); cudaGetSymbolAddress((void**)&aolo, g_aolo);

    cudaFuncSetAttribute(gemm_mma_kernel,
                         cudaFuncAttributeMaxDynamicSharedMemorySize, GSM);
    cudaFuncSetAttribute(attn_mma_kernel,
                         cudaFuncAttributeMaxDynamicSharedMemorySize, ASMEM);

    const int n4x = S_LEN * D_IN / 4;
    const int n4w = HD * D_IN / 4;
    cvt_split_h_kernel<<<(n4x + 255)/256, 256>>>(x, xhi, xlo, n4x);
    cvt_h_kernel<<<(n4w + 255)/256, 256>>>(wq, wqh, n4w);
    cvt_h_kernel<<<(n4w + 255)/256, 256>>>(wk, wkh, n4w);
    cvt_h_kernel<<<(n4w + 255)/256, 256>>>(wv, wvh, n4w);
    cvt_h_kernel<<<(n4w + 255)/256, 256>>>(wo, woh, n4w);

    dim3 gg(GN/128, GM/128);
    gemm_mma_kernel<<<gg, 256, GSM>>>(xhi, xlo, wqh, qp);
    gemm_mma_kernel<<<gg, 256, GSM>>>(xhi, xlo, wkh, kp);
    gemm_mma_kernel<<<gg, 256, GSM>>>(xhi, xlo, wvh, vp);

    rope_table_kernel<<<(S_LEN*(DH/2) + 255)/256, 256>>>();
    rope_cvt_kernel<<<((S_LEN*HD/2) + 255)/256, 256>>>(qp, kp, qhi, qlo, khi);
    cvt_h_kernel<<<(n4x + 255)/256, 256>>>(vp, vhi, n4x);

    attn_mma_kernel<<<dim3(S_LEN/128, NH), 256, ASMEM>>>(
        qhi, qlo, khi, vhi, aohi, aolo);

    gemm_mma_kernel<<<gg, 256, GSM>>>(aohi, aolo, woh, out);
}

// round 6
// speedup vs baseline: 5.2187x; 1.1816x over previous
#include <cuda_runtime.h>
#include <cuda_fp16.h>
#include <math.h>
#include <stdint.h>

#define S_LEN 4096
#define D_IN  2048
#define NH    16
#define DH    128
#define HD    2048
#define GM 4096
#define GN 2048
#define GK 2048

// ---------------- scratch (device globals: no allocation allowed) ----------
__device__ float g_cos[(size_t)S_LEN * (DH/2)];
__device__ float g_sin[(size_t)S_LEN * (DH/2)];
__device__ __half g_xhi [(size_t)S_LEN * D_IN];
__device__ __half g_xlo [(size_t)S_LEN * D_IN];
__device__ __half g_wqh [(size_t)HD * D_IN];
__device__ __half g_wkh [(size_t)HD * D_IN];
__device__ __half g_wvh [(size_t)HD * D_IN];
__device__ __half g_woh [(size_t)D_IN * HD];
__device__ __half g_qh  [(size_t)S_LEN * HD];
__device__ __half g_kh  [(size_t)S_LEN * HD];
__device__ __half g_vh  [(size_t)S_LEN * HD];
__device__ __half g_aohi[(size_t)S_LEN * HD];
__device__ __half g_aolo[(size_t)S_LEN * HD];

// ---------------- PTX helpers ------------------------------------------------
__device__ __forceinline__ uint32_t smem_u32(const void* p) {
    uint32_t a;
    asm("{ .reg .u64 t; cvta.to.shared.u64 t, %1; cvt.u32.u64 %0, t; }"
        : "=r"(a) : "l"(p));
    return a;
}
__device__ __forceinline__ void cpa16(uint32_t dst, const void* src) {
    asm volatile("cp.async.cg.shared.global [%0], [%1], 16;" :: "r"(dst), "l"(src));
}
__device__ __forceinline__ void cpa_commit() { asm volatile("cp.async.commit_group;"); }
__device__ __forceinline__ void cpa_wait0()  { asm volatile("cp.async.wait_group 0;"); }

__device__ __forceinline__ void ldsm4(uint32_t r[4], uint32_t addr) {
    asm volatile("ldmatrix.sync.aligned.m8n8.x4.shared.b16 {%0,%1,%2,%3}, [%4];"
        : "=r"(r[0]), "=r"(r[1]), "=r"(r[2]), "=r"(r[3]) : "r"(addr));
}
__device__ __forceinline__ void ldsm4t(uint32_t r[4], uint32_t addr) {
    asm volatile("ldmatrix.sync.aligned.m8n8.x4.trans.shared.b16 {%0,%1,%2,%3}, [%4];"
        : "=r"(r[0]), "=r"(r[1]), "=r"(r[2]), "=r"(r[3]) : "r"(addr));
}
__device__ __forceinline__ void mma16816h(float c[4], const uint32_t a[4],
                                          uint32_t b0, uint32_t b1) {
    asm volatile(
        "mma.sync.aligned.m16n8k16.row.col.f32.f16.f16.f32 "
        "{%0,%1,%2,%3}, {%4,%5,%6,%7}, {%8,%9}, {%0,%1,%2,%3};"
        : "+f"(c[0]), "+f"(c[1]), "+f"(c[2]), "+f"(c[3])
        : "r"(a[0]), "r"(a[1]), "r"(a[2]), "r"(a[3]), "r"(b0), "r"(b1));
}
__device__ __forceinline__ uint32_t packh(float a, float b) {
    __half2 t = __floats2half2_rn(a, b);
    return *(uint32_t*)&t;
}

// ---------------- fp32 -> fp16 conversions -------------------------------------
__global__ void cvt_split_h_kernel(const float* __restrict__ in,
                                   __half* __restrict__ hi,
                                   __half* __restrict__ lo, int n4) {
    int i = blockIdx.x * blockDim.x + threadIdx.x;
    if (i >= n4) return;
    float4 v = ((const float4*)in)[i];
    __half h0 = __float2half_rn(v.x);
    __half h1 = __float2half_rn(v.y);
    __half h2 = __float2half_rn(v.z);
    __half h3 = __float2half_rn(v.w);
    ((uint32_t*)hi)[2*i]   = packh(v.x, v.y);
    ((uint32_t*)hi)[2*i+1] = packh(v.z, v.w);
    ((uint32_t*)lo)[2*i]   = packh(v.x - __half2float(h0), v.y - __half2float(h1));
    ((uint32_t*)lo)[2*i+1] = packh(v.z - __half2float(h2), v.w - __half2float(h3));
}

__global__ void cvt_h_kernel(const float* __restrict__ in,
                             __half* __restrict__ out, int n4) {
    int i = blockIdx.x * blockDim.x + threadIdx.x;
    if (i >= n4) return;
    float4 v = ((const float4*)in)[i];
    ((uint32_t*)out)[2*i]   = packh(v.x, v.y);
    ((uint32_t*)out)[2*i+1] = packh(v.z, v.w);
}

// ---------------- RoPE tables ---------------------------------------------------
__global__ void rope_table_kernel() {
    int idx = blockIdx.x * blockDim.x + threadIdx.x;
    if (idx >= S_LEN * (DH/2)) return;
    int row = idx / (DH/2);
    int kp  = idx % (DH/2);
    float inv = (float)pow(10000.0, -(double)(2*kp) / (double)DH);
    float fr  = (float)row * inv;
    g_cos[idx] = cosf(fr);
    g_sin[idx] = sinf(fr);
}

// ---------------- shared GEMM tiling constants ----------------------------------
#define KS   32
#define ROWB 80
#define OPB  (128*ROWB)
#define STB  (3*OPB)
#define GSM  (2*STB)

// ---------------- merged QKV GEMM: fp16 2-pass + fused RoPE + fp16 out ----------
// grid (48, 32): blockIdx.x>>4 selects {q,k,v}; epilogue applies RoPE (q,k) and
// writes fp16 directly.
__global__ void __launch_bounds__(256, 1) qkv_gemm_kernel(
    const __half* __restrict__ Ah, const __half* __restrict__ Al,
    const __half* __restrict__ Wq, const __half* __restrict__ Wk,
    const __half* __restrict__ Wv,
    __half* __restrict__ Qo, __half* __restrict__ Ko, __half* __restrict__ Vo)
{
    extern __shared__ char smraw[];
    const uint32_t sb = smem_u32(smraw);
    const int tid = threadIdx.x;
    const int w   = tid >> 5;
    const int l   = tid & 31;
    const int wm  = w & 3;
    const int wn  = w >> 2;
    const int m0  = blockIdx.y * 128;
    const int which = blockIdx.x >> 4;          // 0=q 1=k 2=v
    const int n0  = (blockIdx.x & 15) * 128;

    const __half* B = (which == 0) ? Wq : (which == 1) ? Wk : Wv;
    __half* Out     = (which == 0) ? Qo : (which == 1) ? Ko : Vo;

    const __half* ops[3] = {
        Ah + (size_t)m0 * GK, Al + (size_t)m0 * GK, B + (size_t)n0 * GK };

    const int r0 = tid >> 2, c0 = tid & 3;
    const int r1 = (tid + 256) >> 2, c1 = tid & 3;

    float acc[2][8][4];
#pragma unroll
    for (int a = 0; a < 2; a++)
#pragma unroll
        for (int b = 0; b < 8; b++)
#pragma unroll
            for (int c = 0; c < 4; c++) acc[a][b][c] = 0.f;

#pragma unroll
    for (int op = 0; op < 3; op++) {
        cpa16(sb + op*OPB + r0*ROWB + c0*16, ops[op] + (size_t)r0 * GK + c0*8);
        cpa16(sb + op*OPB + r1*ROWB + c1*16, ops[op] + (size_t)r1 * GK + c1*8);
    }
    cpa_commit();

    const int a_row = wm*32 + (l & 15);
    const int a_kc  = (l >> 4) * 8;
    const int b_row = wn*64 + (l & 7) + ((l >> 4) << 3);
    const int b_kc  = ((l >> 3) & 1) * 8;

    const int NSLAB = GK / KS;
    for (int s = 0; s < NSLAB; s++) {
        const int buf = s & 1;
        cpa_wait0();
        __syncthreads();
        if (s + 1 < NSLAB) {
            const int k0 = (s + 1) * KS;
            const uint32_t dst = sb + (buf ^ 1) * STB;
#pragma unroll
            for (int op = 0; op < 3; op++) {
                cpa16(dst + op*OPB + r0*ROWB + c0*16, ops[op] + (size_t)r0*GK + k0 + c0*8);
                cpa16(dst + op*OPB + r1*ROWB + c1*16, ops[op] + (size_t)r1*GK + k0 + c1*8);
            }
            cpa_commit();
        }
        const uint32_t base = sb + buf * STB;
#pragma unroll
        for (int ks = 0; ks < 2; ks++) {
            uint32_t ah[2][4], al[2][4];
#pragma unroll
            for (int mt = 0; mt < 2; mt++) {
                uint32_t aaddr = base + (a_row + mt*16) * ROWB + (ks*16 + a_kc) * 2;
                ldsm4(ah[mt], aaddr);
                ldsm4(al[mt], aaddr + OPB);
            }
#pragma unroll
            for (int np = 0; np < 4; np++) {
                uint32_t bh[4];
                uint32_t baddr = base + 2*OPB + (b_row + np*16) * ROWB + (ks*16 + b_kc) * 2;
                ldsm4(bh, baddr);
#pragma unroll
                for (int mt = 0; mt < 2; mt++) {
                    mma16816h(acc[mt][np*2+0], ah[mt], bh[0], bh[1]);
                    mma16816h(acc[mt][np*2+0], al[mt], bh[0], bh[1]);
                    mma16816h(acc[mt][np*2+1], ah[mt], bh[2], bh[3]);
                    mma16816h(acc[mt][np*2+1], al[mt], bh[2], bh[3]);
                }
            }
        }
        __syncthreads();
    }

    // ---- epilogue: optional RoPE, fp16 pack, store ----
#pragma unroll
    for (int mt = 0; mt < 2; mt++) {
        const int row = m0 + wm*32 + mt*16 + (l >> 2);
#pragma unroll
        for (int nt = 0; nt < 8; nt++) {
            const int gcol = n0 + wn*64 + nt*8 + (l & 3) * 2;   // even
            float a0 = acc[mt][nt][0], a1 = acc[mt][nt][1];
            float b0 = acc[mt][nt][2], b1 = acc[mt][nt][3];
            if (which < 2) {
                const int kp = (gcol & (DH - 1)) >> 1;
                float c0 = g_cos[(size_t)row * 64 + kp];
                float s0 = g_sin[(size_t)row * 64 + kp];
                float c1 = g_cos[(size_t)(row + 8) * 64 + kp];
                float s1 = g_sin[(size_t)(row + 8) * 64 + kp];
                float t0 = a0 * c0 - a1 * s0; a1 = a1 * c0 + a0 * s0; a0 = t0;
                float t1 = b0 * c1 - b1 * s1; b1 = b1 * c1 + b0 * s1; b0 = t1;
            }
            *(uint32_t*)&Out[(size_t)row * HD + gcol]       = packh(a0, a1);
            *(uint32_t*)&Out[(size_t)(row + 8) * HD + gcol] = packh(b0, b1);
        }
    }
}

// ---------------- output-projection GEMM (fp16 2-pass, fp32 out) ----------------
__global__ void __launch_bounds__(256, 1) gemm_mma_kernel(
    const __half* __restrict__ Ah, const __half* __restrict__ Al,
    const __half* __restrict__ Bh, float* __restrict__ C)
{
    extern __shared__ char smraw[];
    const uint32_t sb = smem_u32(smraw);
    const int tid = threadIdx.x;
    const int w   = tid >> 5;
    const int l   = tid & 31;
    const int wm  = w & 3;
    const int wn  = w >> 2;
    const int m0  = blockIdx.y * 128;
    const int n0  = blockIdx.x * 128;

    const __half* ops[3] = {
        Ah + (size_t)m0 * GK, Al + (size_t)m0 * GK, Bh + (size_t)n0 * GK };

    const int r0 = tid >> 2, c0 = tid & 3;
    const int r1 = (tid + 256) >> 2, c1 = tid & 3;

    float acc[2][8][4];
#pragma unroll
    for (int a = 0; a < 2; a++)
#pragma unroll
        for (int b = 0; b < 8; b++)
#pragma unroll
            for (int c = 0; c < 4; c++) acc[a][b][c] = 0.f;

#pragma unroll
    for (int op = 0; op < 3; op++) {
        cpa16(sb + op*OPB + r0*ROWB + c0*16, ops[op] + (size_t)r0 * GK + c0*8);
        cpa16(sb + op*OPB + r1*ROWB + c1*16, ops[op] + (size_t)r1 * GK + c1*8);
    }
    cpa_commit();

    const int a_row = wm*32 + (l & 15);
    const int a_kc  = (l >> 4) * 8;
    const int b_row = wn*64 + (l & 7) + ((l >> 4) << 3);
    const int b_kc  = ((l >> 3) & 1) * 8;

    const int NSLAB = GK / KS;
    for (int s = 0; s < NSLAB; s++) {
        const int buf = s & 1;
        cpa_wait0();
        __syncthreads();
        if (s + 1 < NSLAB) {
            const int k0 = (s + 1) * KS;
            const uint32_t dst = sb + (buf ^ 1) * STB;
#pragma unroll
            for (int op = 0; op < 3; op++) {
                cpa16(dst + op*OPB + r0*ROWB + c0*16, ops[op] + (size_t)r0*GK + k0 + c0*8);
                cpa16(dst + op*OPB + r1*ROWB + c1*16, ops[op] + (size_t)r1*GK + k0 + c1*8);
            }
            cpa_commit();
        }
        const uint32_t base = sb + buf * STB;
#pragma unroll
        for (int ks = 0; ks < 2; ks++) {
            uint32_t ah[2][4], al[2][4];
#pragma unroll
            for (int mt = 0; mt < 2; mt++) {
                uint32_t aaddr = base + (a_row + mt*16) * ROWB + (ks*16 + a_kc) * 2;
                ldsm4(ah[mt], aaddr);
                ldsm4(al[mt], aaddr + OPB);
            }
#pragma unroll
            for (int np = 0; np < 4; np++) {
                uint32_t bh[4];
                uint32_t baddr = base + 2*OPB + (b_row + np*16) * ROWB + (ks*16 + b_kc) * 2;
                ldsm4(bh, baddr);
#pragma unroll
                for (int mt = 0; mt < 2; mt++) {
                    mma16816h(acc[mt][np*2+0], ah[mt], bh[0], bh[1]);
                    mma16816h(acc[mt][np*2+0], al[mt], bh[0], bh[1]);
                    mma16816h(acc[mt][np*2+1], ah[mt], bh[2], bh[3]);
                    mma16816h(acc[mt][np*2+1], al[mt], bh[2], bh[3]);
                }
            }
        }
        __syncthreads();
    }

#pragma unroll
    for (int mt = 0; mt < 2; mt++) {
        const int row = m0 + wm*32 + mt*16 + (l >> 2);
#pragma unroll
        for (int nt = 0; nt < 8; nt++) {
            const int col = n0 + wn*64 + nt*8 + (l & 3) * 2;
            float2 v0 = make_float2(acc[mt][nt][0], acc[mt][nt][1]);
            float2 v1 = make_float2(acc[mt][nt][2], acc[mt][nt][3]);
            *(float2*)&C[(size_t)row * GN + col]       = v0;
            *(float2*)&C[(size_t)(row + 8) * GN + col] = v1;
        }
    }
}

// ---------------- tensor-core flash attention (fp16 single-pass, causal) --------
#define KROWB 272
#define KOPB  (64*KROWB)
#define KSTB  (2*KOPB)
#define ASMEM (2*KSTB)

__device__ __forceinline__ void attn_load_kv(
    uint32_t dstbase,
    const __half* __restrict__ kh, const __half* __restrict__ vh,
    int kvbase, int tid)
{
#pragma unroll
    for (int i = 0; i < 8; i++) {
        const int op  = i >> 2;
        const int rem = (i & 3) * 256 + tid;
        const int row = rem >> 4;
        const int col = rem & 15;
        const __half* src = (op == 0) ? kh : vh;
        cpa16(dstbase + op*KOPB + row*KROWB + col*16,
              src + (size_t)(kvbase + row) * HD + col*8);
    }
    cpa_commit();
}

__global__ void __launch_bounds__(256, 1) attn_mma_kernel(
    const __half* __restrict__ Qh, const __half* __restrict__ Kh,
    const __half* __restrict__ Vh,
    __half* __restrict__ Ohi, __half* __restrict__ Olo)
{
    extern __shared__ char smraw[];
    const uint32_t sb = smem_u32(smraw);
    const int tid = threadIdx.x;
    const int w = tid >> 5, l = tid & 31;
    const int qb = gridDim.x - 1 - blockIdx.x;   // big tiles first
    const int h  = blockIdx.y;
    const int lq = l >> 2;
    const int lc = (l & 3) * 2;
    const float scale = 0.08838834764831845f;

    const int R = qb * 128 + w * 16;
    const size_t hoff = (size_t)h * DH;
    const __half* kh = Kh + hoff;
    const __half* vh = Vh + hoff;

    uint32_t qf[8][4];
    {
        const __half* qhp = Qh + hoff;
        const size_t ra = (size_t)(R + lq) * HD;
        const size_t rb = (size_t)(R + lq + 8) * HD;
#pragma unroll
        for (int kc = 0; kc < 8; kc++) {
            const int c = kc * 16 + lc;
            qf[kc][0] = *(const uint32_t*)&qhp[ra + c];
            qf[kc][1] = *(const uint32_t*)&qhp[rb + c];
            qf[kc][2] = *(const uint32_t*)&qhp[ra + c + 8];
            qf[kc][3] = *(const uint32_t*)&qhp[rb + c + 8];
        }
    }

    float O_[16][4];
#pragma unroll
    for (int nb = 0; nb < 16; nb++)
#pragma unroll
        for (int e = 0; e < 4; e++) O_[nb][e] = 0.f;
    float mrow0 = -INFINITY, mrow1 = -INFINITY;
    float lrow0 = 0.f, lrow1 = 0.f;

    const int nkv = 2 * qb + 2;
    attn_load_kv(sb, kh, vh, 0, tid);

    for (int jb = 0; jb < nkv; jb++) {
        const uint32_t base = sb + (jb & 1) * KSTB;
        cpa_wait0();
        __syncthreads();
        if (jb + 1 < nkv)
            attn_load_kv(sb + ((jb + 1) & 1) * KSTB, kh, vh, (jb + 1) * 64, tid);

        const int kvb = jb * 64;
        const bool active = (kvb <= R + 15);     // warp-uniform
        if (active) {
            // ---- S = Q K^T (16 x 64), single pass ----
            float S_[8][4];
#pragma unroll
            for (int nb = 0; nb < 8; nb++)
#pragma unroll
                for (int e = 0; e < 4; e++) S_[nb][e] = 0.f;

            const uint32_t krow = (l & 7) + ((l >> 4) << 3);
            const uint32_t kcol = ((l >> 3) & 1) * 8;
#pragma unroll
            for (int kc = 0; kc < 8; kc++) {
#pragma unroll
                for (int p = 0; p < 4; p++) {
                    uint32_t bh[4];
                    uint32_t addr = base + (p*16 + krow) * KROWB + (kc*16 + kcol) * 2;
                    ldsm4(bh, addr);
                    mma16816h(S_[p*2+0], qf[kc], bh[0], bh[1]);
                    mma16816h(S_[p*2+1], qf[kc], bh[2], bh[3]);
                }
            }

            // ---- online softmax ----
            const bool domask = (kvb + 63 > R);
            float mx0 = -INFINITY, mx1 = -INFINITY;
#pragma unroll
            for (int nb = 0; nb < 8; nb++) {
                const int colb = kvb + nb*8 + lc;
#pragma unroll
                for (int e = 0; e < 4; e++) {
                    float v = S_[nb][e] * scale;
                    if (domask) {
                        int row = R + lq + (e >> 1) * 8;
                        int col = colb + (e & 1);
                        if (col > row) v = -INFINITY;
                    }
                    S_[nb][e] = v;
                    if (e < 2) mx0 = fmaxf(mx0, v); else mx1 = fmaxf(mx1, v);
                }
            }
            mx0 = fmaxf(mx0, __shfl_xor_sync(0xffffffffu, mx0, 1));
            mx0 = fmaxf(mx0, __shfl_xor_sync(0xffffffffu, mx0, 2));
            mx1 = fmaxf(mx1, __shfl_xor_sync(0xffffffffu, mx1, 1));
            mx1 = fmaxf(mx1, __shfl_xor_sync(0xffffffffu, mx1, 2));
            const float mn0 = fmaxf(mrow0, mx0);
            const float mn1 = fmaxf(mrow1, mx1);
            const float cr0 = __expf(mrow0 - mn0);
            const float cr1 = __expf(mrow1 - mn1);
            mrow0 = mn0; mrow1 = mn1;
            float ls0 = 0.f, ls1 = 0.f;
#pragma unroll
            for (int nb = 0; nb < 8; nb++) {
                float p0 = __expf(S_[nb][0] - mn0);
                float p1 = __expf(S_[nb][1] - mn0);
                float p2 = __expf(S_[nb][2] - mn1);
                float p3 = __expf(S_[nb][3] - mn1);
                S_[nb][0] = p0; S_[nb][1] = p1; S_[nb][2] = p2; S_[nb][3] = p3;
                ls0 += p0 + p1; ls1 += p2 + p3;
            }
            ls0 += __shfl_xor_sync(0xffffffffu, ls0, 1);
            ls0 += __shfl_xor_sync(0xffffffffu, ls0, 2);
            ls1 += __shfl_xor_sync(0xffffffffu, ls1, 1);
            ls1 += __shfl_xor_sync(0xffffffffu, ls1, 2);
            lrow0 = lrow0 * cr0 + ls0;
            lrow1 = lrow1 * cr1 + ls1;

            // ---- pack P into A-fragments ----
            uint32_t aP[4][4];
#pragma unroll
            for (int kj = 0; kj < 4; kj++) {
#pragma unroll
                for (int half = 0; half < 2; half++) {
                    const int nb = kj*2 + half;
                    aP[kj][half*2+0] = packh(S_[nb][0], S_[nb][1]);
                    aP[kj][half*2+1] = packh(S_[nb][2], S_[nb][3]);
                }
            }

            // ---- rescale O ----
#pragma unroll
            for (int nb = 0; nb < 16; nb++) {
                O_[nb][0] *= cr0; O_[nb][1] *= cr0;
                O_[nb][2] *= cr1; O_[nb][3] *= cr1;
            }

            // ---- O += P V (single pass), V via ldmatrix.trans ----
            const uint32_t vrow = (l & 15);
            const uint32_t vcol = ((l >> 4) << 3);
#pragma unroll
            for (int kj = 0; kj < 4; kj++) {
#pragma unroll
                for (int p = 0; p < 8; p++) {
                    uint32_t vf[4];
                    uint32_t addr = base + KOPB + (kj*16 + vrow) * KROWB + (p*16 + vcol) * 2;
                    ldsm4t(vf, addr);
                    mma16816h(O_[p*2+0], aP[kj], vf[0], vf[1]);
                    mma16816h(O_[p*2+1], aP[kj], vf[2], vf[3]);
                }
            }
        }
        __syncthreads();
    }

    // ---- epilogue: normalize, split to fp16 hi/lo, store ----
    const float li0 = 1.f / lrow0;
    const float li1 = 1.f / lrow1;
    const size_t ra = (size_t)(R + lq) * HD + hoff;
    const size_t rb = (size_t)(R + lq + 8) * HD + hoff;
#pragma unroll
    for (int nb = 0; nb < 16; nb++) {
        const int c = nb*8 + lc;
        float a0 = O_[nb][0] * li0, a1 = O_[nb][1] * li0;
        float b0 = O_[nb][2] * li1, b1 = O_[nb][3] * li1;
        __half ha0 = __float2half_rn(a0), ha1 = __float2half_rn(a1);
        __half hb0 = __float2half_rn(b0), hb1 = __float2half_rn(b1);
        *(uint32_t*)&Ohi[ra + c] = packh(a0, a1);
        *(uint32_t*)&Ohi[rb + c] = packh(b0, b1);
        *(uint32_t*)&Olo[ra + c] = packh(a0 - __half2float(ha0), a1 - __half2float(ha1));
        *(uint32_t*)&Olo[rb + c] = packh(b0 - __half2float(hb0), b1 - __half2float(hb1));
    }
}

// ---------------- launch ---------------------------------------------------------
extern "C" void kernel_launch(void* const* d_in, const int* in_sizes, int n_in,
                              void* d_out, int out_size)
{
    const float* x  = (const float*)d_in[0];
    const float* wq = (const float*)d_in[2];
    const float* wk = (const float*)d_in[3];
    const float* wv = (const float*)d_in[4];
    const float* wo = (const float*)d_in[5];
    float* out = (float*)d_out;

    __half *xhi, *xlo, *wqh, *wkh, *wvh, *woh;
    __half *qh, *kh, *vh, *aohi, *aolo;
    cudaGetSymbolAddress((void**)&xhi,  g_xhi);  cudaGetSymbolAddress((void**)&xlo,  g_xlo);
    cudaGetSymbolAddress((void**)&wqh,  g_wqh);  cudaGetSymbolAddress((void**)&wkh,  g_wkh);
    cudaGetSymbolAddress((void**)&wvh,  g_wvh);  cudaGetSymbolAddress((void**)&woh,  g_woh);
    cudaGetSymbolAddress((void**)&qh,   g_qh);   cudaGetSymbolAddress((void**)&kh,   g_kh);
    cudaGetSymbolAddress((void**)&vh,   g_vh);
    cudaGetSymbolAddress((void**)&aohi, g_aohi); cudaGetSymbolAddress((void**)&aolo, g_aolo);

    cudaFuncSetAttribute(qkv_gemm_kernel,
                         cudaFuncAttributeMaxDynamicSharedMemorySize, GSM);
    cudaFuncSetAttribute(gemm_mma_kernel,
                         cudaFuncAttributeMaxDynamicSharedMemorySize, GSM);
    cudaFuncSetAttribute(attn_mma_kernel,
                         cudaFuncAttributeMaxDynamicSharedMemorySize, ASMEM);

    rope_table_kernel<<<(S_LEN*(DH/2) + 255)/256, 256>>>();

    const int n4x = S_LEN * D_IN / 4;
    const int n4w = HD * D_IN / 4;
    cvt_split_h_kernel<<<(n4x + 255)/256, 256>>>(x, xhi, xlo, n4x);
    cvt_h_kernel<<<(n4w + 255)/256, 256>>>(wq, wqh, n4w);
    cvt_h_kernel<<<(n4w + 255)/256, 256>>>(wk, wkh, n4w);
    cvt_h_kernel<<<(n4w + 255)/256, 256>>>(wv, wvh, n4w);
    cvt_h_kernel<<<(n4w + 255)/256, 256>>>(wo, woh, n4w);

    qkv_gemm_kernel<<<dim3(48, GM/128), 256, GSM>>>(
        xhi, xlo, wqh, wkh, wvh, qh, kh, vh);

    attn_mma_kernel<<<dim3(S_LEN/128, NH), 256, ASMEM>>>(
        qh, kh, vh, aohi, aolo);

    gemm_mma_kernel<<<dim3(GN/128, GM/128), 256, GSM>>>(aohi, aolo, woh, out);
}

// round 7
// speedup vs baseline: 6.3293x; 1.2128x over previous
#include <cuda_runtime.h>
#include <cuda_fp16.h>
#include <math.h>
#include <stdint.h>

#define S_LEN 4096
#define D_IN  2048
#define NH    16
#define DH    128
#define HD    2048
#define GM 4096
#define GN 2048
#define GK 2048

// ---------------- scratch (device globals: no allocation allowed) ----------
__device__ float g_inv[64];
__device__ float g_cos[(size_t)S_LEN * (DH/2)];
__device__ float g_sin[(size_t)S_LEN * (DH/2)];
__device__ __half g_xh  [(size_t)S_LEN * D_IN];
__device__ __half g_wqh [(size_t)HD * D_IN];
__device__ __half g_wkh [(size_t)HD * D_IN];
__device__ __half g_wvh [(size_t)HD * D_IN];
__device__ __half g_woh [(size_t)D_IN * HD];
__device__ __half g_qh  [(size_t)S_LEN * HD];
__device__ __half g_kh  [(size_t)S_LEN * HD];
__device__ __half g_vh  [(size_t)S_LEN * HD];
__device__ __half g_aohi[(size_t)S_LEN * HD];
__device__ __half g_aolo[(size_t)S_LEN * HD];

// ---------------- PTX helpers ------------------------------------------------
__device__ __forceinline__ uint32_t smem_u32(const void* p) {
    uint32_t a;
    asm("{ .reg .u64 t; cvta.to.shared.u64 t, %1; cvt.u32.u64 %0, t; }"
        : "=r"(a) : "l"(p));
    return a;
}
__device__ __forceinline__ void cpa16(uint32_t dst, const void* src) {
    asm volatile("cp.async.cg.shared.global [%0], [%1], 16;" :: "r"(dst), "l"(src));
}
__device__ __forceinline__ void cpa_commit() { asm volatile("cp.async.commit_group;"); }
__device__ __forceinline__ void cpa_wait0()  { asm volatile("cp.async.wait_group 0;"); }

__device__ __forceinline__ void ldsm4(uint32_t r[4], uint32_t addr) {
    asm volatile("ldmatrix.sync.aligned.m8n8.x4.shared.b16 {%0,%1,%2,%3}, [%4];"
        : "=r"(r[0]), "=r"(r[1]), "=r"(r[2]), "=r"(r[3]) : "r"(addr));
}
__device__ __forceinline__ void ldsm4t(uint32_t r[4], uint32_t addr) {
    asm volatile("ldmatrix.sync.aligned.m8n8.x4.trans.shared.b16 {%0,%1,%2,%3}, [%4];"
        : "=r"(r[0]), "=r"(r[1]), "=r"(r[2]), "=r"(r[3]) : "r"(addr));
}
__device__ __forceinline__ void mma16816h(float c[4], const uint32_t a[4],
                                          uint32_t b0, uint32_t b1) {
    asm volatile(
        "mma.sync.aligned.m16n8k16.row.col.f32.f16.f16.f32 "
        "{%0,%1,%2,%3}, {%4,%5,%6,%7}, {%8,%9}, {%0,%1,%2,%3};"
        : "+f"(c[0]), "+f"(c[1]), "+f"(c[2]), "+f"(c[3])
        : "r"(a[0]), "r"(a[1]), "r"(a[2]), "r"(a[3]), "r"(b0), "r"(b1));
}
__device__ __forceinline__ uint32_t packh(float a, float b) {
    __half2 t = __floats2half2_rn(a, b);
    return *(uint32_t*)&t;
}

// ---------------- fp32 -> fp16 conversions -------------------------------------
__global__ void cvt_h_kernel(const float* __restrict__ in,
                             __half* __restrict__ out, int n4) {
    int i = blockIdx.x * blockDim.x + threadIdx.x;
    if (i >= n4) return;
    float4 v = ((const float4*)in)[i];
    ((uint32_t*)out)[2*i]   = packh(v.x, v.y);
    ((uint32_t*)out)[2*i+1] = packh(v.z, v.w);
}

// ---------------- RoPE tables ---------------------------------------------------
__global__ void rope_inv_kernel() {
    int kp = threadIdx.x;   // 0..63
    if (kp < 64)
        g_inv[kp] = (float)pow(10000.0, -(double)(2*kp) / (double)DH);
}
__global__ void rope_table_kernel() {
    int idx = blockIdx.x * blockDim.x + threadIdx.x;
    if (idx >= S_LEN * (DH/2)) return;
    int row = idx >> 6;
    int kp  = idx & 63;
    float fr = (float)row * g_inv[kp];
    g_cos[idx] = cosf(fr);
    g_sin[idx] = sinf(fr);
}

// ---------------- shared GEMM tiling constants ----------------------------------
#define KS   32
#define ROWB 80
#define OPB  (128*ROWB)
// 2-operand (single-pass) variant for QKV
#define QSTB (2*OPB)
#define QGSM (2*QSTB)
// 3-operand (2-pass A) variant for WO
#define STB  (3*OPB)
#define GSM  (2*STB)

// ---------------- merged QKV GEMM: fp16 single-pass + fused RoPE ----------------
__global__ void __launch_bounds__(256, 1) qkv_gemm_kernel(
    const __half* __restrict__ Ah,
    const __half* __restrict__ Wq, const __half* __restrict__ Wk,
    const __half* __restrict__ Wv,
    __half* __restrict__ Qo, __half* __restrict__ Ko, __half* __restrict__ Vo)
{
    extern __shared__ char smraw[];
    const uint32_t sb = smem_u32(smraw);
    const int tid = threadIdx.x;
    const int w   = tid >> 5;
    const int l   = tid & 31;
    const int wm  = w & 3;
    const int wn  = w >> 2;
    const int m0  = blockIdx.y * 128;
    const int which = blockIdx.x >> 4;          // 0=q 1=k 2=v
    const int n0  = (blockIdx.x & 15) * 128;

    const __half* B = (which == 0) ? Wq : (which == 1) ? Wk : Wv;
    __half* Out     = (which == 0) ? Qo : (which == 1) ? Ko : Vo;

    const __half* ops[2] = { Ah + (size_t)m0 * GK, B + (size_t)n0 * GK };

    const int r0 = tid >> 2, c0 = tid & 3;
    const int r1 = (tid + 256) >> 2, c1 = tid & 3;

    float acc[2][8][4];
#pragma unroll
    for (int a = 0; a < 2; a++)
#pragma unroll
        for (int b = 0; b < 8; b++)
#pragma unroll
            for (int c = 0; c < 4; c++) acc[a][b][c] = 0.f;

#pragma unroll
    for (int op = 0; op < 2; op++) {
        cpa16(sb + op*OPB + r0*ROWB + c0*16, ops[op] + (size_t)r0 * GK + c0*8);
        cpa16(sb + op*OPB + r1*ROWB + c1*16, ops[op] + (size_t)r1 * GK + c1*8);
    }
    cpa_commit();

    const int a_row = wm*32 + (l & 15);
    const int a_kc  = (l >> 4) * 8;
    const int b_row = wn*64 + (l & 7) + ((l >> 4) << 3);
    const int b_kc  = ((l >> 3) & 1) * 8;

    const int NSLAB = GK / KS;
    for (int s = 0; s < NSLAB; s++) {
        const int buf = s & 1;
        cpa_wait0();
        __syncthreads();
        if (s + 1 < NSLAB) {
            const int k0 = (s + 1) * KS;
            const uint32_t dst = sb + (buf ^ 1) * QSTB;
#pragma unroll
            for (int op = 0; op < 2; op++) {
                cpa16(dst + op*OPB + r0*ROWB + c0*16, ops[op] + (size_t)r0*GK + k0 + c0*8);
                cpa16(dst + op*OPB + r1*ROWB + c1*16, ops[op] + (size_t)r1*GK + k0 + c1*8);
            }
            cpa_commit();
        }
        const uint32_t base = sb + buf * QSTB;
#pragma unroll
        for (int ks = 0; ks < 2; ks++) {
            uint32_t ah[2][4];
#pragma unroll
            for (int mt = 0; mt < 2; mt++) {
                uint32_t aaddr = base + (a_row + mt*16) * ROWB + (ks*16 + a_kc) * 2;
                ldsm4(ah[mt], aaddr);
            }
#pragma unroll
            for (int np = 0; np < 4; np++) {
                uint32_t bh[4];
                uint32_t baddr = base + OPB + (b_row + np*16) * ROWB + (ks*16 + b_kc) * 2;
                ldsm4(bh, baddr);
#pragma unroll
                for (int mt = 0; mt < 2; mt++) {
                    mma16816h(acc[mt][np*2+0], ah[mt], bh[0], bh[1]);
                    mma16816h(acc[mt][np*2+1], ah[mt], bh[2], bh[3]);
                }
            }
        }
        __syncthreads();
    }

    // ---- epilogue: optional RoPE, fp16 pack, store ----
#pragma unroll
    for (int mt = 0; mt < 2; mt++) {
        const int row = m0 + wm*32 + mt*16 + (l >> 2);
#pragma unroll
        for (int nt = 0; nt < 8; nt++) {
            const int gcol = n0 + wn*64 + nt*8 + (l & 3) * 2;   // even
            float a0 = acc[mt][nt][0], a1 = acc[mt][nt][1];
            float b0 = acc[mt][nt][2], b1 = acc[mt][nt][3];
            if (which < 2) {
                const int kp = (gcol & (DH - 1)) >> 1;
                float c0 = g_cos[(size_t)row * 64 + kp];
                float s0 = g_sin[(size_t)row * 64 + kp];
                float c1 = g_cos[(size_t)(row + 8) * 64 + kp];
                float s1 = g_sin[(size_t)(row + 8) * 64 + kp];
                float t0 = a0 * c0 - a1 * s0; a1 = a1 * c0 + a0 * s0; a0 = t0;
                float t1 = b0 * c1 - b1 * s1; b1 = b1 * c1 + b0 * s1; b0 = t1;
            }
            *(uint32_t*)&Out[(size_t)row * HD + gcol]       = packh(a0, a1);
            *(uint32_t*)&Out[(size_t)(row + 8) * HD + gcol] = packh(b0, b1);
        }
    }
}

// ---------------- output-projection GEMM (fp16 2-pass A, fp32 out) --------------
__global__ void __launch_bounds__(256, 1) gemm_mma_kernel(
    const __half* __restrict__ Ah, const __half* __restrict__ Al,
    const __half* __restrict__ Bh, float* __restrict__ C)
{
    extern __shared__ char smraw[];
    const uint32_t sb = smem_u32(smraw);
    const int tid = threadIdx.x;
    const int w   = tid >> 5;
    const int l   = tid & 31;
    const int wm  = w & 3;
    const int wn  = w >> 2;
    const int m0  = blockIdx.y * 128;
    const int n0  = blockIdx.x * 128;

    const __half* ops[3] = {
        Ah + (size_t)m0 * GK, Al + (size_t)m0 * GK, Bh + (size_t)n0 * GK };

    const int r0 = tid >> 2, c0 = tid & 3;
    const int r1 = (tid + 256) >> 2, c1 = tid & 3;

    float acc[2][8][4];
#pragma unroll
    for (int a = 0; a < 2; a++)
#pragma unroll
        for (int b = 0; b < 8; b++)
#pragma unroll
            for (int c = 0; c < 4; c++) acc[a][b][c] = 0.f;

#pragma unroll
    for (int op = 0; op < 3; op++) {
        cpa16(sb + op*OPB + r0*ROWB + c0*16, ops[op] + (size_t)r0 * GK + c0*8);
        cpa16(sb + op*OPB + r1*ROWB + c1*16, ops[op] + (size_t)r1 * GK + c1*8);
    }
    cpa_commit();

    const int a_row = wm*32 + (l & 15);
    const int a_kc  = (l >> 4) * 8;
    const int b_row = wn*64 + (l & 7) + ((l >> 4) << 3);
    const int b_kc  = ((l >> 3) & 1) * 8;

    const int NSLAB = GK / KS;
    for (int s = 0; s < NSLAB; s++) {
        const int buf = s & 1;
        cpa_wait0();
        __syncthreads();
        if (s + 1 < NSLAB) {
            const int k0 = (s + 1) * KS;
            const uint32_t dst = sb + (buf ^ 1) * STB;
#pragma unroll
            for (int op = 0; op < 3; op++) {
                cpa16(dst + op*OPB + r0*ROWB + c0*16, ops[op] + (size_t)r0*GK + k0 + c0*8);
                cpa16(dst + op*OPB + r1*ROWB + c1*16, ops[op] + (size_t)r1*GK + k0 + c1*8);
            }
            cpa_commit();
        }
        const uint32_t base = sb + buf * STB;
#pragma unroll
        for (int ks = 0; ks < 2; ks++) {
            uint32_t ah[2][4], al[2][4];
#pragma unroll
            for (int mt = 0; mt < 2; mt++) {
                uint32_t aaddr = base + (a_row + mt*16) * ROWB + (ks*16 + a_kc) * 2;
                ldsm4(ah[mt], aaddr);
                ldsm4(al[mt], aaddr + OPB);
            }
#pragma unroll
            for (int np = 0; np < 4; np++) {
                uint32_t bh[4];
                uint32_t baddr = base + 2*OPB + (b_row + np*16) * ROWB + (ks*16 + b_kc) * 2;
                ldsm4(bh, baddr);
#pragma unroll
                for (int mt = 0; mt < 2; mt++) {
                    mma16816h(acc[mt][np*2+0], ah[mt], bh[0], bh[1]);
                    mma16816h(acc[mt][np*2+0], al[mt], bh[0], bh[1]);
                    mma16816h(acc[mt][np*2+1], ah[mt], bh[2], bh[3]);
                    mma16816h(acc[mt][np*2+1], al[mt], bh[2], bh[3]);
                }
            }
        }
        __syncthreads();
    }

#pragma unroll
    for (int mt = 0; mt < 2; mt++) {
        const int row = m0 + wm*32 + mt*16 + (l >> 2);
#pragma unroll
        for (int nt = 0; nt < 8; nt++) {
            const int col = n0 + wn*64 + nt*8 + (l & 3) * 2;
            float2 v0 = make_float2(acc[mt][nt][0], acc[mt][nt][1]);
            float2 v1 = make_float2(acc[mt][nt][2], acc[mt][nt][3]);
            *(float2*)&C[(size_t)row * GN + col]       = v0;
            *(float2*)&C[(size_t)(row + 8) * GN + col] = v1;
        }
    }
}

// ---------------- tensor-core flash attention (fp16 single-pass, causal) --------
#define KROWB 272
#define KOPB  (64*KROWB)
#define KSTB  (2*KOPB)
#define ASMEM (2*KSTB)

__device__ __forceinline__ void attn_load_kv(
    uint32_t dstbase,
    const __half* __restrict__ kh, const __half* __restrict__ vh,
    int kvbase, int tid)
{
#pragma unroll
    for (int i = 0; i < 8; i++) {
        const int op  = i >> 2;
        const int rem = (i & 3) * 256 + tid;
        const int row = rem >> 4;
        const int col = rem & 15;
        const __half* src = (op == 0) ? kh : vh;
        cpa16(dstbase + op*KOPB + row*KROWB + col*16,
              src + (size_t)(kvbase + row) * HD + col*8);
    }
    cpa_commit();
}

__global__ void __launch_bounds__(256, 1) attn_mma_kernel(
    const __half* __restrict__ Qh, const __half* __restrict__ Kh,
    const __half* __restrict__ Vh,
    __half* __restrict__ Ohi, __half* __restrict__ Olo)
{
    extern __shared__ char smraw[];
    const uint32_t sb = smem_u32(smraw);
    const int tid = threadIdx.x;
    const int w = tid >> 5, l = tid & 31;
    const int qb = gridDim.x - 1 - blockIdx.x;   // big tiles first
    const int h  = blockIdx.y;
    const int lq = l >> 2;
    const int lc = (l & 3) * 2;
    const float scale = 0.08838834764831845f;

    const int R = qb * 128 + w * 16;
    const size_t hoff = (size_t)h * DH;
    const __half* kh = Kh + hoff;
    const __half* vh = Vh + hoff;

    uint32_t qf[8][4];
    {
        const __half* qhp = Qh + hoff;
        const size_t ra = (size_t)(R + lq) * HD;
        const size_t rb = (size_t)(R + lq + 8) * HD;
#pragma unroll
        for (int kc = 0; kc < 8; kc++) {
            const int c = kc * 16 + lc;
            qf[kc][0] = *(const uint32_t*)&qhp[ra + c];
            qf[kc][1] = *(const uint32_t*)&qhp[rb + c];
            qf[kc][2] = *(const uint32_t*)&qhp[ra + c + 8];
            qf[kc][3] = *(const uint32_t*)&qhp[rb + c + 8];
        }
    }

    float O_[16][4];
#pragma unroll
    for (int nb = 0; nb < 16; nb++)
#pragma unroll
        for (int e = 0; e < 4; e++) O_[nb][e] = 0.f;
    float mrow0 = -INFINITY, mrow1 = -INFINITY;
    float lrow0 = 0.f, lrow1 = 0.f;

    const int nkv = 2 * qb + 2;
    attn_load_kv(sb, kh, vh, 0, tid);

    for (int jb = 0; jb < nkv; jb++) {
        const uint32_t base = sb + (jb & 1) * KSTB;
        cpa_wait0();
        __syncthreads();
        if (jb + 1 < nkv)
            attn_load_kv(sb + ((jb + 1) & 1) * KSTB, kh, vh, (jb + 1) * 64, tid);

        const int kvb = jb * 64;
        const bool active = (kvb <= R + 15);     // warp-uniform
        if (active) {
            float S_[8][4];
#pragma unroll
            for (int nb = 0; nb < 8; nb++)
#pragma unroll
                for (int e = 0; e < 4; e++) S_[nb][e] = 0.f;

            const uint32_t krow = (l & 7) + ((l >> 4) << 3);
            const uint32_t kcol = ((l >> 3) & 1) * 8;
#pragma unroll
            for (int kc = 0; kc < 8; kc++) {
#pragma unroll
                for (int p = 0; p < 4; p++) {
                    uint32_t bh[4];
                    uint32_t addr = base + (p*16 + krow) * KROWB + (kc*16 + kcol) * 2;
                    ldsm4(bh, addr);
                    mma16816h(S_[p*2+0], qf[kc], bh[0], bh[1]);
                    mma16816h(S_[p*2+1], qf[kc], bh[2], bh[3]);
                }
            }

            const bool domask = (kvb + 63 > R);
            float mx0 = -INFINITY, mx1 = -INFINITY;
#pragma unroll
            for (int nb = 0; nb < 8; nb++) {
                const int colb = kvb + nb*8 + lc;
#pragma unroll
                for (int e = 0; e < 4; e++) {
                    float v = S_[nb][e] * scale;
                    if (domask) {
                        int row = R + lq + (e >> 1) * 8;
                        int col = colb + (e & 1);
                        if (col > row) v = -INFINITY;
                    }
                    S_[nb][e] = v;
                    if (e < 2) mx0 = fmaxf(mx0, v); else mx1 = fmaxf(mx1, v);
                }
            }
            mx0 = fmaxf(mx0, __shfl_xor_sync(0xffffffffu, mx0, 1));
            mx0 = fmaxf(mx0, __shfl_xor_sync(0xffffffffu, mx0, 2));
            mx1 = fmaxf(mx1, __shfl_xor_sync(0xffffffffu, mx1, 1));
            mx1 = fmaxf(mx1, __shfl_xor_sync(0xffffffffu, mx1, 2));
            const float mn0 = fmaxf(mrow0, mx0);
            const float mn1 = fmaxf(mrow1, mx1);
            const float cr0 = __expf(mrow0 - mn0);
            const float cr1 = __expf(mrow1 - mn1);
            mrow0 = mn0; mrow1 = mn1;
            float ls0 = 0.f, ls1 = 0.f;
#pragma unroll
            for (int nb = 0; nb < 8; nb++) {
                float p0 = __expf(S_[nb][0] - mn0);
                float p1 = __expf(S_[nb][1] - mn0);
                float p2 = __expf(S_[nb][2] - mn1);
                float p3 = __expf(S_[nb][3] - mn1);
                S_[nb][0] = p0; S_[nb][1] = p1; S_[nb][2] = p2; S_[nb][3] = p3;
                ls0 += p0 + p1; ls1 += p2 + p3;
            }
            ls0 += __shfl_xor_sync(0xffffffffu, ls0, 1);
            ls0 += __shfl_xor_sync(0xffffffffu, ls0, 2);
            ls1 += __shfl_xor_sync(0xffffffffu, ls1, 1);
            ls1 += __shfl_xor_sync(0xffffffffu, ls1, 2);
            lrow0 = lrow0 * cr0 + ls0;
            lrow1 = lrow1 * cr1 + ls1;

            uint32_t aP[4][4];
#pragma unroll
            for (int kj = 0; kj < 4; kj++) {
#pragma unroll
                for (int half = 0; half < 2; half++) {
                    const int nb = kj*2 + half;
                    aP[kj][half*2+0] = packh(S_[nb][0], S_[nb][1]);
                    aP[kj][half*2+1] = packh(S_[nb][2], S_[nb][3]);
                }
            }

#pragma unroll
            for (int nb = 0; nb < 16; nb++) {
                O_[nb][0] *= cr0; O_[nb][1] *= cr0;
                O_[nb][2] *= cr1; O_[nb][3] *= cr1;
            }

            const uint32_t vrow = (l & 15);
            const uint32_t vcol = ((l >> 4) << 3);
#pragma unroll
            for (int kj = 0; kj < 4; kj++) {
#pragma unroll
                for (int p = 0; p < 8; p++) {
                    uint32_t vf[4];
                    uint32_t addr = base + KOPB + (kj*16 + vrow) * KROWB + (p*16 + vcol) * 2;
                    ldsm4t(vf, addr);
                    mma16816h(O_[p*2+0], aP[kj], vf[0], vf[1]);
                    mma16816h(O_[p*2+1], aP[kj], vf[2], vf[3]);
                }
            }
        }
        __syncthreads();
    }

    const float li0 = 1.f / lrow0;
    const float li1 = 1.f / lrow1;
    const size_t ra = (size_t)(R + lq) * HD + hoff;
    const size_t rb = (size_t)(R + lq + 8) * HD + hoff;
#pragma unroll
    for (int nb = 0; nb < 16; nb++) {
        const int c = nb*8 + lc;
        float a0 = O_[nb][0] * li0, a1 = O_[nb][1] * li0;
        float b0 = O_[nb][2] * li1, b1 = O_[nb][3] * li1;
        __half ha0 = __float2half_rn(a0), ha1 = __float2half_rn(a1);
        __half hb0 = __float2half_rn(b0), hb1 = __float2half_rn(b1);
        *(uint32_t*)&Ohi[ra + c] = packh(a0, a1);
        *(uint32_t*)&Ohi[rb + c] = packh(b0, b1);
        *(uint32_t*)&Olo[ra + c] = packh(a0 - __half2float(ha0), a1 - __half2float(ha1));
        *(uint32_t*)&Olo[rb + c] = packh(b0 - __half2float(hb0), b1 - __half2float(hb1));
    }
}

// ---------------- launch ---------------------------------------------------------
extern "C" void kernel_launch(void* const* d_in, const int* in_sizes, int n_in,
                              void* d_out, int out_size)
{
    const float* x  = (const float*)d_in[0];
    const float* wq = (const float*)d_in[2];
    const float* wk = (const float*)d_in[3];
    const float* wv = (const float*)d_in[4];
    const float* wo = (const float*)d_in[5];
    float* out = (float*)d_out;

    __half *xh, *wqh, *wkh, *wvh, *woh;
    __half *qh, *kh, *vh, *aohi, *aolo;
    cudaGetSymbolAddress((void**)&xh,   g_xh);
    cudaGetSymbolAddress((void**)&wqh,  g_wqh);  cudaGetSymbolAddress((void**)&wkh,  g_wkh);
    cudaGetSymbolAddress((void**)&wvh,  g_wvh);  cudaGetSymbolAddress((void**)&woh,  g_woh);
    cudaGetSymbolAddress((void**)&qh,   g_qh);   cudaGetSymbolAddress((void**)&kh,   g_kh);
    cudaGetSymbolAddress((void**)&vh,   g_vh);
    cudaGetSymbolAddress((void**)&aohi, g_aohi); cudaGetSymbolAddress((void**)&aolo, g_aolo);

    cudaFuncSetAttribute(qkv_gemm_kernel,
                         cudaFuncAttributeMaxDynamicSharedMemorySize, QGSM);
    cudaFuncSetAttribute(gemm_mma_kernel,
                         cudaFuncAttributeMaxDynamicSharedMemorySize, GSM);
    cudaFuncSetAttribute(attn_mma_kernel,
                         cudaFuncAttributeMaxDynamicSharedMemorySize, ASMEM);

    rope_inv_kernel<<<1, 64>>>();
    rope_table_kernel<<<(S_LEN*(DH/2) + 255)/256, 256>>>();

    const int n4x = S_LEN * D_IN / 4;
    const int n4w = HD * D_IN / 4;
    cvt_h_kernel<<<(n4x + 255)/256, 256>>>(x,  xh,  n4x);
    cvt_h_kernel<<<(n4w + 255)/256, 256>>>(wq, wqh, n4w);
    cvt_h_kernel<<<(n4w + 255)/256, 256>>>(wk, wkh, n4w);
    cvt_h_kernel<<<(n4w + 255)/256, 256>>>(wv, wvh, n4w);
    cvt_h_kernel<<<(n4w + 255)/256, 256>>>(wo, woh, n4w);

    qkv_gemm_kernel<<<dim3(48, GM/128), 256, QGSM>>>(
        xh, wqh, wkh, wvh, qh, kh, vh);

    attn_mma_kernel<<<dim3(S_LEN/128, NH), 256, ASMEM>>>(
        qh, kh, vh, aohi, aolo);

    gemm_mma_kernel<<<dim3(GN/128, GM/128), 256, GSM>>>(aohi, aolo, woh, out);
}

// round 8
// speedup vs baseline: 6.8262x; 1.0785x over previous
#include <cuda_runtime.h>
#include <cuda_fp16.h>
#include <math.h>
#include <stdint.h>

#define S_LEN 4096
#define D_IN  2048
#define NH    16
#define DH    128
#define HD    2048
#define GM 4096
#define GN 2048
#define GK 2048

// ---------------- scratch (device globals: no allocation allowed) ----------
__device__ float g_inv[64];
__device__ float g_cos[(size_t)S_LEN * (DH/2)];
__device__ float g_sin[(size_t)S_LEN * (DH/2)];
__device__ __half g_xh  [(size_t)S_LEN * D_IN];
__device__ __half g_wqh [(size_t)HD * D_IN];
__device__ __half g_wkh [(size_t)HD * D_IN];
__device__ __half g_wvh [(size_t)HD * D_IN];
__device__ __half g_woh [(size_t)D_IN * HD];
__device__ __half g_qh  [(size_t)S_LEN * HD];
__device__ __half g_kh  [(size_t)S_LEN * HD];
__device__ __half g_vh  [(size_t)S_LEN * HD];
__device__ __half g_aoh [(size_t)S_LEN * HD];

// ---------------- PTX helpers ------------------------------------------------
__device__ __forceinline__ uint32_t smem_u32(const void* p) {
    uint32_t a;
    asm("{ .reg .u64 t; cvta.to.shared.u64 t, %1; cvt.u32.u64 %0, t; }"
        : "=r"(a) : "l"(p));
    return a;
}
__device__ __forceinline__ void cpa16(uint32_t dst, const void* src) {
    asm volatile("cp.async.cg.shared.global [%0], [%1], 16;" :: "r"(dst), "l"(src));
}
__device__ __forceinline__ void cpa_commit() { asm volatile("cp.async.commit_group;"); }
__device__ __forceinline__ void cpa_wait0()  { asm volatile("cp.async.wait_group 0;"); }

__device__ __forceinline__ void ldsm4(uint32_t r[4], uint32_t addr) {
    asm volatile("ldmatrix.sync.aligned.m8n8.x4.shared.b16 {%0,%1,%2,%3}, [%4];"
        : "=r"(r[0]), "=r"(r[1]), "=r"(r[2]), "=r"(r[3]) : "r"(addr));
}
__device__ __forceinline__ void ldsm4t(uint32_t r[4], uint32_t addr) {
    asm volatile("ldmatrix.sync.aligned.m8n8.x4.trans.shared.b16 {%0,%1,%2,%3}, [%4];"
        : "=r"(r[0]), "=r"(r[1]), "=r"(r[2]), "=r"(r[3]) : "r"(addr));
}
__device__ __forceinline__ void mma16816h(float c[4], const uint32_t a[4],
                                          uint32_t b0, uint32_t b1) {
    asm volatile(
        "mma.sync.aligned.m16n8k16.row.col.f32.f16.f16.f32 "
        "{%0,%1,%2,%3}, {%4,%5,%6,%7}, {%8,%9}, {%0,%1,%2,%3};"
        : "+f"(c[0]), "+f"(c[1]), "+f"(c[2]), "+f"(c[3])
        : "r"(a[0]), "r"(a[1]), "r"(a[2]), "r"(a[3]), "r"(b0), "r"(b1));
}
__device__ __forceinline__ uint32_t packh(float a, float b) {
    __half2 t = __floats2half2_rn(a, b);
    return *(uint32_t*)&t;
}

// ---------------- fused fp32 -> fp16 conversion (all 5 tensors) ----------------
// segments (in 2^20-quad units): [0,2)=x, [2,3)=wq, [3,4)=wk, [4,5)=wv, [5,6)=wo
#define N4W (HD * D_IN / 4)          // 1048576 = 2^20
#define N4TOT (6 * N4W)

__global__ void cvt_all_kernel(const float* __restrict__ x,
                               const float* __restrict__ wq,
                               const float* __restrict__ wk,
                               const float* __restrict__ wv,
                               const float* __restrict__ wo,
                               __half* __restrict__ xh,
                               __half* __restrict__ wqh,
                               __half* __restrict__ wkh,
                               __half* __restrict__ wvh,
                               __half* __restrict__ woh) {
    int i = blockIdx.x * blockDim.x + threadIdx.x;
    if (i >= N4TOT) return;
    int seg = i >> 20;
    const float* in;
    __half* out;
    int off;
    if (seg < 2)      { in = x;  out = xh;  off = i; }
    else if (seg == 2){ in = wq; out = wqh; off = i - 2*N4W; }
    else if (seg == 3){ in = wk; out = wkh; off = i - 3*N4W; }
    else if (seg == 4){ in = wv; out = wvh; off = i - 4*N4W; }
    else              { in = wo; out = woh; off = i - 5*N4W; }
    float4 v = ((const float4*)in)[off];
    ((uint32_t*)out)[2*off]   = packh(v.x, v.y);
    ((uint32_t*)out)[2*off+1] = packh(v.z, v.w);
}

// ---------------- RoPE tables ---------------------------------------------------
__global__ void rope_inv_kernel() {
    int kp = threadIdx.x;   // 0..63
    if (kp < 64)
        g_inv[kp] = (float)pow(10000.0, -(double)(2*kp) / (double)DH);
}
__global__ void rope_table_kernel() {
    int idx = blockIdx.x * blockDim.x + threadIdx.x;
    if (idx >= S_LEN * (DH/2)) return;
    int row = idx >> 6;
    int kp  = idx & 63;
    float fr = (float)row * g_inv[kp];
    g_cos[idx] = cosf(fr);
    g_sin[idx] = sinf(fr);
}

// ---------------- shared GEMM tiling constants ----------------------------------
#define KS   32
#define ROWB 80
#define OPB  (128*ROWB)
#define QSTB (2*OPB)
#define QGSM (2*QSTB)

// ---------------- merged QKV GEMM: fp16 single-pass + fused RoPE ----------------
__global__ void __launch_bounds__(256, 1) qkv_gemm_kernel(
    const __half* __restrict__ Ah,
    const __half* __restrict__ Wq, const __half* __restrict__ Wk,
    const __half* __restrict__ Wv,
    __half* __restrict__ Qo, __half* __restrict__ Ko, __half* __restrict__ Vo)
{
    extern __shared__ char smraw[];
    const uint32_t sb = smem_u32(smraw);
    const int tid = threadIdx.x;
    const int w   = tid >> 5;
    const int l   = tid & 31;
    const int wm  = w & 3;
    const int wn  = w >> 2;
    const int m0  = blockIdx.y * 128;
    const int which = blockIdx.x >> 4;          // 0=q 1=k 2=v
    const int n0  = (blockIdx.x & 15) * 128;

    const __half* B = (which == 0) ? Wq : (which == 1) ? Wk : Wv;
    __half* Out     = (which == 0) ? Qo : (which == 1) ? Ko : Vo;

    const __half* ops[2] = { Ah + (size_t)m0 * GK, B + (size_t)n0 * GK };

    const int r0 = tid >> 2, c0 = tid & 3;
    const int r1 = (tid + 256) >> 2, c1 = tid & 3;

    float acc[2][8][4];
#pragma unroll
    for (int a = 0; a < 2; a++)
#pragma unroll
        for (int b = 0; b < 8; b++)
#pragma unroll
            for (int c = 0; c < 4; c++) acc[a][b][c] = 0.f;

#pragma unroll
    for (int op = 0; op < 2; op++) {
        cpa16(sb + op*OPB + r0*ROWB + c0*16, ops[op] + (size_t)r0 * GK + c0*8);
        cpa16(sb + op*OPB + r1*ROWB + c1*16, ops[op] + (size_t)r1 * GK + c1*8);
    }
    cpa_commit();

    const int a_row = wm*32 + (l & 15);
    const int a_kc  = (l >> 4) * 8;
    const int b_row = wn*64 + (l & 7) + ((l >> 4) << 3);
    const int b_kc  = ((l >> 3) & 1) * 8;

    const int NSLAB = GK / KS;
    for (int s = 0; s < NSLAB; s++) {
        const int buf = s & 1;
        cpa_wait0();
        __syncthreads();
        if (s + 1 < NSLAB) {
            const int k0 = (s + 1) * KS;
            const uint32_t dst = sb + (buf ^ 1) * QSTB;
#pragma unroll
            for (int op = 0; op < 2; op++) {
                cpa16(dst + op*OPB + r0*ROWB + c0*16, ops[op] + (size_t)r0*GK + k0 + c0*8);
                cpa16(dst + op*OPB + r1*ROWB + c1*16, ops[op] + (size_t)r1*GK + k0 + c1*8);
            }
            cpa_commit();
        }
        const uint32_t base = sb + buf * QSTB;
#pragma unroll
        for (int ks = 0; ks < 2; ks++) {
            uint32_t ah[2][4];
#pragma unroll
            for (int mt = 0; mt < 2; mt++) {
                uint32_t aaddr = base + (a_row + mt*16) * ROWB + (ks*16 + a_kc) * 2;
                ldsm4(ah[mt], aaddr);
            }
#pragma unroll
            for (int np = 0; np < 4; np++) {
                uint32_t bh[4];
                uint32_t baddr = base + OPB + (b_row + np*16) * ROWB + (ks*16 + b_kc) * 2;
                ldsm4(bh, baddr);
#pragma unroll
                for (int mt = 0; mt < 2; mt++) {
                    mma16816h(acc[mt][np*2+0], ah[mt], bh[0], bh[1]);
                    mma16816h(acc[mt][np*2+1], ah[mt], bh[2], bh[3]);
                }
            }
        }
        __syncthreads();
    }

    // ---- epilogue: optional RoPE, fp16 pack, store ----
#pragma unroll
    for (int mt = 0; mt < 2; mt++) {
        const int row = m0 + wm*32 + mt*16 + (l >> 2);
#pragma unroll
        for (int nt = 0; nt < 8; nt++) {
            const int gcol = n0 + wn*64 + nt*8 + (l & 3) * 2;   // even
            float a0 = acc[mt][nt][0], a1 = acc[mt][nt][1];
            float b0 = acc[mt][nt][2], b1 = acc[mt][nt][3];
            if (which < 2) {
                const int kp = (gcol & (DH - 1)) >> 1;
                float c0 = g_cos[(size_t)row * 64 + kp];
                float s0 = g_sin[(size_t)row * 64 + kp];
                float c1 = g_cos[(size_t)(row + 8) * 64 + kp];
                float s1 = g_sin[(size_t)(row + 8) * 64 + kp];
                float t0 = a0 * c0 - a1 * s0; a1 = a1 * c0 + a0 * s0; a0 = t0;
                float t1 = b0 * c1 - b1 * s1; b1 = b1 * c1 + b0 * s1; b0 = t1;
            }
            *(uint32_t*)&Out[(size_t)row * HD + gcol]       = packh(a0, a1);
            *(uint32_t*)&Out[(size_t)(row + 8) * HD + gcol] = packh(b0, b1);
        }
    }
}

// ---------------- output-projection GEMM (fp16 single-pass, fp32 out) ----------
__global__ void __launch_bounds__(256, 1) gemm_mma_kernel(
    const __half* __restrict__ Ah, const __half* __restrict__ Bh,
    float* __restrict__ C)
{
    extern __shared__ char smraw[];
    const uint32_t sb = smem_u32(smraw);
    const int tid = threadIdx.x;
    const int w   = tid >> 5;
    const int l   = tid & 31;
    const int wm  = w & 3;
    const int wn  = w >> 2;
    const int m0  = blockIdx.y * 128;
    const int n0  = blockIdx.x * 128;

    const __half* ops[2] = { Ah + (size_t)m0 * GK, Bh + (size_t)n0 * GK };

    const int r0 = tid >> 2, c0 = tid & 3;
    const int r1 = (tid + 256) >> 2, c1 = tid & 3;

    float acc[2][8][4];
#pragma unroll
    for (int a = 0; a < 2; a++)
#pragma unroll
        for (int b = 0; b < 8; b++)
#pragma unroll
            for (int c = 0; c < 4; c++) acc[a][b][c] = 0.f;

#pragma unroll
    for (int op = 0; op < 2; op++) {
        cpa16(sb + op*OPB + r0*ROWB + c0*16, ops[op] + (size_t)r0 * GK + c0*8);
        cpa16(sb + op*OPB + r1*ROWB + c1*16, ops[op] + (size_t)r1 * GK + c1*8);
    }
    cpa_commit();

    const int a_row = wm*32 + (l & 15);
    const int a_kc  = (l >> 4) * 8;
    const int b_row = wn*64 + (l & 7) + ((l >> 4) << 3);
    const int b_kc  = ((l >> 3) & 1) * 8;

    const int NSLAB = GK / KS;
    for (int s = 0; s < NSLAB; s++) {
        const int buf = s & 1;
        cpa_wait0();
        __syncthreads();
        if (s + 1 < NSLAB) {
            const int k0 = (s + 1) * KS;
            const uint32_t dst = sb + (buf ^ 1) * QSTB;
#pragma unroll
            for (int op = 0; op < 2; op++) {
                cpa16(dst + op*OPB + r0*ROWB + c0*16, ops[op] + (size_t)r0*GK + k0 + c0*8);
                cpa16(dst + op*OPB + r1*ROWB + c1*16, ops[op] + (size_t)r1*GK + k0 + c1*8);
            }
            cpa_commit();
        }
        const uint32_t base = sb + buf * QSTB;
#pragma unroll
        for (int ks = 0; ks < 2; ks++) {
            uint32_t ah[2][4];
#pragma unroll
            for (int mt = 0; mt < 2; mt++) {
                uint32_t aaddr = base + (a_row + mt*16) * ROWB + (ks*16 + a_kc) * 2;
                ldsm4(ah[mt], aaddr);
            }
#pragma unroll
            for (int np = 0; np < 4; np++) {
                uint32_t bh[4];
                uint32_t baddr = base + OPB + (b_row + np*16) * ROWB + (ks*16 + b_kc) * 2;
                ldsm4(bh, baddr);
#pragma unroll
                for (int mt = 0; mt < 2; mt++) {
                    mma16816h(acc[mt][np*2+0], ah[mt], bh[0], bh[1]);
                    mma16816h(acc[mt][np*2+1], ah[mt], bh[2], bh[3]);
                }
            }
        }
        __syncthreads();
    }

#pragma unroll
    for (int mt = 0; mt < 2; mt++) {
        const int row = m0 + wm*32 + mt*16 + (l >> 2);
#pragma unroll
        for (int nt = 0; nt < 8; nt++) {
            const int col = n0 + wn*64 + nt*8 + (l & 3) * 2;
            float2 v0 = make_float2(acc[mt][nt][0], acc[mt][nt][1]);
            float2 v1 = make_float2(acc[mt][nt][2], acc[mt][nt][3]);
            *(float2*)&C[(size_t)row * GN + col]       = v0;
            *(float2*)&C[(size_t)(row + 8) * GN + col] = v1;
        }
    }
}

// ---------------- tensor-core flash attention (fp16 single-pass, causal) --------
#define KROWB 272
#define KOPB  (64*KROWB)
#define KSTB  (2*KOPB)
#define ASMEM (2*KSTB)

__device__ __forceinline__ void attn_load_kv(
    uint32_t dstbase,
    const __half* __restrict__ kh, const __half* __restrict__ vh,
    int kvbase, int tid)
{
#pragma unroll
    for (int i = 0; i < 8; i++) {
        const int op  = i >> 2;
        const int rem = (i & 3) * 256 + tid;
        const int row = rem >> 4;
        const int col = rem & 15;
        const __half* src = (op == 0) ? kh : vh;
        cpa16(dstbase + op*KOPB + row*KROWB + col*16,
              src + (size_t)(kvbase + row) * HD + col*8);
    }
    cpa_commit();
}

__global__ void __launch_bounds__(256, 1) attn_mma_kernel(
    const __half* __restrict__ Qh, const __half* __restrict__ Kh,
    const __half* __restrict__ Vh, __half* __restrict__ Oh)
{
    extern __shared__ char smraw[];
    const uint32_t sb = smem_u32(smraw);
    const int tid = threadIdx.x;
    const int w = tid >> 5, l = tid & 31;
    const int qb = gridDim.x - 1 - blockIdx.x;   // big tiles first
    const int h  = blockIdx.y;
    const int lq = l >> 2;
    const int lc = (l & 3) * 2;
    const float scale = 0.08838834764831845f;

    const int R = qb * 128 + w * 16;
    const size_t hoff = (size_t)h * DH;
    const __half* kh = Kh + hoff;
    const __half* vh = Vh + hoff;

    uint32_t qf[8][4];
    {
        const __half* qhp = Qh + hoff;
        const size_t ra = (size_t)(R + lq) * HD;
        const size_t rb = (size_t)(R + lq + 8) * HD;
#pragma unroll
        for (int kc = 0; kc < 8; kc++) {
            const int c = kc * 16 + lc;
            qf[kc][0] = *(const uint32_t*)&qhp[ra + c];
            qf[kc][1] = *(const uint32_t*)&qhp[rb + c];
            qf[kc][2] = *(const uint32_t*)&qhp[ra + c + 8];
            qf[kc][3] = *(const uint32_t*)&qhp[rb + c + 8];
        }
    }

    float O_[16][4];
#pragma unroll
    for (int nb = 0; nb < 16; nb++)
#pragma unroll
        for (int e = 0; e < 4; e++) O_[nb][e] = 0.f;
    float mrow0 = -INFINITY, mrow1 = -INFINITY;
    float lrow0 = 0.f, lrow1 = 0.f;

    const int nkv = 2 * qb + 2;
    attn_load_kv(sb, kh, vh, 0, tid);

    for (int jb = 0; jb < nkv; jb++) {
        const uint32_t base = sb + (jb & 1) * KSTB;
        cpa_wait0();
        __syncthreads();
        if (jb + 1 < nkv)
            attn_load_kv(sb + ((jb + 1) & 1) * KSTB, kh, vh, (jb + 1) * 64, tid);

        const int kvb = jb * 64;
        const bool active = (kvb <= R + 15);     // warp-uniform
        if (active) {
            float S_[8][4];
#pragma unroll
            for (int nb = 0; nb < 8; nb++)
#pragma unroll
                for (int e = 0; e < 4; e++) S_[nb][e] = 0.f;

            const uint32_t krow = (l & 7) + ((l >> 4) << 3);
            const uint32_t kcol = ((l >> 3) & 1) * 8;
#pragma unroll
            for (int kc = 0; kc < 8; kc++) {
#pragma unroll
                for (int p = 0; p < 4; p++) {
                    uint32_t bh[4];
                    uint32_t addr = base + (p*16 + krow) * KROWB + (kc*16 + kcol) * 2;
                    ldsm4(bh, addr);
                    mma16816h(S_[p*2+0], qf[kc], bh[0], bh[1]);
                    mma16816h(S_[p*2+1], qf[kc], bh[2], bh[3]);
                }
            }

            const bool domask = (kvb + 63 > R);
            float mx0 = -INFINITY, mx1 = -INFINITY;
#pragma unroll
            for (int nb = 0; nb < 8; nb++) {
                const int colb = kvb + nb*8 + lc;
#pragma unroll
                for (int e = 0; e < 4; e++) {
                    float v = S_[nb][e] * scale;
                    if (domask) {
                        int row = R + lq + (e >> 1) * 8;
                        int col = colb + (e & 1);
                        if (col > row) v = -INFINITY;
                    }
                    S_[nb][e] = v;
                    if (e < 2) mx0 = fmaxf(mx0, v); else mx1 = fmaxf(mx1, v);
                }
            }
            mx0 = fmaxf(mx0, __shfl_xor_sync(0xffffffffu, mx0, 1));
            mx0 = fmaxf(mx0, __shfl_xor_sync(0xffffffffu, mx0, 2));
            mx1 = fmaxf(mx1, __shfl_xor_sync(0xffffffffu, mx1, 1));
            mx1 = fmaxf(mx1, __shfl_xor_sync(0xffffffffu, mx1, 2));
            const float mn0 = fmaxf(mrow0, mx0);
            const float mn1 = fmaxf(mrow1, mx1);
            const float cr0 = __expf(mrow0 - mn0);
            const float cr1 = __expf(mrow1 - mn1);
            mrow0 = mn0; mrow1 = mn1;
            float ls0 = 0.f, ls1 = 0.f;
#pragma unroll
            for (int nb = 0; nb < 8; nb++) {
                float p0 = __expf(S_[nb][0] - mn0);
                float p1 = __expf(S_[nb][1] - mn0);
                float p2 = __expf(S_[nb][2] - mn1);
                float p3 = __expf(S_[nb][3] - mn1);
                S_[nb][0] = p0; S_[nb][1] = p1; S_[nb][2] = p2; S_[nb][3] = p3;
                ls0 += p0 + p1; ls1 += p2 + p3;
            }
            ls0 += __shfl_xor_sync(0xffffffffu, ls0, 1);
            ls0 += __shfl_xor_sync(0xffffffffu, ls0, 2);
            ls1 += __shfl_xor_sync(0xffffffffu, ls1, 1);
            ls1 += __shfl_xor_sync(0xffffffffu, ls1, 2);
            lrow0 = lrow0 * cr0 + ls0;
            lrow1 = lrow1 * cr1 + ls1;

            uint32_t aP[4][4];
#pragma unroll
            for (int kj = 0; kj < 4; kj++) {
#pragma unroll
                for (int half = 0; half < 2; half++) {
                    const int nb = kj*2 + half;
                    aP[kj][half*2+0] = packh(S_[nb][0], S_[nb][1]);
                    aP[kj][half*2+1] = packh(S_[nb][2], S_[nb][3]);
                }
            }

#pragma unroll
            for (int nb = 0; nb < 16; nb++) {
                O_[nb][0] *= cr0; O_[nb][1] *= cr0;
                O_[nb][2] *= cr1; O_[nb][3] *= cr1;
            }

            const uint32_t vrow = (l & 15);
            const uint32_t vcol = ((l >> 4) << 3);
#pragma unroll
            for (int kj = 0; kj < 4; kj++) {
#pragma unroll
                for (int p = 0; p < 8; p++) {
                    uint32_t vf[4];
                    uint32_t addr = base + KOPB + (kj*16 + vrow) * KROWB + (p*16 + vcol) * 2;
                    ldsm4t(vf, addr);
                    mma16816h(O_[p*2+0], aP[kj], vf[0], vf[1]);
                    mma16816h(O_[p*2+1], aP[kj], vf[2], vf[3]);
                }
            }
        }
        __syncthreads();
    }

    const float li0 = 1.f / lrow0;
    const float li1 = 1.f / lrow1;
    const size_t ra = (size_t)(R + lq) * HD + hoff;
    const size_t rb = (size_t)(R + lq + 8) * HD + hoff;
#pragma unroll
    for (int nb = 0; nb < 16; nb++) {
        const int c = nb*8 + lc;
        *(uint32_t*)&Oh[ra + c] = packh(O_[nb][0] * li0, O_[nb][1] * li0);
        *(uint32_t*)&Oh[rb + c] = packh(O_[nb][2] * li1, O_[nb][3] * li1);
    }
}

// ---------------- launch ---------------------------------------------------------
extern "C" void kernel_launch(void* const* d_in, const int* in_sizes, int n_in,
                              void* d_out, int out_size)
{
    const float* x  = (const float*)d_in[0];
    const float* wq = (const float*)d_in[2];
    const float* wk = (const float*)d_in[3];
    const float* wv = (const float*)d_in[4];
    const float* wo = (const float*)d_in[5];
    float* out = (float*)d_out;

    __half *xh, *wqh, *wkh, *wvh, *woh;
    __half *qh, *kh, *vh, *aoh;
    cudaGetSymbolAddress((void**)&xh,   g_xh);
    cudaGetSymbolAddress((void**)&wqh,  g_wqh);  cudaGetSymbolAddress((void**)&wkh,  g_wkh);
    cudaGetSymbolAddress((void**)&wvh,  g_wvh);  cudaGetSymbolAddress((void**)&woh,  g_woh);
    cudaGetSymbolAddress((void**)&qh,   g_qh);   cudaGetSymbolAddress((void**)&kh,   g_kh);
    cudaGetSymbolAddress((void**)&vh,   g_vh);   cudaGetSymbolAddress((void**)&aoh,  g_aoh);

    cudaFuncSetAttribute(qkv_gemm_kernel,
                         cudaFuncAttributeMaxDynamicSharedMemorySize, QGSM);
    cudaFuncSetAttribute(gemm_mma_kernel,
                         cudaFuncAttributeMaxDynamicSharedMemorySize, QGSM);
    cudaFuncSetAttribute(attn_mma_kernel,
                         cudaFuncAttributeMaxDynamicSharedMemorySize, ASMEM);

    rope_inv_kernel<<<1, 64>>>();
    rope_table_kernel<<<(S_LEN*(DH/2) + 255)/256, 256>>>();

    cvt_all_kernel<<<(N4TOT + 255)/256, 256>>>(x, wq, wk, wv, wo,
                                               xh, wqh, wkh, wvh, woh);

    qkv_gemm_kernel<<<dim3(48, GM/128), 256, QGSM>>>(
        xh, wqh, wkh, wvh, qh, kh, vh);

    attn_mma_kernel<<<dim3(S_LEN/128, NH), 256, ASMEM>>>(
        qh, kh, vh, aoh);

    gemm_mma_kernel<<<dim3(GN/128, GM/128), 256, QGSM>>>(aoh, woh, out);
}

// round 9
// speedup vs baseline: 8.5937x; 1.2589x over previous
#include <cuda_runtime.h>
#include <cuda_fp16.h>
#include <math.h>
#include <stdint.h>

#define S_LEN 4096
#define D_IN  2048
#define NH    16
#define DH    128
#define HD    2048
#define GM 4096
#define GN 2048
#define GK 2048

// ---------------- scratch (device globals: no allocation allowed) ----------
__device__ float g_inv[64];
__device__ float g_cos[(size_t)S_LEN * (DH/2)];
__device__ float g_sin[(size_t)S_LEN * (DH/2)];
__device__ __half g_xh  [(size_t)S_LEN * D_IN];
__device__ __half g_wqh [(size_t)HD * D_IN];
__device__ __half g_wkh [(size_t)HD * D_IN];
__device__ __half g_wvh [(size_t)HD * D_IN];
__device__ __half g_woh [(size_t)D_IN * HD];
__device__ __half g_qh  [(size_t)S_LEN * HD];
__device__ __half g_kh  [(size_t)S_LEN * HD];
__device__ __half g_vh  [(size_t)S_LEN * HD];
__device__ __half g_aoh [(size_t)S_LEN * HD];

// ---------------- PTX helpers ------------------------------------------------
__device__ __forceinline__ uint32_t smem_u32(const void* p) {
    uint32_t a;
    asm("{ .reg .u64 t; cvta.to.shared.u64 t, %1; cvt.u32.u64 %0, t; }"
        : "=r"(a) : "l"(p));
    return a;
}
__device__ __forceinline__ void cpa16(uint32_t dst, const void* src) {
    asm volatile("cp.async.cg.shared.global [%0], [%1], 16;" :: "r"(dst), "l"(src));
}
__device__ __forceinline__ void cpa_commit() { asm volatile("cp.async.commit_group;"); }
__device__ __forceinline__ void cpa_wait0()  { asm volatile("cp.async.wait_group 0;"); }

__device__ __forceinline__ void ldsm4(uint32_t r[4], uint32_t addr) {
    asm volatile("ldmatrix.sync.aligned.m8n8.x4.shared.b16 {%0,%1,%2,%3}, [%4];"
        : "=r"(r[0]), "=r"(r[1]), "=r"(r[2]), "=r"(r[3]) : "r"(addr));
}
__device__ __forceinline__ void ldsm4t(uint32_t r[4], uint32_t addr) {
    asm volatile("ldmatrix.sync.aligned.m8n8.x4.trans.shared.b16 {%0,%1,%2,%3}, [%4];"
        : "=r"(r[0]), "=r"(r[1]), "=r"(r[2]), "=r"(r[3]) : "r"(addr));
}
__device__ __forceinline__ void mma16816h(float c[4], const uint32_t a[4],
                                          uint32_t b0, uint32_t b1) {
    asm volatile(
        "mma.sync.aligned.m16n8k16.row.col.f32.f16.f16.f32 "
        "{%0,%1,%2,%3}, {%4,%5,%6,%7}, {%8,%9}, {%0,%1,%2,%3};"
        : "+f"(c[0]), "+f"(c[1]), "+f"(c[2]), "+f"(c[3])
        : "r"(a[0]), "r"(a[1]), "r"(a[2]), "r"(a[3]), "r"(b0), "r"(b1));
}
__device__ __forceinline__ uint32_t packh(float a, float b) {
    __half2 t = __floats2half2_rn(a, b);
    return *(uint32_t*)&t;
}

// ---------------- fused fp32 -> fp16 conversion (all 5 tensors) ----------------
#define N4W (HD * D_IN / 4)          // 1048576 = 2^20
#define N4TOT (6 * N4W)

__global__ void cvt_all_kernel(const float* __restrict__ x,
                               const float* __restrict__ wq,
                               const float* __restrict__ wk,
                               const float* __restrict__ wv,
                               const float* __restrict__ wo,
                               __half* __restrict__ xh,
                               __half* __restrict__ wqh,
                               __half* __restrict__ wkh,
                               __half* __restrict__ wvh,
                               __half* __restrict__ woh) {
    int i = blockIdx.x * blockDim.x + threadIdx.x;
    if (i >= N4TOT) return;
    int seg = i >> 20;
    const float* in;
    __half* out;
    int off;
    if (seg < 2)      { in = x;  out = xh;  off = i; }
    else if (seg == 2){ in = wq; out = wqh; off = i - 2*N4W; }
    else if (seg == 3){ in = wk; out = wkh; off = i - 3*N4W; }
    else if (seg == 4){ in = wv; out = wvh; off = i - 4*N4W; }
    else              { in = wo; out = woh; off = i - 5*N4W; }
    float4 v = ((const float4*)in)[off];
    ((uint32_t*)out)[2*off]   = packh(v.x, v.y);
    ((uint32_t*)out)[2*off+1] = packh(v.z, v.w);
}

// ---------------- RoPE tables ---------------------------------------------------
__global__ void rope_inv_kernel() {
    int kp = threadIdx.x;   // 0..63
    if (kp < 64)
        g_inv[kp] = (float)pow(10000.0, -(double)(2*kp) / (double)DH);
}
__global__ void rope_table_kernel() {
    int idx = blockIdx.x * blockDim.x + threadIdx.x;
    if (idx >= S_LEN * (DH/2)) return;
    int row = idx >> 6;
    int kp  = idx & 63;
    float fr = (float)row * g_inv[kp];
    g_cos[idx] = cosf(fr);
    g_sin[idx] = sinf(fr);
}

// ---------------- shared GEMM tiling constants ----------------------------------
#define KS   32
#define ROWB 80
#define OPB  (128*ROWB)
#define QSTB (2*OPB)
#define QGSM (2*QSTB)

// ---------------- merged QKV GEMM: fp16 single-pass + fused RoPE ----------------
// __launch_bounds__(256, 2): cap regs at 128 so TWO CTAs fit per SM (occupancy
// was 12.4% / 1 CTA at 142 regs -> tensor pipe only 34.5% busy, latency-bound).
__global__ void __launch_bounds__(256, 2) qkv_gemm_kernel(
    const __half* __restrict__ Ah,
    const __half* __restrict__ Wq, const __half* __restrict__ Wk,
    const __half* __restrict__ Wv,
    __half* __restrict__ Qo, __half* __restrict__ Ko, __half* __restrict__ Vo)
{
    extern __shared__ char smraw[];
    const uint32_t sb = smem_u32(smraw);
    const int tid = threadIdx.x;
    const int w   = tid >> 5;
    const int l   = tid & 31;
    const int wm  = w & 3;
    const int wn  = w >> 2;
    const int m0  = blockIdx.y * 128;
    const int which = blockIdx.x >> 4;          // 0=q 1=k 2=v
    const int n0  = (blockIdx.x & 15) * 128;

    const __half* B = (which == 0) ? Wq : (which == 1) ? Wk : Wv;
    __half* Out     = (which == 0) ? Qo : (which == 1) ? Ko : Vo;

    const __half* ops[2] = { Ah + (size_t)m0 * GK, B + (size_t)n0 * GK };

    const int r0 = tid >> 2, c0 = tid & 3;
    const int r1 = (tid + 256) >> 2, c1 = tid & 3;

    float acc[2][8][4];
#pragma unroll
    for (int a = 0; a < 2; a++)
#pragma unroll
        for (int b = 0; b < 8; b++)
#pragma unroll
            for (int c = 0; c < 4; c++) acc[a][b][c] = 0.f;

#pragma unroll
    for (int op = 0; op < 2; op++) {
        cpa16(sb + op*OPB + r0*ROWB + c0*16, ops[op] + (size_t)r0 * GK + c0*8);
        cpa16(sb + op*OPB + r1*ROWB + c1*16, ops[op] + (size_t)r1 * GK + c1*8);
    }
    cpa_commit();

    const int a_row = wm*32 + (l & 15);
    const int a_kc  = (l >> 4) * 8;
    const int b_row = wn*64 + (l & 7) + ((l >> 4) << 3);
    const int b_kc  = ((l >> 3) & 1) * 8;

    const int NSLAB = GK / KS;
    for (int s = 0; s < NSLAB; s++) {
        const int buf = s & 1;
        cpa_wait0();
        __syncthreads();
        if (s + 1 < NSLAB) {
            const int k0 = (s + 1) * KS;
            const uint32_t dst = sb + (buf ^ 1) * QSTB;
#pragma unroll
            for (int op = 0; op < 2; op++) {
                cpa16(dst + op*OPB + r0*ROWB + c0*16, ops[op] + (size_t)r0*GK + k0 + c0*8);
                cpa16(dst + op*OPB + r1*ROWB + c1*16, ops[op] + (size_t)r1*GK + k0 + c1*8);
            }
            cpa_commit();
        }
        const uint32_t base = sb + buf * QSTB;
#pragma unroll
        for (int ks = 0; ks < 2; ks++) {
            uint32_t ah[2][4];
#pragma unroll
            for (int mt = 0; mt < 2; mt++) {
                uint32_t aaddr = base + (a_row + mt*16) * ROWB + (ks*16 + a_kc) * 2;
                ldsm4(ah[mt], aaddr);
            }
#pragma unroll
            for (int np = 0; np < 4; np++) {
                uint32_t bh[4];
                uint32_t baddr = base + OPB + (b_row + np*16) * ROWB + (ks*16 + b_kc) * 2;
                ldsm4(bh, baddr);
#pragma unroll
                for (int mt = 0; mt < 2; mt++) {
                    mma16816h(acc[mt][np*2+0], ah[mt], bh[0], bh[1]);
                    mma16816h(acc[mt][np*2+1], ah[mt], bh[2], bh[3]);
                }
            }
        }
        __syncthreads();
    }

    // ---- epilogue: optional RoPE, fp16 pack, store ----
#pragma unroll
    for (int mt = 0; mt < 2; mt++) {
        const int row = m0 + wm*32 + mt*16 + (l >> 2);
#pragma unroll
        for (int nt = 0; nt < 8; nt++) {
            const int gcol = n0 + wn*64 + nt*8 + (l & 3) * 2;   // even
            float a0 = acc[mt][nt][0], a1 = acc[mt][nt][1];
            float b0 = acc[mt][nt][2], b1 = acc[mt][nt][3];
            if (which < 2) {
                const int kp = (gcol & (DH - 1)) >> 1;
                float c0 = g_cos[(size_t)row * 64 + kp];
                float s0 = g_sin[(size_t)row * 64 + kp];
                float c1 = g_cos[(size_t)(row + 8) * 64 + kp];
                float s1 = g_sin[(size_t)(row + 8) * 64 + kp];
                float t0 = a0 * c0 - a1 * s0; a1 = a1 * c0 + a0 * s0; a0 = t0;
                float t1 = b0 * c1 - b1 * s1; b1 = b1 * c1 + b0 * s1; b0 = t1;
            }
            *(uint32_t*)&Out[(size_t)row * HD + gcol]       = packh(a0, a1);
            *(uint32_t*)&Out[(size_t)(row + 8) * HD + gcol] = packh(b0, b1);
        }
    }
}

// ---------------- output-projection GEMM (fp16 single-pass, fp32 out) ----------
__global__ void __launch_bounds__(256, 2) gemm_mma_kernel(
    const __half* __restrict__ Ah, const __half* __restrict__ Bh,
    float* __restrict__ C)
{
    extern __shared__ char smraw[];
    const uint32_t sb = smem_u32(smraw);
    const int tid = threadIdx.x;
    const int w   = tid >> 5;
    const int l   = tid & 31;
    const int wm  = w & 3;
    const int wn  = w >> 2;
    const int m0  = blockIdx.y * 128;
    const int n0  = blockIdx.x * 128;

    const __half* ops[2] = { Ah + (size_t)m0 * GK, Bh + (size_t)n0 * GK };

    const int r0 = tid >> 2, c0 = tid & 3;
    const int r1 = (tid + 256) >> 2, c1 = tid & 3;

    float acc[2][8][4];
#pragma unroll
    for (int a = 0; a < 2; a++)
#pragma unroll
        for (int b = 0; b < 8; b++)
#pragma unroll
            for (int c = 0; c < 4; c++) acc[a][b][c] = 0.f;

#pragma unroll
    for (int op = 0; op < 2; op++) {
        cpa16(sb + op*OPB + r0*ROWB + c0*16, ops[op] + (size_t)r0 * GK + c0*8);
        cpa16(sb + op*OPB + r1*ROWB + c1*16, ops[op] + (size_t)r1 * GK + c1*8);
    }
    cpa_commit();

    const int a_row = wm*32 + (l & 15);
    const int a_kc  = (l >> 4) * 8;
    const int b_row = wn*64 + (l & 7) + ((l >> 4) << 3);
    const int b_kc  = ((l >> 3) & 1) * 8;

    const int NSLAB = GK / KS;
    for (int s = 0; s < NSLAB; s++) {
        const int buf = s & 1;
        cpa_wait0();
        __syncthreads();
        if (s + 1 < NSLAB) {
            const int k0 = (s + 1) * KS;
            const uint32_t dst = sb + (buf ^ 1) * QSTB;
#pragma unroll
            for (int op = 0; op < 2; op++) {
                cpa16(dst + op*OPB + r0*ROWB + c0*16, ops[op] + (size_t)r0*GK + k0 + c0*8);
                cpa16(dst + op*OPB + r1*ROWB + c1*16, ops[op] + (size_t)r1*GK + k0 + c1*8);
            }
            cpa_commit();
        }
        const uint32_t base = sb + buf * QSTB;
#pragma unroll
        for (int ks = 0; ks < 2; ks++) {
            uint32_t ah[2][4];
#pragma unroll
            for (int mt = 0; mt < 2; mt++) {
                uint32_t aaddr = base + (a_row + mt*16) * ROWB + (ks*16 + a_kc) * 2;
                ldsm4(ah[mt], aaddr);
            }
#pragma unroll
            for (int np = 0; np < 4; np++) {
                uint32_t bh[4];
                uint32_t baddr = base + OPB + (b_row + np*16) * ROWB + (ks*16 + b_kc) * 2;
                ldsm4(bh, baddr);
#pragma unroll
                for (int mt = 0; mt < 2; mt++) {
                    mma16816h(acc[mt][np*2+0], ah[mt], bh[0], bh[1]);
                    mma16816h(acc[mt][np*2+1], ah[mt], bh[2], bh[3]);
                }
            }
        }
        __syncthreads();
    }

#pragma unroll
    for (int mt = 0; mt < 2; mt++) {
        const int row = m0 + wm*32 + mt*16 + (l >> 2);
#pragma unroll
        for (int nt = 0; nt < 8; nt++) {
            const int col = n0 + wn*64 + nt*8 + (l & 3) * 2;
            float2 v0 = make_float2(acc[mt][nt][0], acc[mt][nt][1]);
            float2 v1 = make_float2(acc[mt][nt][2], acc[mt][nt][3]);
            *(float2*)&C[(size_t)row * GN + col]       = v0;
            *(float2*)&C[(size_t)(row + 8) * GN + col] = v1;
        }
    }
}

// ---------------- tensor-core flash attention (fp16 single-pass, causal) --------
#define KROWB 272
#define KOPB  (64*KROWB)
#define KSTB  (2*KOPB)
#define ASMEM (2*KSTB)

__device__ __forceinline__ void attn_load_kv(
    uint32_t dstbase,
    const __half* __restrict__ kh, const __half* __restrict__ vh,
    int kvbase, int tid)
{
#pragma unroll
    for (int i = 0; i < 8; i++) {
        const int op  = i >> 2;
        const int rem = (i & 3) * 256 + tid;
        const int row = rem >> 4;
        const int col = rem & 15;
        const __half* src = (op == 0) ? kh : vh;
        cpa16(dstbase + op*KOPB + row*KROWB + col*16,
              src + (size_t)(kvbase + row) * HD + col*8);
    }
    cpa_commit();
}

__global__ void __launch_bounds__(256, 1) attn_mma_kernel(
    const __half* __restrict__ Qh, const __half* __restrict__ Kh,
    const __half* __restrict__ Vh, __half* __restrict__ Oh)
{
    extern __shared__ char smraw[];
    const uint32_t sb = smem_u32(smraw);
    const int tid = threadIdx.x;
    const int w = tid >> 5, l = tid & 31;
    const int qb = gridDim.x - 1 - blockIdx.x;   // big tiles first
    const int h  = blockIdx.y;
    const int lq = l >> 2;
    const int lc = (l & 3) * 2;
    const float scale = 0.08838834764831845f;

    const int R = qb * 128 + w * 16;
    const size_t hoff = (size_t)h * DH;
    const __half* kh = Kh + hoff;
    const __half* vh = Vh + hoff;

    uint32_t qf[8][4];
    {
        const __half* qhp = Qh + hoff;
        const size_t ra = (size_t)(R + lq) * HD;
        const size_t rb = (size_t)(R + lq + 8) * HD;
#pragma unroll
        for (int kc = 0; kc < 8; kc++) {
            const int c = kc * 16 + lc;
            qf[kc][0] = *(const uint32_t*)&qhp[ra + c];
            qf[kc][1] = *(const uint32_t*)&qhp[rb + c];
            qf[kc][2] = *(const uint32_t*)&qhp[ra + c + 8];
            qf[kc][3] = *(const uint32_t*)&qhp[rb + c + 8];
        }
    }

    float O_[16][4];
#pragma unroll
    for (int nb = 0; nb < 16; nb++)
#pragma unroll
        for (int e = 0; e < 4; e++) O_[nb][e] = 0.f;
    float mrow0 = -INFINITY, mrow1 = -INFINITY;
    float lrow0 = 0.f, lrow1 = 0.f;

    const int nkv = 2 * qb + 2;
    attn_load_kv(sb, kh, vh, 0, tid);

    for (int jb = 0; jb < nkv; jb++) {
        const uint32_t base = sb + (jb & 1) * KSTB;
        cpa_wait0();
        __syncthreads();
        if (jb + 1 < nkv)
            attn_load_kv(sb + ((jb + 1) & 1) * KSTB, kh, vh, (jb + 1) * 64, tid);

        const int kvb = jb * 64;
        const bool active = (kvb <= R + 15);     // warp-uniform
        if (active) {
            float S_[8][4];
#pragma unroll
            for (int nb = 0; nb < 8; nb++)
#pragma unroll
                for (int e = 0; e < 4; e++) S_[nb][e] = 0.f;

            const uint32_t krow = (l & 7) + ((l >> 4) << 3);
            const uint32_t kcol = ((l >> 3) & 1) * 8;
#pragma unroll
            for (int kc = 0; kc < 8; kc++) {
#pragma unroll
                for (int p = 0; p < 4; p++) {
                    uint32_t bh[4];
                    uint32_t addr = base + (p*16 + krow) * KROWB + (kc*16 + kcol) * 2;
                    ldsm4(bh, addr);
                    mma16816h(S_[p*2+0], qf[kc], bh[0], bh[1]);
                    mma16816h(S_[p*2+1], qf[kc], bh[2], bh[3]);
                }
            }

            const bool domask = (kvb + 63 > R);
            float mx0 = -INFINITY, mx1 = -INFINITY;
#pragma unroll
            for (int nb = 0; nb < 8; nb++) {
                const int colb = kvb + nb*8 + lc;
#pragma unroll
                for (int e = 0; e < 4; e++) {
                    float v = S_[nb][e] * scale;
                    if (domask) {
                        int row = R + lq + (e >> 1) * 8;
                        int col = colb + (e & 1);
                        if (col > row) v = -INFINITY;
                    }
                    S_[nb][e] = v;
                    if (e < 2) mx0 = fmaxf(mx0, v); else mx1 = fmaxf(mx1, v);
                }
            }
            mx0 = fmaxf(mx0, __shfl_xor_sync(0xffffffffu, mx0, 1));
            mx0 = fmaxf(mx0, __shfl_xor_sync(0xffffffffu, mx0, 2));
            mx1 = fmaxf(mx1, __shfl_xor_sync(0xffffffffu, mx1, 1));
            mx1 = fmaxf(mx1, __shfl_xor_sync(0xffffffffu, mx1, 2));
            const float mn0 = fmaxf(mrow0, mx0);
            const float mn1 = fmaxf(mrow1, mx1);
            const float cr0 = __expf(mrow0 - mn0);
            const float cr1 = __expf(mrow1 - mn1);
            mrow0 = mn0; mrow1 = mn1;
            float ls0 = 0.f, ls1 = 0.f;
#pragma unroll
            for (int nb = 0; nb < 8; nb++) {
                float p0 = __expf(S_[nb][0] - mn0);
                float p1 = __expf(S_[nb][1] - mn0);
                float p2 = __expf(S_[nb][2] - mn1);
                float p3 = __expf(S_[nb][3] - mn1);
                S_[nb][0] = p0; S_[nb][1] = p1; S_[nb][2] = p2; S_[nb][3] = p3;
                ls0 += p0 + p1; ls1 += p2 + p3;
            }
            ls0 += __shfl_xor_sync(0xffffffffu, ls0, 1);
            ls0 += __shfl_xor_sync(0xffffffffu, ls0, 2);
            ls1 += __shfl_xor_sync(0xffffffffu, ls1, 1);
            ls1 += __shfl_xor_sync(0xffffffffu, ls1, 2);
            lrow0 = lrow0 * cr0 + ls0;
            lrow1 = lrow1 * cr1 + ls1;

            uint32_t aP[4][4];
#pragma unroll
            for (int kj = 0; kj < 4; kj++) {
#pragma unroll
                for (int half = 0; half < 2; half++) {
                    const int nb = kj*2 + half;
                    aP[kj][half*2+0] = packh(S_[nb][0], S_[nb][1]);
                    aP[kj][half*2+1] = packh(S_[nb][2], S_[nb][3]);
                }
            }

#pragma unroll
            for (int nb = 0; nb < 16; nb++) {
                O_[nb][0] *= cr0; O_[nb][1] *= cr0;
                O_[nb][2] *= cr1; O_[nb][3] *= cr1;
            }

            const uint32_t vrow = (l & 15);
            const uint32_t vcol = ((l >> 4) << 3);
#pragma unroll
            for (int kj = 0; kj < 4; kj++) {
#pragma unroll
                for (int p = 0; p < 8; p++) {
                    uint32_t vf[4];
                    uint32_t addr = base + KOPB + (kj*16 + vrow) * KROWB + (p*16 + vcol) * 2;
                    ldsm4t(vf, addr);
                    mma16816h(O_[p*2+0], aP[kj], vf[0], vf[1]);
                    mma16816h(O_[p*2+1], aP[kj], vf[2], vf[3]);
                }
            }
        }
        __syncthreads();
    }

    const float li0 = 1.f / lrow0;
    const float li1 = 1.f / lrow1;
    const size_t ra = (size_t)(R + lq) * HD + hoff;
    const size_t rb = (size_t)(R + lq + 8) * HD + hoff;
#pragma unroll
    for (int nb = 0; nb < 16; nb++) {
        const int c = nb*8 + lc;
        *(uint32_t*)&Oh[ra + c] = packh(O_[nb][0] * li0, O_[nb][1] * li0);
        *(uint32_t*)&Oh[rb + c] = packh(O_[nb][2] * li1, O_[nb][3] * li1);
    }
}

// ---------------- launch ---------------------------------------------------------
extern "C" void kernel_launch(void* const* d_in, const int* in_sizes, int n_in,
                              void* d_out, int out_size)
{
    const float* x  = (const float*)d_in[0];
    const float* wq = (const float*)d_in[2];
    const float* wk = (const float*)d_in[3];
    const float* wv = (const float*)d_in[4];
    const float* wo = (const float*)d_in[5];
    float* out = (float*)d_out;

    __half *xh, *wqh, *wkh, *wvh, *woh;
    __half *qh, *kh, *vh, *aoh;
    cudaGetSymbolAddress((void**)&xh,   g_xh);
    cudaGetSymbolAddress((void**)&wqh,  g_wqh);  cudaGetSymbolAddress((void**)&wkh,  g_wkh);
    cudaGetSymbolAddress((void**)&wvh,  g_wvh);  cudaGetSymbolAddress((void**)&woh,  g_woh);
    cudaGetSymbolAddress((void**)&qh,   g_qh);   cudaGetSymbolAddress((void**)&kh,   g_kh);
    cudaGetSymbolAddress((void**)&vh,   g_vh);   cudaGetSymbolAddress((void**)&aoh,  g_aoh);

    cudaFuncSetAttribute(qkv_gemm_kernel,
                         cudaFuncAttributeMaxDynamicSharedMemorySize, QGSM);
    cudaFuncSetAttribute(gemm_mma_kernel,
                         cudaFuncAttributeMaxDynamicSharedMemorySize, QGSM);
    cudaFuncSetAttribute(attn_mma_kernel,
                         cudaFuncAttributeMaxDynamicSharedMemorySize, ASMEM);

    rope_inv_kernel<<<1, 64>>>();
    rope_table_kernel<<<(S_LEN*(DH/2) + 255)/256, 256>>>();

    cvt_all_kernel<<<(N4TOT + 255)/256, 256>>>(x, wq, wk, wv, wo,
                                               xh, wqh, wkh, wvh, woh);

    qkv_gemm_kernel<<<dim3(48, GM/128), 256, QGSM>>>(
        xh, wqh, wkh, wvh, qh, kh, vh);

    attn_mma_kernel<<<dim3(S_LEN/128, NH), 256, ASMEM>>>(
        qh, kh, vh, aoh);

    gemm_mma_kernel<<<dim3(GN/128, GM/128), 256, QGSM>>>(aoh, woh, out);
}

// round 10
// speedup vs baseline: 8.8092x; 1.0251x over previous
#include <cuda_runtime.h>
#include <cuda_fp16.h>
#include <math.h>
#include <stdint.h>

#define S_LEN 4096
#define D_IN  2048
#define NH    16
#define DH    128
#define HD    2048
#define GM 4096
#define GN 2048
#define GK 2048

// ---------------- scratch (device globals: no allocation allowed) ----------
__device__ float g_inv[64];
__device__ float g_cos[(size_t)S_LEN * (DH/2)];
__device__ float g_sin[(size_t)S_LEN * (DH/2)];
__device__ __half g_xh  [(size_t)S_LEN * D_IN];
__device__ __half g_wqh [(size_t)HD * D_IN];
__device__ __half g_wkh [(size_t)HD * D_IN];
__device__ __half g_wvh [(size_t)HD * D_IN];
__device__ __half g_woh [(size_t)D_IN * HD];
__device__ __half g_qh  [(size_t)S_LEN * HD];
__device__ __half g_kh  [(size_t)S_LEN * HD];
__device__ __half g_vh  [(size_t)S_LEN * HD];
__device__ __half g_aoh [(size_t)S_LEN * HD];

// ---------------- PTX helpers ------------------------------------------------
__device__ __forceinline__ uint32_t smem_u32(const void* p) {
    uint32_t a;
    asm("{ .reg .u64 t; cvta.to.shared.u64 t, %1; cvt.u32.u64 %0, t; }"
        : "=r"(a) : "l"(p));
    return a;
}
__device__ __forceinline__ void cpa16(uint32_t dst, const void* src) {
    asm volatile("cp.async.cg.shared.global [%0], [%1], 16;" :: "r"(dst), "l"(src));
}
__device__ __forceinline__ void cpa_commit() { asm volatile("cp.async.commit_group;"); }
__device__ __forceinline__ void cpa_wait0()  { asm volatile("cp.async.wait_group 0;"); }

__device__ __forceinline__ void ldsm4(uint32_t r[4], uint32_t addr) {
    asm volatile("ldmatrix.sync.aligned.m8n8.x4.shared.b16 {%0,%1,%2,%3}, [%4];"
        : "=r"(r[0]), "=r"(r[1]), "=r"(r[2]), "=r"(r[3]) : "r"(addr));
}
__device__ __forceinline__ void ldsm4t(uint32_t r[4], uint32_t addr) {
    asm volatile("ldmatrix.sync.aligned.m8n8.x4.trans.shared.b16 {%0,%1,%2,%3}, [%4];"
        : "=r"(r[0]), "=r"(r[1]), "=r"(r[2]), "=r"(r[3]) : "r"(addr));
}
__device__ __forceinline__ void mma16816h(float c[4], const uint32_t a[4],
                                          uint32_t b0, uint32_t b1) {
    asm volatile(
        "mma.sync.aligned.m16n8k16.row.col.f32.f16.f16.f32 "
        "{%0,%1,%2,%3}, {%4,%5,%6,%7}, {%8,%9}, {%0,%1,%2,%3};"
        : "+f"(c[0]), "+f"(c[1]), "+f"(c[2]), "+f"(c[3])
        : "r"(a[0]), "r"(a[1]), "r"(a[2]), "r"(a[3]), "r"(b0), "r"(b1));
}
__device__ __forceinline__ uint32_t packh(float a, float b) {
    __half2 t = __floats2half2_rn(a, b);
    return *(uint32_t*)&t;
}

// ---------------- fused fp32 -> fp16 conversion (all 5 tensors) ----------------
#define N4W (HD * D_IN / 4)          // 1048576 = 2^20
#define N4TOT (6 * N4W)

__global__ void cvt_all_kernel(const float* __restrict__ x,
                               const float* __restrict__ wq,
                               const float* __restrict__ wk,
                               const float* __restrict__ wv,
                               const float* __restrict__ wo,
                               __half* __restrict__ xh,
                               __half* __restrict__ wqh,
                               __half* __restrict__ wkh,
                               __half* __restrict__ wvh,
                               __half* __restrict__ woh) {
    int i = blockIdx.x * blockDim.x + threadIdx.x;
    if (i >= N4TOT) return;
    int seg = i >> 20;
    const float* in;
    __half* out;
    int off;
    if (seg < 2)      { in = x;  out = xh;  off = i; }
    else if (seg == 2){ in = wq; out = wqh; off = i - 2*N4W; }
    else if (seg == 3){ in = wk; out = wkh; off = i - 3*N4W; }
    else if (seg == 4){ in = wv; out = wvh; off = i - 4*N4W; }
    else              { in = wo; out = woh; off = i - 5*N4W; }
    float4 v = ((const float4*)in)[off];
    ((uint32_t*)out)[2*off]   = packh(v.x, v.y);
    ((uint32_t*)out)[2*off+1] = packh(v.z, v.w);
}

// ---------------- RoPE tables ---------------------------------------------------
__global__ void rope_inv_kernel() {
    int kp = threadIdx.x;   // 0..63
    if (kp < 64)
        g_inv[kp] = (float)pow(10000.0, -(double)(2*kp) / (double)DH);
}
__global__ void rope_table_kernel() {
    int idx = blockIdx.x * blockDim.x + threadIdx.x;
    if (idx >= S_LEN * (DH/2)) return;
    int row = idx >> 6;
    int kp  = idx & 63;
    float fr = (float)row * g_inv[kp];
    g_cos[idx] = cosf(fr);
    g_sin[idx] = sinf(fr);
}

// ---------------- shared GEMM tiling constants ----------------------------------
// K slab 64 (was 32): half the __syncthreads, 2x MMA run-length per barrier.
#define KS   64
#define ROWB 144                 // 128B data + 16B pad; row offsets mod 128 step 16
#define OPB  (128*ROWB)          // 18432
#define QSTB (2*OPB)             // 36864 per stage
#define QGSM (2*QSTB)            // 73728

// ---------------- merged QKV GEMM: fp16 single-pass + fused RoPE ----------------
__global__ void __launch_bounds__(256, 2) qkv_gemm_kernel(
    const __half* __restrict__ Ah,
    const __half* __restrict__ Wq, const __half* __restrict__ Wk,
    const __half* __restrict__ Wv,
    __half* __restrict__ Qo, __half* __restrict__ Ko, __half* __restrict__ Vo)
{
    extern __shared__ char smraw[];
    const uint32_t sb = smem_u32(smraw);
    const int tid = threadIdx.x;
    const int w   = tid >> 5;
    const int l   = tid & 31;
    const int wm  = w & 3;
    const int wn  = w >> 2;
    const int m0  = blockIdx.y * 128;
    const int which = blockIdx.x >> 4;          // 0=q 1=k 2=v
    const int n0  = (blockIdx.x & 15) * 128;

    const __half* B = (which == 0) ? Wq : (which == 1) ? Wk : Wv;
    __half* Out     = (which == 0) ? Qo : (which == 1) ? Ko : Vo;

    const __half* ops[2] = { Ah + (size_t)m0 * GK, B + (size_t)n0 * GK };

    float acc[2][8][4];
#pragma unroll
    for (int a = 0; a < 2; a++)
#pragma unroll
        for (int b = 0; b < 8; b++)
#pragma unroll
            for (int c = 0; c < 4; c++) acc[a][b][c] = 0.f;

    // prologue: stage 0 (k0 = 0); 128 rows x 8 chunks per operand
#pragma unroll
    for (int op = 0; op < 2; op++)
#pragma unroll
        for (int it = 0; it < 4; it++) {
            const int rem = it * 256 + tid;
            const int r = rem >> 3, ch = rem & 7;
            cpa16(sb + op*OPB + r*ROWB + ch*16, ops[op] + (size_t)r * GK + ch*8);
        }
    cpa_commit();

    const int a_row = wm*32 + (l & 15);
    const int a_kc  = (l >> 4) * 8;
    const int b_row = wn*64 + (l & 7) + ((l >> 4) << 3);
    const int b_kc  = ((l >> 3) & 1) * 8;

    const int NSLAB = GK / KS;   // 32
    for (int s = 0; s < NSLAB; s++) {
        const int buf = s & 1;
        cpa_wait0();
        __syncthreads();
        if (s + 1 < NSLAB) {
            const int k0 = (s + 1) * KS;
            const uint32_t dst = sb + (buf ^ 1) * QSTB;
#pragma unroll
            for (int op = 0; op < 2; op++)
#pragma unroll
                for (int it = 0; it < 4; it++) {
                    const int rem = it * 256 + tid;
                    const int r = rem >> 3, ch = rem & 7;
                    cpa16(dst + op*OPB + r*ROWB + ch*16,
                          ops[op] + (size_t)r*GK + k0 + ch*8);
                }
            cpa_commit();
        }
        const uint32_t base = sb + buf * QSTB;
#pragma unroll
        for (int ks = 0; ks < 4; ks++) {
            uint32_t ah[2][4];
#pragma unroll
            for (int mt = 0; mt < 2; mt++) {
                uint32_t aaddr = base + (a_row + mt*16) * ROWB + (ks*16 + a_kc) * 2;
                ldsm4(ah[mt], aaddr);
            }
#pragma unroll
            for (int np = 0; np < 4; np++) {
                uint32_t bh[4];
                uint32_t baddr = base + OPB + (b_row + np*16) * ROWB + (ks*16 + b_kc) * 2;
                ldsm4(bh, baddr);
#pragma unroll
                for (int mt = 0; mt < 2; mt++) {
                    mma16816h(acc[mt][np*2+0], ah[mt], bh[0], bh[1]);
                    mma16816h(acc[mt][np*2+1], ah[mt], bh[2], bh[3]);
                }
            }
        }
        __syncthreads();
    }

    // ---- epilogue: optional RoPE, fp16 pack, store ----
#pragma unroll
    for (int mt = 0; mt < 2; mt++) {
        const int row = m0 + wm*32 + mt*16 + (l >> 2);
#pragma unroll
        for (int nt = 0; nt < 8; nt++) {
            const int gcol = n0 + wn*64 + nt*8 + (l & 3) * 2;   // even
            float a0 = acc[mt][nt][0], a1 = acc[mt][nt][1];
            float b0 = acc[mt][nt][2], b1 = acc[mt][nt][3];
            if (which < 2) {
                const int kp = (gcol & (DH - 1)) >> 1;
                float c0 = g_cos[(size_t)row * 64 + kp];
                float s0 = g_sin[(size_t)row * 64 + kp];
                float c1 = g_cos[(size_t)(row + 8) * 64 + kp];
                float s1 = g_sin[(size_t)(row + 8) * 64 + kp];
                float t0 = a0 * c0 - a1 * s0; a1 = a1 * c0 + a0 * s0; a0 = t0;
                float t1 = b0 * c1 - b1 * s1; b1 = b1 * c1 + b0 * s1; b0 = t1;
            }
            *(uint32_t*)&Out[(size_t)row * HD + gcol]       = packh(a0, a1);
            *(uint32_t*)&Out[(size_t)(row + 8) * HD + gcol] = packh(b0, b1);
        }
    }
}

// ---------------- output-projection GEMM (fp16 single-pass, fp32 out) ----------
__global__ void __launch_bounds__(256, 2) gemm_mma_kernel(
    const __half* __restrict__ Ah, const __half* __restrict__ Bh,
    float* __restrict__ C)
{
    extern __shared__ char smraw[];
    const uint32_t sb = smem_u32(smraw);
    const int tid = threadIdx.x;
    const int w   = tid >> 5;
    const int l   = tid & 31;
    const int wm  = w & 3;
    const int wn  = w >> 2;
    const int m0  = blockIdx.y * 128;
    const int n0  = blockIdx.x * 128;

    const __half* ops[2] = { Ah + (size_t)m0 * GK, Bh + (size_t)n0 * GK };

    float acc[2][8][4];
#pragma unroll
    for (int a = 0; a < 2; a++)
#pragma unroll
        for (int b = 0; b < 8; b++)
#pragma unroll
            for (int c = 0; c < 4; c++) acc[a][b][c] = 0.f;

#pragma unroll
    for (int op = 0; op < 2; op++)
#pragma unroll
        for (int it = 0; it < 4; it++) {
            const int rem = it * 256 + tid;
            const int r = rem >> 3, ch = rem & 7;
            cpa16(sb + op*OPB + r*ROWB + ch*16, ops[op] + (size_t)r * GK + ch*8);
        }
    cpa_commit();

    const int a_row = wm*32 + (l & 15);
    const int a_kc  = (l >> 4) * 8;
    const int b_row = wn*64 + (l & 7) + ((l >> 4) << 3);
    const int b_kc  = ((l >> 3) & 1) * 8;

    const int NSLAB = GK / KS;
    for (int s = 0; s < NSLAB; s++) {
        const int buf = s & 1;
        cpa_wait0();
        __syncthreads();
        if (s + 1 < NSLAB) {
            const int k0 = (s + 1) * KS;
            const uint32_t dst = sb + (buf ^ 1) * QSTB;
#pragma unroll
            for (int op = 0; op < 2; op++)
#pragma unroll
                for (int it = 0; it < 4; it++) {
                    const int rem = it * 256 + tid;
                    const int r = rem >> 3, ch = rem & 7;
                    cpa16(dst + op*OPB + r*ROWB + ch*16,
                          ops[op] + (size_t)r*GK + k0 + ch*8);
                }
            cpa_commit();
        }
        const uint32_t base = sb + buf * QSTB;
#pragma unroll
        for (int ks = 0; ks < 4; ks++) {
            uint32_t ah[2][4];
#pragma unroll
            for (int mt = 0; mt < 2; mt++) {
                uint32_t aaddr = base + (a_row + mt*16) * ROWB + (ks*16 + a_kc) * 2;
                ldsm4(ah[mt], aaddr);
            }
#pragma unroll
            for (int np = 0; np < 4; np++) {
                uint32_t bh[4];
                uint32_t baddr = base + OPB + (b_row + np*16) * ROWB + (ks*16 + b_kc) * 2;
                ldsm4(bh, baddr);
#pragma unroll
                for (int mt = 0; mt < 2; mt++) {
                    mma16816h(acc[mt][np*2+0], ah[mt], bh[0], bh[1]);
                    mma16816h(acc[mt][np*2+1], ah[mt], bh[2], bh[3]);
                }
            }
        }
        __syncthreads();
    }

#pragma unroll
    for (int mt = 0; mt < 2; mt++) {
        const int row = m0 + wm*32 + mt*16 + (l >> 2);
#pragma unroll
        for (int nt = 0; nt < 8; nt++) {
            const int col = n0 + wn*64 + nt*8 + (l & 3) * 2;
            float2 v0 = make_float2(acc[mt][nt][0], acc[mt][nt][1]);
            float2 v1 = make_float2(acc[mt][nt][2], acc[mt][nt][3]);
            *(float2*)&C[(size_t)row * GN + col]       = v0;
            *(float2*)&C[(size_t)(row + 8) * GN + col] = v1;
        }
    }
}

// ---------------- tensor-core flash attention (fp16, causal) --------------------
// Q tile in SMEM (frees 32 regs/thread) -> 2 CTAs/SM.
#define QROWB 272
#define QTILE (128*QROWB)         // 34816
#define KROWB 272
#define KOPB  (64*KROWB)          // 17408
#define KSTB  (2*KOPB)            // 34816
#define ASMEM (QTILE + 2*KSTB)    // 104448

__device__ __forceinline__ void attn_load_kv(
    uint32_t dstbase,
    const __half* __restrict__ kh, const __half* __restrict__ vh,
    int kvbase, int tid)
{
#pragma unroll
    for (int i = 0; i < 8; i++) {
        const int op  = i >> 2;
        const int rem = (i & 3) * 256 + tid;
        const int row = rem >> 4;
        const int col = rem & 15;
        const __half* src = (op == 0) ? kh : vh;
        cpa16(dstbase + op*KOPB + row*KROWB + col*16,
              src + (size_t)(kvbase + row) * HD + col*8);
    }
    cpa_commit();
}

__global__ void __launch_bounds__(256, 2) attn_mma_kernel(
    const __half* __restrict__ Qh, const __half* __restrict__ Kh,
    const __half* __restrict__ Vh, __half* __restrict__ Oh)
{
    extern __shared__ char smraw[];
    const uint32_t sb = smem_u32(smraw);
    const uint32_t kvb0 = sb + QTILE;           // KV stages start after Q tile
    const int tid = threadIdx.x;
    const int w = tid >> 5, l = tid & 31;
    const int qb = gridDim.x - 1 - blockIdx.x;   // big tiles first
    const int h  = blockIdx.y;
    const int lq = l >> 2;
    const int lc = (l & 3) * 2;
    const float scale = 0.08838834764831845f;

    const int R = qb * 128 + w * 16;
    const size_t hoff = (size_t)h * DH;
    const __half* kh = Kh + hoff;
    const __half* vh = Vh + hoff;

    // load Q tile (128 rows x 256B) into smem via cp.async
    {
        const __half* qhp = Qh + hoff;
#pragma unroll
        for (int i = 0; i < 8; i++) {
            const int rem = i * 256 + tid;
            const int r = rem >> 4, ch = rem & 15;
            cpa16(sb + r*QROWB + ch*16,
                  qhp + (size_t)(qb*128 + r) * HD + ch*8);
        }
        cpa_commit();
    }

    float O_[16][4];
#pragma unroll
    for (int nb = 0; nb < 16; nb++)
#pragma unroll
        for (int e = 0; e < 4; e++) O_[nb][e] = 0.f;
    float mrow0 = -INFINITY, mrow1 = -INFINITY;
    float lrow0 = 0.f, lrow1 = 0.f;

    const int nkv = 2 * qb + 2;
    attn_load_kv(kvb0, kh, vh, 0, tid);

    // Q a-frag ldsm base address (row = w*16 + (l&15), col chunk = (l>>4)*8)
    const uint32_t qaddr0 = sb + (w*16 + (l & 15)) * QROWB + ((l >> 4) * 8) * 2;

    for (int jb = 0; jb < nkv; jb++) {
        const uint32_t base = kvb0 + (jb & 1) * KSTB;
        cpa_wait0();
        __syncthreads();
        if (jb + 1 < nkv)
            attn_load_kv(kvb0 + ((jb + 1) & 1) * KSTB, kh, vh, (jb + 1) * 64, tid);

        const int kvb = jb * 64;
        const bool active = (kvb <= R + 15);     // warp-uniform
        if (active) {
            float S_[8][4];
#pragma unroll
            for (int nb = 0; nb < 8; nb++)
#pragma unroll
                for (int e = 0; e < 4; e++) S_[nb][e] = 0.f;

            const uint32_t krow = (l & 7) + ((l >> 4) << 3);
            const uint32_t kcol = ((l >> 3) & 1) * 8;
#pragma unroll
            for (int kc = 0; kc < 8; kc++) {
                uint32_t qf[4];
                ldsm4(qf, qaddr0 + kc * 32);     // kc*16 cols * 2 bytes
#pragma unroll
                for (int p = 0; p < 4; p++) {
                    uint32_t bh[4];
                    uint32_t addr = base + (p*16 + krow) * KROWB + (kc*16 + kcol) * 2;
                    ldsm4(bh, addr);
                    mma16816h(S_[p*2+0], qf, bh[0], bh[1]);
                    mma16816h(S_[p*2+1], qf, bh[2], bh[3]);
                }
            }

            const bool domask = (kvb + 63 > R);
            float mx0 = -INFINITY, mx1 = -INFINITY;
#pragma unroll
            for (int nb = 0; nb < 8; nb++) {
                const int colb = kvb + nb*8 + lc;
#pragma unroll
                for (int e = 0; e < 4; e++) {
                    float v = S_[nb][e] * scale;
                    if (domask) {
                        int row = R + lq + (e >> 1) * 8;
                        int col = colb + (e & 1);
                        if (col > row) v = -INFINITY;
                    }
                    S_[nb][e] = v;
                    if (e < 2) mx0 = fmaxf(mx0, v); else mx1 = fmaxf(mx1, v);
                }
            }
            mx0 = fmaxf(mx0, __shfl_xor_sync(0xffffffffu, mx0, 1));
            mx0 = fmaxf(mx0, __shfl_xor_sync(0xffffffffu, mx0, 2));
            mx1 = fmaxf(mx1, __shfl_xor_sync(0xffffffffu, mx1, 1));
            mx1 = fmaxf(mx1, __shfl_xor_sync(0xffffffffu, mx1, 2));
            const float mn0 = fmaxf(mrow0, mx0);
            const float mn1 = fmaxf(mrow1, mx1);
            const float cr0 = __expf(mrow0 - mn0);
            const float cr1 = __expf(mrow1 - mn1);
            mrow0 = mn0; mrow1 = mn1;
            float ls0 = 0.f, ls1 = 0.f;
#pragma unroll
            for (int nb = 0; nb < 8; nb++) {
                float p0 = __expf(S_[nb][0] - mn0);
                float p1 = __expf(S_[nb][1] - mn0);
                float p2 = __expf(S_[nb][2] - mn1);
                float p3 = __expf(S_[nb][3] - mn1);
                S_[nb][0] = p0; S_[nb][1] = p1; S_[nb][2] = p2; S_[nb][3] = p3;
                ls0 += p0 + p1; ls1 += p2 + p3;
            }
            ls0 += __shfl_xor_sync(0xffffffffu, ls0, 1);
            ls0 += __shfl_xor_sync(0xffffffffu, ls0, 2);
            ls1 += __shfl_xor_sync(0xffffffffu, ls1, 1);
            ls1 += __shfl_xor_sync(0xffffffffu, ls1, 2);
            lrow0 = lrow0 * cr0 + ls0;
            lrow1 = lrow1 * cr1 + ls1;

            uint32_t aP[4][4];
#pragma unroll
            for (int kj = 0; kj < 4; kj++) {
#pragma unroll
                for (int half = 0; half < 2; half++) {
                    const int nb = kj*2 + half;
                    aP[kj][half*2+0] = packh(S_[nb][0], S_[nb][1]);
                    aP[kj][half*2+1] = packh(S_[nb][2], S_[nb][3]);
                }
            }

#pragma unroll
            for (int nb = 0; nb < 16; nb++) {
                O_[nb][0] *= cr0; O_[nb][1] *= cr0;
                O_[nb][2] *= cr1; O_[nb][3] *= cr1;
            }

            const uint32_t vrow = (l & 15);
            const uint32_t vcol = ((l >> 4) << 3);
#pragma unroll
            for (int kj = 0; kj < 4; kj++) {
#pragma unroll
                for (int p = 0; p < 8; p++) {
                    uint32_t vf[4];
                    uint32_t addr = base + KOPB + (kj*16 + vrow) * KROWB + (p*16 + vcol) * 2;
                    ldsm4t(vf, addr);
                    mma16816h(O_[p*2+0], aP[kj], vf[0], vf[1]);
                    mma16816h(O_[p*2+1], aP[kj], vf[2], vf[3]);
                }
            }
        }
        __syncthreads();
    }

    const float li0 = 1.f / lrow0;
    const float li1 = 1.f / lrow1;
    const size_t ra = (size_t)(R + lq) * HD + hoff;
    const size_t rb = (size_t)(R + lq + 8) * HD + hoff;
#pragma unroll
    for (int nb = 0; nb < 16; nb++) {
        const int c = nb*8 + lc;
        *(uint32_t*)&Oh[ra + c] = packh(O_[nb][0] * li0, O_[nb][1] * li0);
        *(uint32_t*)&Oh[rb + c] = packh(O_[nb][2] * li1, O_[nb][3] * li1);
    }
}

// ---------------- launch ---------------------------------------------------------
extern "C" void kernel_launch(void* const* d_in, const int* in_sizes, int n_in,
                              void* d_out, int out_size)
{
    const float* x  = (const float*)d_in[0];
    const float* wq = (const float*)d_in[2];
    const float* wk = (const float*)d_in[3];
    const float* wv = (const float*)d_in[4];
    const float* wo = (const float*)d_in[5];
    float* out = (float*)d_out;

    __half *xh, *wqh, *wkh, *wvh, *woh;
    __half *qh, *kh, *vh, *aoh;
    cudaGetSymbolAddress((void**)&xh,   g_xh);
    cudaGetSymbolAddress((void**)&wqh,  g_wqh);  cudaGetSymbolAddress((void**)&wkh,  g_wkh);
    cudaGetSymbolAddress((void**)&wvh,  g_wvh);  cudaGetSymbolAddress((void**)&woh,  g_woh);
    cudaGetSymbolAddress((void**)&qh,   g_qh);   cudaGetSymbolAddress((void**)&kh,   g_kh);
    cudaGetSymbolAddress((void**)&vh,   g_vh);   cudaGetSymbolAddress((void**)&aoh,  g_aoh);

    cudaFuncSetAttribute(qkv_gemm_kernel,
                         cudaFuncAttributeMaxDynamicSharedMemorySize, QGSM);
    cudaFuncSetAttribute(gemm_mma_kernel,
                         cudaFuncAttributeMaxDynamicSharedMemorySize, QGSM);
    cudaFuncSetAttribute(attn_mma_kernel,
                         cudaFuncAttributeMaxDynamicSharedMemorySize, ASMEM);

    rope_inv_kernel<<<1, 64>>>();
    rope_table_kernel<<<(S_LEN*(DH/2) + 255)/256, 256>>>();

    cvt_all_kernel<<<(N4TOT + 255)/256, 256>>>(x, wq, wk, wv, wo,
                                               xh, wqh, wkh, wvh, woh);

    qkv_gemm_kernel<<<dim3(48, GM/128), 256, QGSM>>>(
        xh, wqh, wkh, wvh, qh, kh, vh);

    attn_mma_kernel<<<dim3(S_LEN/128, NH), 256, ASMEM>>>(
        qh, kh, vh, aoh);

    gemm_mma_kernel<<<dim3(GN/128, GM/128), 256, QGSM>>>(aoh, woh, out);
}